// round 3
// baseline (speedup 1.0000x reference)
#include <cuda_runtime.h>
#include <math.h>

#define NB 4
#define NS 2048
#define ND 1024
#define NH 16
#define NDK 64

// Scratch (allocation-free rule: __device__ globals). [B,H,S,DK] for Q/K/V, [B,S,D] for X.
__device__ float g_Q[NB * NH * NS * NDK];
__device__ float g_K[NB * NH * NS * NDK];
__device__ float g_V[NB * NH * NS * NDK];
__device__ float g_X[NB * NS * ND];

// ---------------------------------------------------------------------------
// Projection GEMM: C[m,n] = sum_k A[m,k] * W[n,k]   (A:[M,K] row-major, W:[N,K] row-major)
// M = NB*NS = 8192, N = ND = 1024, K = ND = 1024.
// 64x64 tile, BK=16, 256 threads, 4x4 per-thread register tile.
// SPLIT=true  -> write C into [B,H,S,DK] layout (for Q/K/V)
// SPLIT=false -> write C row-major [M,N] (for final output)
// ---------------------------------------------------------------------------
template <bool SPLIT>
__global__ __launch_bounds__(256) void proj_kernel(const float* __restrict__ A,
                                                   const float* __restrict__ W,
                                                   float* __restrict__ C) {
    __shared__ float As[16][68];  // [k][m]
    __shared__ float Ws[16][68];  // [k][n]

    const int tid = threadIdx.x;
    const int tx = tid & 15;        // 0..15
    const int ty = tid >> 4;        // 0..15
    const int m0 = blockIdx.y * 64;
    const int n0 = blockIdx.x * 64;

    const int lr = tid >> 2;            // 0..63 : row within tile for loads
    const int lk = (tid & 3) << 2;      // 0,4,8,12 : k offset for loads

    const float* Ap = A + (size_t)(m0 + lr) * ND + lk;
    const float* Wp = W + (size_t)(n0 + lr) * ND + lk;

    float acc[4][4] = {};

    for (int k0 = 0; k0 < ND; k0 += 16) {
        float4 av = *(const float4*)(Ap + k0);
        float4 wv = *(const float4*)(Wp + k0);
        As[lk + 0][lr] = av.x; As[lk + 1][lr] = av.y;
        As[lk + 2][lr] = av.z; As[lk + 3][lr] = av.w;
        Ws[lk + 0][lr] = wv.x; Ws[lk + 1][lr] = wv.y;
        Ws[lk + 2][lr] = wv.z; Ws[lk + 3][lr] = wv.w;
        __syncthreads();

#pragma unroll
        for (int k = 0; k < 16; k++) {
            float4 a = *(const float4*)&As[k][ty << 2];
            float4 b = *(const float4*)&Ws[k][tx << 2];
            float ar[4] = {a.x, a.y, a.z, a.w};
            float br[4] = {b.x, b.y, b.z, b.w};
#pragma unroll
            for (int i = 0; i < 4; i++)
#pragma unroll
                for (int j = 0; j < 4; j++) acc[i][j] += ar[i] * br[j];
        }
        __syncthreads();
    }

    if (SPLIT) {
#pragma unroll
        for (int i = 0; i < 4; i++) {
            const int gm = m0 + (ty << 2) + i;
            const int bb = gm >> 11;        // / NS
            const int ss = gm & (NS - 1);
#pragma unroll
            for (int j = 0; j < 4; j++) {
                const int gn = n0 + (tx << 2) + j;
                const int hh = gn >> 6;     // / NDK
                const int dk = gn & 63;
                C[(((size_t)bb * NH + hh) * NS + ss) * NDK + dk] = acc[i][j];
            }
        }
    } else {
#pragma unroll
        for (int i = 0; i < 4; i++) {
            const int gm = m0 + (ty << 2) + i;
            float4 o = make_float4(acc[i][0], acc[i][1], acc[i][2], acc[i][3]);
            *(float4*)&C[(size_t)gm * ND + n0 + (tx << 2)] = o;
        }
    }
}

// ---------------------------------------------------------------------------
// Flash attention (fp32, causal). One block = 64 query rows of one (b,h).
// 256 threads, 4x4 register tiles, online softmax.
// ---------------------------------------------------------------------------
#define ATT_SMEM (4 * 64 * 68 * 4)

__global__ __launch_bounds__(256) void attn_kernel(const float* __restrict__ Q,
                                                   const float* __restrict__ K,
                                                   const float* __restrict__ V,
                                                   float* __restrict__ X) {
    extern __shared__ float sm[];
    float* Qs = sm;                 // [d][r]  stride 68
    float* Ks = sm + 64 * 68;       // [d][c]  stride 68
    float* Vs = sm + 2 * 64 * 68;   // [kk][d] stride 68
    float* Ps = sm + 3 * 64 * 68;   // [r][kk] stride 68

    const int tid = threadIdx.x;
    const int tx = tid & 15;
    const int ty = tid >> 4;
    const int qb = blockIdx.x;
    const int h = blockIdx.y;
    const int b = blockIdx.z;

    const size_t bh = ((size_t)b * NH + h) * NS * NDK;
    const int r0 = ty << 2;
    const int c0 = tx << 2;
    const int d0 = (tid & 15) << 2;   // load column offset
    const int rl = tid >> 4;          // load row base

    // Load Q tile, transposed into Qs[d][r]
#pragma unroll
    for (int p = 0; p < 4; p++) {
        const int row = rl + p * 16;
        float4 qv = *(const float4*)&Q[bh + (size_t)(qb * 64 + row) * NDK + d0];
        Qs[(d0 + 0) * 68 + row] = qv.x;
        Qs[(d0 + 1) * 68 + row] = qv.y;
        Qs[(d0 + 2) * 68 + row] = qv.z;
        Qs[(d0 + 3) * 68 + row] = qv.w;
    }

    float m[4], l[4], acc[4][4];
#pragma unroll
    for (int i = 0; i < 4; i++) {
        m[i] = -INFINITY;
        l[i] = 0.f;
#pragma unroll
        for (int j = 0; j < 4; j++) acc[i][j] = 0.f;
    }

    for (int kb = 0; kb <= qb; kb++) {
        __syncthreads();  // protect Ks/Vs from previous iteration's readers (also covers Q load)

        // Load K (transposed) and V tiles
#pragma unroll
        for (int p = 0; p < 4; p++) {
            const int row = rl + p * 16;
            float4 kv = *(const float4*)&K[bh + (size_t)(kb * 64 + row) * NDK + d0];
            Ks[(d0 + 0) * 68 + row] = kv.x;
            Ks[(d0 + 1) * 68 + row] = kv.y;
            Ks[(d0 + 2) * 68 + row] = kv.z;
            Ks[(d0 + 3) * 68 + row] = kv.w;
            float4 vv = *(const float4*)&V[bh + (size_t)(kb * 64 + row) * NDK + d0];
            *(float4*)&Vs[row * 68 + d0] = vv;
        }
        __syncthreads();

        // Scores: s = Q_tile @ K_tile^T  (4x4 per thread)
        float s[4][4] = {};
#pragma unroll 8
        for (int d = 0; d < 64; d++) {
            float4 qv = *(const float4*)&Qs[d * 68 + r0];
            float4 kv = *(const float4*)&Ks[d * 68 + c0];
            float qr[4] = {qv.x, qv.y, qv.z, qv.w};
            float kr[4] = {kv.x, kv.y, kv.z, kv.w};
#pragma unroll
            for (int i = 0; i < 4; i++)
#pragma unroll
                for (int j = 0; j < 4; j++) s[i][j] += qr[i] * kr[j];
        }

        const float scale = 0.125f;  // 1/sqrt(64)
#pragma unroll
        for (int i = 0; i < 4; i++)
#pragma unroll
            for (int j = 0; j < 4; j++) s[i][j] *= scale;

        if (kb == qb) {
            // diagonal tile: mask col > row (local offsets coincide)
#pragma unroll
            for (int i = 0; i < 4; i++)
#pragma unroll
                for (int j = 0; j < 4; j++)
                    if (c0 + j > r0 + i) s[i][j] = -1e9f;
        }

        // Online softmax per owned row; reduce across the 16 tx lanes.
#pragma unroll
        for (int i = 0; i < 4; i++) {
            float mt = fmaxf(fmaxf(s[i][0], s[i][1]), fmaxf(s[i][2], s[i][3]));
#pragma unroll
            for (int off = 8; off >= 1; off >>= 1)
                mt = fmaxf(mt, __shfl_xor_sync(0xffffffffu, mt, off));
            const float mn = fmaxf(m[i], mt);
            const float al = __expf(m[i] - mn);
            float p[4], rs = 0.f;
#pragma unroll
            for (int j = 0; j < 4; j++) {
                p[j] = __expf(s[i][j] - mn);
                rs += p[j];
            }
#pragma unroll
            for (int off = 8; off >= 1; off >>= 1)
                rs += __shfl_xor_sync(0xffffffffu, rs, off);
            l[i] = l[i] * al + rs;
            m[i] = mn;
#pragma unroll
            for (int j = 0; j < 4; j++) acc[i][j] *= al;
#pragma unroll
            for (int j = 0; j < 4; j++) Ps[(r0 + i) * 68 + c0 + j] = p[j];
        }
        __syncthreads();

        // acc += P_tile @ V_tile
#pragma unroll 4
        for (int kk = 0; kk < 64; kk++) {
            float4 vv = *(const float4*)&Vs[kk * 68 + c0];
            float vr[4] = {vv.x, vv.y, vv.z, vv.w};
#pragma unroll
            for (int i = 0; i < 4; i++) {
                const float pv = Ps[(r0 + i) * 68 + kk];
#pragma unroll
                for (int j = 0; j < 4; j++) acc[i][j] += pv * vr[j];
            }
        }
    }

    // Epilogue: normalize and write X[b, s, h*64 + d]
#pragma unroll
    for (int i = 0; i < 4; i++) {
        const float inv = 1.0f / l[i];
        float4 o = make_float4(acc[i][0] * inv, acc[i][1] * inv,
                               acc[i][2] * inv, acc[i][3] * inv);
        const size_t idx =
            ((size_t)b * NS + qb * 64 + r0 + i) * ND + h * NDK + c0;
        *(float4*)&X[idx] = o;
    }
}

// ---------------------------------------------------------------------------
extern "C" void kernel_launch(void* const* d_in, const int* in_sizes, int n_in,
                              void* d_out, int out_size) {
    const float* q  = (const float*)d_in[0];
    const float* k  = (const float*)d_in[1];
    const float* v  = (const float*)d_in[2];
    // d_in[3] = mask (causal tril) -- implied by kernel structure
    const float* wq = (const float*)d_in[4];
    const float* wk = (const float*)d_in[5];
    const float* wv = (const float*)d_in[6];
    const float* wo = (const float*)d_in[7];
    float* out = (float*)d_out;

    float *Qp, *Kp, *Vp, *Xp;
    cudaGetSymbolAddress((void**)&Qp, g_Q);
    cudaGetSymbolAddress((void**)&Kp, g_K);
    cudaGetSymbolAddress((void**)&Vp, g_V);
    cudaGetSymbolAddress((void**)&Xp, g_X);

    cudaFuncSetAttribute(attn_kernel,
                         cudaFuncAttributeMaxDynamicSharedMemorySize, ATT_SMEM);

    dim3 pg(ND / 64, (NB * NS) / 64);  // (16, 128)
    proj_kernel<true><<<pg, 256>>>(q, wq, Qp);
    proj_kernel<true><<<pg, 256>>>(k, wk, Kp);
    proj_kernel<true><<<pg, 256>>>(v, wv, Vp);

    attn_kernel<<<dim3(NS / 64, NH, NB), 256, ATT_SMEM>>>(Qp, Kp, Vp, Xp);

    proj_kernel<false><<<pg, 256>>>(Xp, wo, out);
}

// round 4
// speedup vs baseline: 2.5323x; 2.5323x over previous
#include <cuda_runtime.h>
#include <cuda_bf16.h>
#include <math.h>
#include <stdint.h>

#define NB 4
#define NS 2048
#define ND 1024
#define NH 16
#define NDK 64
#define NM (NB * NS)  // 8192

// ---------------- device scratch (allocation-free rule) ----------------
// bf16 split planes of inputs / weights
__device__ __nv_bfloat16 g_qh[NM * ND], g_ql[NM * ND];
__device__ __nv_bfloat16 g_kh[NM * ND], g_kl[NM * ND];
__device__ __nv_bfloat16 g_vh[NM * ND], g_vl[NM * ND];
__device__ __nv_bfloat16 g_wqh[ND * ND], g_wql[ND * ND];
__device__ __nv_bfloat16 g_wkh[ND * ND], g_wkl[ND * ND];
__device__ __nv_bfloat16 g_wvh[ND * ND], g_wvl[ND * ND];
__device__ __nv_bfloat16 g_woh[ND * ND], g_wol[ND * ND];
// projected Q,K: [B,H,S,DK] planes ; V: [B,H,DK,S] planes (pre-transposed for PV)
__device__ __nv_bfloat16 g_Qh[NM * ND], g_Ql[NM * ND];
__device__ __nv_bfloat16 g_Kh[NM * ND], g_Kl[NM * ND];
__device__ __nv_bfloat16 g_Vh[NM * ND], g_Vl[NM * ND];
// attention output: [B,S,D] planes
__device__ __nv_bfloat16 g_Xh[NM * ND], g_Xl[NM * ND];

// ---------------- helpers ----------------
__device__ __forceinline__ uint32_t ld32(const __nv_bfloat16* p) {
    return *(const uint32_t*)p;
}

__device__ __forceinline__ void mma_bf16(float* d, const uint32_t* a, uint32_t b0, uint32_t b1) {
    asm volatile(
        "mma.sync.aligned.m16n8k16.row.col.f32.bf16.bf16.f32 "
        "{%0,%1,%2,%3}, {%4,%5,%6,%7}, {%8,%9}, {%0,%1,%2,%3};\n"
        : "+f"(d[0]), "+f"(d[1]), "+f"(d[2]), "+f"(d[3])
        : "r"(a[0]), "r"(a[1]), "r"(a[2]), "r"(a[3]), "r"(b0), "r"(b1));
}

__device__ __forceinline__ void cpa16(__nv_bfloat16* dst, const __nv_bfloat16* src) {
    uint32_t d = (uint32_t)__cvta_generic_to_shared(dst);
    asm volatile("cp.async.ca.shared.global [%0], [%1], 16;\n" ::"r"(d), "l"(src));
}
#define CP_COMMIT() asm volatile("cp.async.commit_group;\n")
template <int N>
__device__ __forceinline__ void cp_wait() {
    asm volatile("cp.async.wait_group %0;\n" ::"n"(N));
}

// split-store a pair of fp32 into hi/lo bf16 planes (4B vector stores)
__device__ __forceinline__ void split_store2(__nv_bfloat16* ph, __nv_bfloat16* pl,
                                             float x, float y) {
    __nv_bfloat16 hx = __float2bfloat16(x), hy = __float2bfloat16(y);
    __nv_bfloat162 h2; h2.x = hx; h2.y = hy;
    *(__nv_bfloat162*)ph = h2;
    __nv_bfloat162 l2;
    l2.x = __float2bfloat16(x - __bfloat162float(hx));
    l2.y = __float2bfloat16(y - __bfloat162float(hy));
    *(__nv_bfloat162*)pl = l2;
}

// ---------------- prep: fp32 -> bf16 hi/lo planes ----------------
__global__ void split_kernel(const float* __restrict__ src, __nv_bfloat16* __restrict__ h,
                             __nv_bfloat16* __restrict__ l, int n) {
    int i = (blockIdx.x * blockDim.x + threadIdx.x) * 4;
    if (i < n) {
        float4 v = *(const float4*)(src + i);
        split_store2(h + i, l + i, v.x, v.y);
        split_store2(h + i + 2, l + i + 2, v.z, v.w);
    }
}

// ---------------- GEMM: C[m,n] = sum_k A[m,k] * W[n,k], bf16x2 3-pass ----------------
// MODE 0: split-store to [B,H,S,DK] bf16 planes (Q, K)
// MODE 1: split-store to [B,H,DK,S] bf16 planes (V, transposed)
// MODE 2: fp32 store row-major [M,N] (final output)
#define G_PL (128 * 40)      // plane stride (elems)
#define G_SA (2 * G_PL)      // stage stride
#define GEMM_SMEM (4 * G_SA * 2)  // bytes: (A + W) * 2 stages * 2 planes

template <int MODE>
__global__ __launch_bounds__(256) void gemm_bf16x2(
    const __nv_bfloat16* __restrict__ Ah, const __nv_bfloat16* __restrict__ Al,
    const __nv_bfloat16* __restrict__ Wh, const __nv_bfloat16* __restrict__ Wl,
    __nv_bfloat16* __restrict__ Oh, __nv_bfloat16* __restrict__ Ol,
    float* __restrict__ Of) {
    extern __shared__ __nv_bfloat16 sm[];
    __nv_bfloat16* sA = sm;              // [stage][plane][128][40]
    __nv_bfloat16* sW = sm + 2 * G_SA;

    const int tid = threadIdx.x;
    const int lane = tid & 31, wid = tid >> 5;
    const int wm = (wid >> 2) * 64, wn = (wid & 3) * 32;
    const int gr = lane >> 2, gc = (lane & 3) * 2;
    const int m0 = blockIdx.y * 128, n0 = blockIdx.x * 128;

    const int lrow = tid >> 2;           // 0..63 (x2 passes -> 128 rows)
    const int lseg = (tid & 3) * 8;

    float acc[4][4][4];
#pragma unroll
    for (int i = 0; i < 4; i++)
#pragma unroll
        for (int j = 0; j < 4; j++)
#pragma unroll
            for (int c = 0; c < 4; c++) acc[i][j][c] = 0.f;

    auto load_stage = [&](int st, int k0) {
#pragma unroll
        for (int i = 0; i < 2; i++) {
            int row = lrow + i * 64;
            __nv_bfloat16* da = sA + st * G_SA + row * 40 + lseg;
            cpa16(da, Ah + (size_t)(m0 + row) * ND + k0 + lseg);
            cpa16(da + G_PL, Al + (size_t)(m0 + row) * ND + k0 + lseg);
            __nv_bfloat16* dw = sW + st * G_SA + row * 40 + lseg;
            cpa16(dw, Wh + (size_t)(n0 + row) * ND + k0 + lseg);
            cpa16(dw + G_PL, Wl + (size_t)(n0 + row) * ND + k0 + lseg);
        }
    };

    load_stage(0, 0);
    CP_COMMIT();

    for (int k0 = 0; k0 < ND; k0 += 32) {
        const int st = (k0 >> 5) & 1;
        if (k0 + 32 < ND) load_stage(st ^ 1, k0 + 32);
        CP_COMMIT();
        cp_wait<1>();
        __syncthreads();

#pragma unroll
        for (int kk = 0; kk < 2; kk++) {
            const int kb = kk * 16;
            uint32_t bh[4][2], bl[4][2];
#pragma unroll
            for (int nf = 0; nf < 4; nf++) {
                const __nv_bfloat16* p = sW + st * G_SA + (wn + nf * 8 + gr) * 40 + kb + gc;
                bh[nf][0] = ld32(p); bh[nf][1] = ld32(p + 8);
                bl[nf][0] = ld32(p + G_PL); bl[nf][1] = ld32(p + G_PL + 8);
            }
#pragma unroll
            for (int mf = 0; mf < 4; mf++) {
                const __nv_bfloat16* pa = sA + st * G_SA + (wm + mf * 16 + gr) * 40 + kb + gc;
                uint32_t ah[4], al[4];
                ah[0] = ld32(pa); ah[1] = ld32(pa + 8 * 40);
                ah[2] = ld32(pa + 8); ah[3] = ld32(pa + 8 * 40 + 8);
                al[0] = ld32(pa + G_PL); al[1] = ld32(pa + G_PL + 8 * 40);
                al[2] = ld32(pa + G_PL + 8); al[3] = ld32(pa + G_PL + 8 * 40 + 8);
#pragma unroll
                for (int nf = 0; nf < 4; nf++) {
                    mma_bf16(acc[mf][nf], ah, bh[nf][0], bh[nf][1]);
                    mma_bf16(acc[mf][nf], ah, bl[nf][0], bl[nf][1]);
                    mma_bf16(acc[mf][nf], al, bh[nf][0], bh[nf][1]);
                }
            }
        }
        __syncthreads();
    }

    // epilogue
#pragma unroll
    for (int mf = 0; mf < 4; mf++) {
        const int r0 = m0 + wm + mf * 16 + gr;
#pragma unroll
        for (int nf = 0; nf < 4; nf++) {
            const int c0 = n0 + wn + nf * 8 + gc;
            float* a = acc[mf][nf];
            if (MODE == 2) {
                float2 v0 = make_float2(a[0], a[1]);
                float2 v1 = make_float2(a[2], a[3]);
                *(float2*)&Of[(size_t)r0 * ND + c0] = v0;
                *(float2*)&Of[(size_t)(r0 + 8) * ND + c0] = v1;
            } else {
                const int bb = r0 >> 11, ss = r0 & (NS - 1);
                const int hh = c0 >> 6, dk = c0 & 63;
                if (MODE == 0) {
                    size_t b0 = (((size_t)bb * NH + hh) * NS + ss) * NDK + dk;
                    size_t b1 = (((size_t)bb * NH + hh) * NS + ss + 8) * NDK + dk;
                    split_store2(Oh + b0, Ol + b0, a[0], a[1]);
                    split_store2(Oh + b1, Ol + b1, a[2], a[3]);
                } else {  // MODE 1: [B,H,DK,S]
                    size_t base = (((size_t)bb * NH + hh) * NDK + dk) * NS + ss;
                    __nv_bfloat16 h0 = __float2bfloat16(a[0]);
                    __nv_bfloat16 h1 = __float2bfloat16(a[1]);
                    __nv_bfloat16 h2 = __float2bfloat16(a[2]);
                    __nv_bfloat16 h3 = __float2bfloat16(a[3]);
                    Oh[base] = h0;          Ol[base] = __float2bfloat16(a[0] - __bfloat162float(h0));
                    Oh[base + NS] = h1;     Ol[base + NS] = __float2bfloat16(a[1] - __bfloat162float(h1));
                    Oh[base + 8] = h2;      Ol[base + 8] = __float2bfloat16(a[2] - __bfloat162float(h2));
                    Oh[base + NS + 8] = h3; Ol[base + NS + 8] = __float2bfloat16(a[3] - __bfloat162float(h3));
                }
            }
        }
    }
}

// ---------------- flash attention, bf16x2 3-pass mma ----------------
#define A_QP (128 * 72)          // Q/P plane stride
#define A_KP (64 * 72)           // K/V plane stride
#define A_KS (2 * A_KP)          // K/V stage stride
#define ATT_SMEM ((2 * A_QP + 2 * A_KS + 2 * A_KS) * 2)  // bytes = 110592

__global__ __launch_bounds__(256) void attn_kernel(
    const __nv_bfloat16* __restrict__ Qh, const __nv_bfloat16* __restrict__ Ql,
    const __nv_bfloat16* __restrict__ Kh, const __nv_bfloat16* __restrict__ Kl,
    const __nv_bfloat16* __restrict__ Vh, const __nv_bfloat16* __restrict__ Vl,
    __nv_bfloat16* __restrict__ Xh, __nv_bfloat16* __restrict__ Xl) {
    extern __shared__ __nv_bfloat16 sm[];
    __nv_bfloat16* sQ = sm;                        // 2 planes [128][72]; reused as P after frag load
    __nv_bfloat16* sK = sm + 2 * A_QP;             // 2 stages x 2 planes [64][72]
    __nv_bfloat16* sV = sK + 2 * A_KS;

    const int tid = threadIdx.x;
    const int lane = tid & 31, wid = tid >> 5;
    const int gr = lane >> 2, gc = (lane & 3) * 2;
    const int qb = (gridDim.x - 1) - blockIdx.x;   // longest blocks first
    const int h = blockIdx.y, b = blockIdx.z;

    const size_t bqk = ((size_t)b * NH + h) * NS * NDK;   // Q,K base ([B,H,S,DK])
    const size_t bv = ((size_t)b * NH + h) * NDK * NS;    // V base ([B,H,DK,S])
    const size_t qoff = bqk + (size_t)qb * 128 * NDK;

    auto load_kv = [&](int st, int kt) {
#pragma unroll
        for (int i = 0; i < 4; i++) {
            int idx = tid + 256 * i;
            int p = idx >> 9, r = (idx >> 3) & 63, seg = (idx & 7) * 8;
            cpa16(sK + st * A_KS + p * A_KP + r * 72 + seg,
                  (p ? Kl : Kh) + bqk + (size_t)(kt * 64 + r) * NDK + seg);
            cpa16(sV + st * A_KS + p * A_KP + r * 72 + seg,
                  (p ? Vl : Vh) + bv + (size_t)r * NS + kt * 64 + seg);
        }
    };

    // prologue: load Q tile + KV stage0
#pragma unroll
    for (int i = 0; i < 8; i++) {
        int idx = tid + 256 * i;
        int p = idx >> 10, r = (idx >> 3) & 127, seg = (idx & 7) * 8;
        cpa16(sQ + p * A_QP + r * 72 + seg, (p ? Ql : Qh) + qoff + (size_t)r * NDK + seg);
    }
    load_kv(0, 0);
    CP_COMMIT();
    cp_wait<0>();
    __syncthreads();

    // Q fragments -> registers (reused across all k-tiles)
    uint32_t qfh[4][4], qfl[4][4];
    const int rw = wid * 16 + gr;
#pragma unroll
    for (int df = 0; df < 4; df++) {
        const __nv_bfloat16* p = sQ + rw * 72 + df * 16 + gc;
        qfh[df][0] = ld32(p); qfh[df][1] = ld32(p + 8 * 72);
        qfh[df][2] = ld32(p + 8); qfh[df][3] = ld32(p + 8 * 72 + 8);
        qfl[df][0] = ld32(p + A_QP); qfl[df][1] = ld32(p + A_QP + 8 * 72);
        qfl[df][2] = ld32(p + A_QP + 8); qfl[df][3] = ld32(p + A_QP + 8 * 72 + 8);
    }
    __syncthreads();  // sQ now reusable as P
    __nv_bfloat16* sPh = sQ;
    __nv_bfloat16* sPl = sQ + A_QP;

    float O[8][4];
#pragma unroll
    for (int i = 0; i < 8; i++)
#pragma unroll
        for (int j = 0; j < 4; j++) O[i][j] = 0.f;
    float mrA = -INFINITY, mrB = -INFINITY, lrA = 0.f, lrB = 0.f;

    const int nkt = 2 * qb + 2;
    const int growA = qb * 128 + wid * 16 + gr;
    const int growB = growA + 8;

    for (int kt = 0; kt < nkt; kt++) {
        const int st = kt & 1;
        if (kt + 1 < nkt) load_kv(st ^ 1, kt + 1);
        CP_COMMIT();
        cp_wait<1>();
        __syncthreads();

        const bool act = !(kt == 2 * qb + 1 && wid < 4);
        if (act) {
            // ---- S = Q K^T ----
            float S[8][4];
#pragma unroll
            for (int i = 0; i < 8; i++)
#pragma unroll
                for (int j = 0; j < 4; j++) S[i][j] = 0.f;
#pragma unroll
            for (int df = 0; df < 4; df++) {
#pragma unroll
                for (int nf = 0; nf < 8; nf++) {
                    const __nv_bfloat16* pb = sK + st * A_KS + (nf * 8 + gr) * 72 + df * 16 + gc;
                    uint32_t b0h = ld32(pb), b1h = ld32(pb + 8);
                    uint32_t b0l = ld32(pb + A_KP), b1l = ld32(pb + A_KP + 8);
                    mma_bf16(S[nf], qfh[df], b0h, b1h);
                    mma_bf16(S[nf], qfh[df], b0l, b1l);
                    mma_bf16(S[nf], qfl[df], b0h, b1h);
                }
            }

            // ---- scale + mask ----
            const float sc = 0.125f;
#pragma unroll
            for (int nf = 0; nf < 8; nf++)
#pragma unroll
                for (int j = 0; j < 4; j++) S[nf][j] *= sc;
            if (kt >= 2 * qb) {
#pragma unroll
                for (int nf = 0; nf < 8; nf++) {
                    const int col = kt * 64 + nf * 8 + gc;
                    if (col > growA) S[nf][0] = -1e30f;
                    if (col + 1 > growA) S[nf][1] = -1e30f;
                    if (col > growB) S[nf][2] = -1e30f;
                    if (col + 1 > growB) S[nf][3] = -1e30f;
                }
            }

            // ---- online softmax (rows A=gr, B=gr+8 within warp) ----
            float mA = -INFINITY, mB = -INFINITY;
#pragma unroll
            for (int nf = 0; nf < 8; nf++) {
                mA = fmaxf(mA, fmaxf(S[nf][0], S[nf][1]));
                mB = fmaxf(mB, fmaxf(S[nf][2], S[nf][3]));
            }
            mA = fmaxf(mA, __shfl_xor_sync(0xffffffffu, mA, 1));
            mA = fmaxf(mA, __shfl_xor_sync(0xffffffffu, mA, 2));
            mB = fmaxf(mB, __shfl_xor_sync(0xffffffffu, mB, 1));
            mB = fmaxf(mB, __shfl_xor_sync(0xffffffffu, mB, 2));
            const float mnA = fmaxf(mrA, mA), mnB = fmaxf(mrB, mB);
            const float aA = __expf(mrA - mnA), aB = __expf(mrB - mnB);
            float rsA = 0.f, rsB = 0.f;
            const int prow = wid * 16 + gr;
#pragma unroll
            for (int nf = 0; nf < 8; nf++) {
                float p0 = __expf(S[nf][0] - mnA);
                float p1 = __expf(S[nf][1] - mnA);
                float p2 = __expf(S[nf][2] - mnB);
                float p3 = __expf(S[nf][3] - mnB);
                rsA += p0 + p1; rsB += p2 + p3;
                const int pc = nf * 8 + gc;
                split_store2(sPh + prow * 72 + pc, sPl + prow * 72 + pc, p0, p1);
                split_store2(sPh + (prow + 8) * 72 + pc, sPl + (prow + 8) * 72 + pc, p2, p3);
            }
            rsA += __shfl_xor_sync(0xffffffffu, rsA, 1);
            rsA += __shfl_xor_sync(0xffffffffu, rsA, 2);
            rsB += __shfl_xor_sync(0xffffffffu, rsB, 1);
            rsB += __shfl_xor_sync(0xffffffffu, rsB, 2);
            lrA = lrA * aA + rsA; mrA = mnA;
            lrB = lrB * aB + rsB; mrB = mnB;
#pragma unroll
            for (int df = 0; df < 8; df++) {
                O[df][0] *= aA; O[df][1] *= aA;
                O[df][2] *= aB; O[df][3] *= aB;
            }
            __syncwarp();

            // ---- O += P V ----
#pragma unroll
            for (int ks = 0; ks < 4; ks++) {
                const __nv_bfloat16* pa = sPh + rw * 72 + ks * 16 + gc;
                uint32_t ph[4], pl[4];
                ph[0] = ld32(pa); ph[1] = ld32(pa + 8 * 72);
                ph[2] = ld32(pa + 8); ph[3] = ld32(pa + 8 * 72 + 8);
                pl[0] = ld32(pa + A_QP); pl[1] = ld32(pa + A_QP + 8 * 72);
                pl[2] = ld32(pa + A_QP + 8); pl[3] = ld32(pa + A_QP + 8 * 72 + 8);
#pragma unroll
                for (int df = 0; df < 8; df++) {
                    const __nv_bfloat16* pv = sV + st * A_KS + (df * 8 + gr) * 72 + ks * 16 + gc;
                    uint32_t v0h = ld32(pv), v1h = ld32(pv + 8);
                    uint32_t v0l = ld32(pv + A_KP), v1l = ld32(pv + A_KP + 8);
                    mma_bf16(O[df], ph, v0h, v1h);
                    mma_bf16(O[df], ph, v0l, v1l);
                    mma_bf16(O[df], pl, v0h, v1h);
                }
            }
        }
        __syncthreads();
    }

    // ---- epilogue: X[b, s, h*64+d] split planes ----
    const float iA = 1.0f / lrA, iB = 1.0f / lrB;
    const size_t baseA = ((size_t)b * NS + growA) * ND + h * NDK;
    const size_t baseB = ((size_t)b * NS + growB) * ND + h * NDK;
#pragma unroll
    for (int df = 0; df < 8; df++) {
        const int col = df * 8 + gc;
        split_store2(Xh + baseA + col, Xl + baseA + col, O[df][0] * iA, O[df][1] * iA);
        split_store2(Xh + baseB + col, Xl + baseB + col, O[df][2] * iB, O[df][3] * iB);
    }
}

// ---------------- launch ----------------
extern "C" void kernel_launch(void* const* d_in, const int* in_sizes, int n_in,
                              void* d_out, int out_size) {
    const float* q = (const float*)d_in[0];
    const float* k = (const float*)d_in[1];
    const float* v = (const float*)d_in[2];
    const float* wq = (const float*)d_in[4];
    const float* wk = (const float*)d_in[5];
    const float* wv = (const float*)d_in[6];
    const float* wo = (const float*)d_in[7];
    float* out = (float*)d_out;

    __nv_bfloat16 *qh, *ql, *kh, *kl, *vh, *vl;
    __nv_bfloat16 *wqh, *wql, *wkh, *wkl, *wvh, *wvl, *woh, *wol;
    __nv_bfloat16 *Qh, *Ql, *Kh, *Kl, *Vh, *Vl, *Xh, *Xl;
    cudaGetSymbolAddress((void**)&qh, g_qh);   cudaGetSymbolAddress((void**)&ql, g_ql);
    cudaGetSymbolAddress((void**)&kh, g_kh);   cudaGetSymbolAddress((void**)&kl, g_kl);
    cudaGetSymbolAddress((void**)&vh, g_vh);   cudaGetSymbolAddress((void**)&vl, g_vl);
    cudaGetSymbolAddress((void**)&wqh, g_wqh); cudaGetSymbolAddress((void**)&wql, g_wql);
    cudaGetSymbolAddress((void**)&wkh, g_wkh); cudaGetSymbolAddress((void**)&wkl, g_wkl);
    cudaGetSymbolAddress((void**)&wvh, g_wvh); cudaGetSymbolAddress((void**)&wvl, g_wvl);
    cudaGetSymbolAddress((void**)&woh, g_woh); cudaGetSymbolAddress((void**)&wol, g_wol);
    cudaGetSymbolAddress((void**)&Qh, g_Qh);   cudaGetSymbolAddress((void**)&Ql, g_Ql);
    cudaGetSymbolAddress((void**)&Kh, g_Kh);   cudaGetSymbolAddress((void**)&Kl, g_Kl);
    cudaGetSymbolAddress((void**)&Vh, g_Vh);   cudaGetSymbolAddress((void**)&Vl, g_Vl);
    cudaGetSymbolAddress((void**)&Xh, g_Xh);   cudaGetSymbolAddress((void**)&Xl, g_Xl);

    cudaFuncSetAttribute(gemm_bf16x2<0>, cudaFuncAttributeMaxDynamicSharedMemorySize, GEMM_SMEM);
    cudaFuncSetAttribute(gemm_bf16x2<1>, cudaFuncAttributeMaxDynamicSharedMemorySize, GEMM_SMEM);
    cudaFuncSetAttribute(gemm_bf16x2<2>, cudaFuncAttributeMaxDynamicSharedMemorySize, GEMM_SMEM);
    cudaFuncSetAttribute(attn_kernel, cudaFuncAttributeMaxDynamicSharedMemorySize, ATT_SMEM);

    // prep: split fp32 -> bf16 hi/lo
    const int nA = NM * ND, nW = ND * ND;
    split_kernel<<<nA / 4 / 256, 256>>>(q, qh, ql, nA);
    split_kernel<<<nA / 4 / 256, 256>>>(k, kh, kl, nA);
    split_kernel<<<nA / 4 / 256, 256>>>(v, vh, vl, nA);
    split_kernel<<<nW / 4 / 256, 256>>>(wq, wqh, wql, nW);
    split_kernel<<<nW / 4 / 256, 256>>>(wk, wkh, wkl, nW);
    split_kernel<<<nW / 4 / 256, 256>>>(wv, wvh, wvl, nW);
    split_kernel<<<nW / 4 / 256, 256>>>(wo, woh, wol, nW);

    dim3 pg(ND / 128, NM / 128);  // (8, 64)
    gemm_bf16x2<0><<<pg, 256, GEMM_SMEM>>>(qh, ql, wqh, wql, Qh, Ql, nullptr);
    gemm_bf16x2<0><<<pg, 256, GEMM_SMEM>>>(kh, kl, wkh, wkl, Kh, Kl, nullptr);
    gemm_bf16x2<1><<<pg, 256, GEMM_SMEM>>>(vh, vl, wvh, wvl, Vh, Vl, nullptr);

    attn_kernel<<<dim3(NS / 128, NH, NB), 256, ATT_SMEM>>>(Qh, Ql, Kh, Kl, Vh, Vl, Xh, Xl);

    gemm_bf16x2<2><<<pg, 256, GEMM_SMEM>>>(Xh, Xl, woh, wol, nullptr, nullptr, out);
}

// round 7
// speedup vs baseline: 2.8283x; 1.1169x over previous
#include <cuda_runtime.h>
#include <cuda_bf16.h>
#include <math.h>
#include <stdint.h>

#define NB 4
#define NS 2048
#define ND 1024
#define NH 16
#define NDK 64
#define NM (NB * NS)  // 8192

// ---------------- device scratch (allocation-free rule) ----------------
__device__ __nv_bfloat16 g_qh[NM * ND], g_ql[NM * ND];
__device__ __nv_bfloat16 g_kh[NM * ND], g_kl[NM * ND];
__device__ __nv_bfloat16 g_vh[NM * ND], g_vl[NM * ND];
__device__ __nv_bfloat16 g_wqh[ND * ND], g_wql[ND * ND];
__device__ __nv_bfloat16 g_wkh[ND * ND], g_wkl[ND * ND];
__device__ __nv_bfloat16 g_wvh[ND * ND], g_wvl[ND * ND];
__device__ __nv_bfloat16 g_woh[ND * ND], g_wol[ND * ND];
__device__ __nv_bfloat16 g_Qh[NM * ND], g_Ql[NM * ND];
__device__ __nv_bfloat16 g_Kh[NM * ND], g_Kl[NM * ND];
__device__ __nv_bfloat16 g_Vh[NM * ND], g_Vl[NM * ND];   // [B,H,DK,S]
__device__ __nv_bfloat16 g_Xh[NM * ND], g_Xl[NM * ND];

// ---------------- helpers ----------------
__device__ __forceinline__ uint32_t ld32(const __nv_bfloat16* p) {
    return *(const uint32_t*)p;
}
__device__ __forceinline__ uint32_t smem_u32(const void* p) {
    return (uint32_t)__cvta_generic_to_shared(p);
}

__device__ __forceinline__ void mma_bf16(float* d, const uint32_t* a, uint32_t b0, uint32_t b1) {
    asm volatile(
        "mma.sync.aligned.m16n8k16.row.col.f32.bf16.bf16.f32 "
        "{%0,%1,%2,%3}, {%4,%5,%6,%7}, {%8,%9}, {%0,%1,%2,%3};\n"
        : "+f"(d[0]), "+f"(d[1]), "+f"(d[2]), "+f"(d[3])
        : "r"(a[0]), "r"(a[1]), "r"(a[2]), "r"(a[3]), "r"(b0), "r"(b1));
}

__device__ __forceinline__ void ldsm_x4(uint32_t* r, uint32_t addr) {
    asm volatile("ldmatrix.sync.aligned.m8n8.x4.shared.b16 {%0,%1,%2,%3}, [%4];"
                 : "=r"(r[0]), "=r"(r[1]), "=r"(r[2]), "=r"(r[3])
                 : "r"(addr));
}

__device__ __forceinline__ void cpa16(__nv_bfloat16* dst, const __nv_bfloat16* src) {
    uint32_t d = (uint32_t)__cvta_generic_to_shared(dst);
    asm volatile("cp.async.ca.shared.global [%0], [%1], 16;\n" ::"r"(d), "l"(src));
}
#define CP_COMMIT() asm volatile("cp.async.commit_group;\n")
template <int N>
__device__ __forceinline__ void cp_wait() {
    asm volatile("cp.async.wait_group %0;\n" ::"n"(N));
}

__device__ __forceinline__ void split_store2(__nv_bfloat16* ph, __nv_bfloat16* pl,
                                             float x, float y) {
    __nv_bfloat16 hx = __float2bfloat16(x), hy = __float2bfloat16(y);
    __nv_bfloat162 h2; h2.x = hx; h2.y = hy;
    *(__nv_bfloat162*)ph = h2;
    __nv_bfloat162 l2;
    l2.x = __float2bfloat16(x - __bfloat162float(hx));
    l2.y = __float2bfloat16(y - __bfloat162float(hy));
    *(__nv_bfloat162*)pl = l2;
}

// ---------------- prep: fp32 -> bf16 hi/lo planes (3-way / 4-way fused) ----------------
__global__ void split3_kernel(const float* s0, const float* s1, const float* s2,
                              __nv_bfloat16* h0, __nv_bfloat16* l0,
                              __nv_bfloat16* h1, __nv_bfloat16* l1,
                              __nv_bfloat16* h2, __nv_bfloat16* l2, int n) {
    const float* s = (blockIdx.y == 0) ? s0 : (blockIdx.y == 1) ? s1 : s2;
    __nv_bfloat16* h = (blockIdx.y == 0) ? h0 : (blockIdx.y == 1) ? h1 : h2;
    __nv_bfloat16* l = (blockIdx.y == 0) ? l0 : (blockIdx.y == 1) ? l1 : l2;
    int i = (blockIdx.x * blockDim.x + threadIdx.x) * 4;
    if (i < n) {
        float4 v = *(const float4*)(s + i);
        split_store2(h + i, l + i, v.x, v.y);
        split_store2(h + i + 2, l + i + 2, v.z, v.w);
    }
}
__global__ void split4_kernel(const float* s0, const float* s1, const float* s2, const float* s3,
                              __nv_bfloat16* h0, __nv_bfloat16* l0,
                              __nv_bfloat16* h1, __nv_bfloat16* l1,
                              __nv_bfloat16* h2, __nv_bfloat16* l2,
                              __nv_bfloat16* h3, __nv_bfloat16* l3, int n) {
    const float* s = (blockIdx.y == 0) ? s0 : (blockIdx.y == 1) ? s1 : (blockIdx.y == 2) ? s2 : s3;
    __nv_bfloat16* h = (blockIdx.y == 0) ? h0 : (blockIdx.y == 1) ? h1 : (blockIdx.y == 2) ? h2 : h3;
    __nv_bfloat16* l = (blockIdx.y == 0) ? l0 : (blockIdx.y == 1) ? l1 : (blockIdx.y == 2) ? l2 : l3;
    int i = (blockIdx.x * blockDim.x + threadIdx.x) * 4;
    if (i < n) {
        float4 v = *(const float4*)(s + i);
        split_store2(h + i, l + i, v.x, v.y);
        split_store2(h + i + 2, l + i + 2, v.z, v.w);
    }
}

// ---------------- GEMM: C[m,n] = sum_k A[m,k] * W[n,k], bf16x2 3-pass, ldmatrix ----------------
#define G_PL (128 * 40)
#define G_SA (2 * G_PL)
#define GEMM_SMEM (4 * G_SA * 2)

template <int MODE>
__global__ __launch_bounds__(256) void gemm_bf16x2(
    const __nv_bfloat16* __restrict__ Ah, const __nv_bfloat16* __restrict__ Al,
    const __nv_bfloat16* __restrict__ Wh, const __nv_bfloat16* __restrict__ Wl,
    __nv_bfloat16* __restrict__ Oh, __nv_bfloat16* __restrict__ Ol,
    float* __restrict__ Of) {
    extern __shared__ __nv_bfloat16 sm[];
    __nv_bfloat16* sA = sm;
    __nv_bfloat16* sW = sm + 2 * G_SA;

    const int tid = threadIdx.x;
    const int lane = tid & 31, wid = tid >> 5;
    const int wm = (wid >> 2) * 64, wn = (wid & 3) * 32;
    const int gr = lane >> 2, gc = (lane & 3) * 2;
    const int m0 = blockIdx.y * 128, n0 = blockIdx.x * 128;

    const int lrow = tid >> 2;
    const int lseg = (tid & 3) << 3;

    // ldmatrix lane address components
    const int a_row = lane & 15, a_colo = (lane >> 4) << 3;                 // A-pattern
    const int b_row = ((lane >> 4) << 3) + (lane & 7), b_colo = ((lane >> 3) & 1) << 3;  // B-pattern
    const uint32_t sAb = smem_u32(sA);
    const uint32_t sWb = smem_u32(sW);

    float acc[4][4][4];
#pragma unroll
    for (int i = 0; i < 4; i++)
#pragma unroll
        for (int j = 0; j < 4; j++)
#pragma unroll
            for (int c = 0; c < 4; c++) acc[i][j][c] = 0.f;

    auto load_stage = [&](int st, int k0) {
#pragma unroll
        for (int i = 0; i < 2; i++) {
            int row = lrow + i * 64;
            __nv_bfloat16* da = sA + st * G_SA + row * 40 + lseg;
            cpa16(da, Ah + (size_t)(m0 + row) * ND + k0 + lseg);
            cpa16(da + G_PL, Al + (size_t)(m0 + row) * ND + k0 + lseg);
            __nv_bfloat16* dw = sW + st * G_SA + row * 40 + lseg;
            cpa16(dw, Wh + (size_t)(n0 + row) * ND + k0 + lseg);
            cpa16(dw + G_PL, Wl + (size_t)(n0 + row) * ND + k0 + lseg);
        }
    };

    load_stage(0, 0);
    CP_COMMIT();

    for (int k0 = 0; k0 < ND; k0 += 32) {
        const int st = (k0 >> 5) & 1;
        if (k0 + 32 < ND) load_stage(st ^ 1, k0 + 32);
        CP_COMMIT();
        cp_wait<1>();
        __syncthreads();

        const uint32_t sa0 = sAb + (uint32_t)(st * G_SA) * 2;
        const uint32_t sw0 = sWb + (uint32_t)(st * G_SA) * 2;

#pragma unroll
        for (int kk = 0; kk < 2; kk++) {
            const int kb = kk * 16;
            uint32_t bh[4][2], bl[4][2], t[4];
#pragma unroll
            for (int p2 = 0; p2 < 2; p2++) {
                const uint32_t ad = sw0 + (uint32_t)((wn + p2 * 16 + b_row) * 40 + kb + b_colo) * 2;
                ldsm_x4(t, ad);
                bh[2 * p2][0] = t[0]; bh[2 * p2][1] = t[1];
                bh[2 * p2 + 1][0] = t[2]; bh[2 * p2 + 1][1] = t[3];
                ldsm_x4(t, ad + G_PL * 2);
                bl[2 * p2][0] = t[0]; bl[2 * p2][1] = t[1];
                bl[2 * p2 + 1][0] = t[2]; bl[2 * p2 + 1][1] = t[3];
            }
#pragma unroll
            for (int mf = 0; mf < 4; mf++) {
                uint32_t ah[4], al[4];
                const uint32_t ad = sa0 + (uint32_t)((wm + mf * 16 + a_row) * 40 + kb + a_colo) * 2;
                ldsm_x4(ah, ad);
                ldsm_x4(al, ad + G_PL * 2);
#pragma unroll
                for (int nf = 0; nf < 4; nf++) {
                    mma_bf16(acc[mf][nf], ah, bh[nf][0], bh[nf][1]);
                    mma_bf16(acc[mf][nf], ah, bl[nf][0], bl[nf][1]);
                    mma_bf16(acc[mf][nf], al, bh[nf][0], bh[nf][1]);
                }
            }
        }
        __syncthreads();
    }

    // epilogue
#pragma unroll
    for (int mf = 0; mf < 4; mf++) {
        const int r0 = m0 + wm + mf * 16 + gr;
#pragma unroll
        for (int nf = 0; nf < 4; nf++) {
            const int c0 = n0 + wn + nf * 8 + gc;
            float* a = acc[mf][nf];
            if (MODE == 2) {
                float2 v0 = make_float2(a[0], a[1]);
                float2 v1 = make_float2(a[2], a[3]);
                *(float2*)&Of[(size_t)r0 * ND + c0] = v0;
                *(float2*)&Of[(size_t)(r0 + 8) * ND + c0] = v1;
            } else {
                const int bb = r0 >> 11, ss = r0 & (NS - 1);
                const int hh = c0 >> 6, dk = c0 & 63;
                if (MODE == 0) {
                    size_t b0 = (((size_t)bb * NH + hh) * NS + ss) * NDK + dk;
                    size_t b1 = (((size_t)bb * NH + hh) * NS + ss + 8) * NDK + dk;
                    split_store2(Oh + b0, Ol + b0, a[0], a[1]);
                    split_store2(Oh + b1, Ol + b1, a[2], a[3]);
                } else {  // MODE 1: [B,H,DK,S]
                    size_t base = (((size_t)bb * NH + hh) * NDK + dk) * NS + ss;
                    __nv_bfloat16 h0 = __float2bfloat16(a[0]);
                    __nv_bfloat16 h1 = __float2bfloat16(a[1]);
                    __nv_bfloat16 h2 = __float2bfloat16(a[2]);
                    __nv_bfloat16 h3 = __float2bfloat16(a[3]);
                    Oh[base] = h0;          Ol[base] = __float2bfloat16(a[0] - __bfloat162float(h0));
                    Oh[base + NS] = h1;     Ol[base + NS] = __float2bfloat16(a[1] - __bfloat162float(h1));
                    Oh[base + 8] = h2;      Ol[base + 8] = __float2bfloat16(a[2] - __bfloat162float(h2));
                    Oh[base + NS + 8] = h3; Ol[base + NS + 8] = __float2bfloat16(a[3] - __bfloat162float(h3));
                }
            }
        }
    }
}

// ---------------- flash attention, bf16x2 3-pass mma, ldmatrix ----------------
#define A_QP (128 * 72)
#define A_KP (64 * 72)
#define A_KS (2 * A_KP)
#define ATT_SMEM ((2 * A_QP + 2 * A_KS + 2 * A_KS) * 2)

__global__ __launch_bounds__(256) void attn_kernel(
    const __nv_bfloat16* __restrict__ Qh, const __nv_bfloat16* __restrict__ Ql,
    const __nv_bfloat16* __restrict__ Kh, const __nv_bfloat16* __restrict__ Kl,
    const __nv_bfloat16* __restrict__ Vh, const __nv_bfloat16* __restrict__ Vl,
    __nv_bfloat16* __restrict__ Xh, __nv_bfloat16* __restrict__ Xl) {
    extern __shared__ __nv_bfloat16 sm[];
    __nv_bfloat16* sQ = sm;
    __nv_bfloat16* sK = sm + 2 * A_QP;
    __nv_bfloat16* sV = sK + 2 * A_KS;

    const int tid = threadIdx.x;
    const int lane = tid & 31, wid = tid >> 5;
    const int gr = lane >> 2, gc = (lane & 3) * 2;
    const int qb = (gridDim.x - 1) - blockIdx.x;
    const int h = blockIdx.y, b = blockIdx.z;

    const size_t bqk = ((size_t)b * NH + h) * NS * NDK;
    const size_t bv = ((size_t)b * NH + h) * NDK * NS;
    const size_t qoff = bqk + (size_t)qb * 128 * NDK;

    // ldmatrix lane address components
    const int a_row = lane & 15, a_colo = (lane >> 4) << 3;
    const int b_row = ((lane >> 4) << 3) + (lane & 7), b_colo = ((lane >> 3) & 1) << 3;
    const uint32_t sKb = smem_u32(sK);
    const uint32_t sVb = smem_u32(sV);
    const uint32_t sPb = smem_u32(sQ);  // P reuses sQ

    auto load_kv = [&](int st, int kt) {
#pragma unroll
        for (int i = 0; i < 4; i++) {
            int idx = tid + 256 * i;
            int p = idx >> 9, r = (idx >> 3) & 63, seg = (idx & 7) * 8;
            cpa16(sK + st * A_KS + p * A_KP + r * 72 + seg,
                  (p ? Kl : Kh) + bqk + (size_t)(kt * 64 + r) * NDK + seg);
            cpa16(sV + st * A_KS + p * A_KP + r * 72 + seg,
                  (p ? Vl : Vh) + bv + (size_t)r * NS + kt * 64 + seg);
        }
    };

#pragma unroll
    for (int i = 0; i < 8; i++) {
        int idx = tid + 256 * i;
        int p = idx >> 10, r = (idx >> 3) & 127, seg = (idx & 7) * 8;
        cpa16(sQ + p * A_QP + r * 72 + seg, (p ? Ql : Qh) + qoff + (size_t)r * NDK + seg);
    }
    load_kv(0, 0);
    CP_COMMIT();
    cp_wait<0>();
    __syncthreads();

    // Q fragments -> registers (ldmatrix, reused across all k-tiles)
    uint32_t qfh[4][4], qfl[4][4];
#pragma unroll
    for (int df = 0; df < 4; df++) {
        const uint32_t ad = sPb + (uint32_t)((wid * 16 + a_row) * 72 + df * 16 + a_colo) * 2;
        ldsm_x4(qfh[df], ad);
        ldsm_x4(qfl[df], ad + A_QP * 2);
    }
    __syncthreads();  // sQ now reusable as P
    __nv_bfloat16* sPh = sQ;
    __nv_bfloat16* sPl = sQ + A_QP;

    float O[8][4];
#pragma unroll
    for (int i = 0; i < 8; i++)
#pragma unroll
        for (int j = 0; j < 4; j++) O[i][j] = 0.f;
    float mrA = -INFINITY, mrB = -INFINITY, lrA = 0.f, lrB = 0.f;

    const int nkt = 2 * qb + 2;
    const int growA = qb * 128 + wid * 16 + gr;
    const int growB = growA + 8;

    for (int kt = 0; kt < nkt; kt++) {
        const int st = kt & 1;
        if (kt + 1 < nkt) load_kv(st ^ 1, kt + 1);
        CP_COMMIT();
        cp_wait<1>();
        __syncthreads();

        const bool act = !(kt == 2 * qb + 1 && wid < 4);
        if (act) {
            const uint32_t sk0 = sKb + (uint32_t)(st * A_KS) * 2;
            const uint32_t sv0 = sVb + (uint32_t)(st * A_KS) * 2;

            // ---- S = Q K^T ----
            float S[8][4];
#pragma unroll
            for (int i = 0; i < 8; i++)
#pragma unroll
                for (int j = 0; j < 4; j++) S[i][j] = 0.f;
#pragma unroll
            for (int df = 0; df < 4; df++) {
#pragma unroll
                for (int pr = 0; pr < 4; pr++) {
                    uint32_t th[4], tl[4];
                    const uint32_t ad = sk0 + (uint32_t)((pr * 16 + b_row) * 72 + df * 16 + b_colo) * 2;
                    ldsm_x4(th, ad);
                    ldsm_x4(tl, ad + A_KP * 2);
                    mma_bf16(S[2 * pr], qfh[df], th[0], th[1]);
                    mma_bf16(S[2 * pr], qfh[df], tl[0], tl[1]);
                    mma_bf16(S[2 * pr], qfl[df], th[0], th[1]);
                    mma_bf16(S[2 * pr + 1], qfh[df], th[2], th[3]);
                    mma_bf16(S[2 * pr + 1], qfh[df], tl[2], tl[3]);
                    mma_bf16(S[2 * pr + 1], qfl[df], th[2], th[3]);
                }
            }

            // ---- scale + mask ----
            const float sc = 0.125f;
#pragma unroll
            for (int nf = 0; nf < 8; nf++)
#pragma unroll
                for (int j = 0; j < 4; j++) S[nf][j] *= sc;
            if (kt >= 2 * qb) {
#pragma unroll
                for (int nf = 0; nf < 8; nf++) {
                    const int col = kt * 64 + nf * 8 + gc;
                    if (col > growA) S[nf][0] = -1e30f;
                    if (col + 1 > growA) S[nf][1] = -1e30f;
                    if (col > growB) S[nf][2] = -1e30f;
                    if (col + 1 > growB) S[nf][3] = -1e30f;
                }
            }

            // ---- online softmax ----
            float mA = -INFINITY, mB = -INFINITY;
#pragma unroll
            for (int nf = 0; nf < 8; nf++) {
                mA = fmaxf(mA, fmaxf(S[nf][0], S[nf][1]));
                mB = fmaxf(mB, fmaxf(S[nf][2], S[nf][3]));
            }
            mA = fmaxf(mA, __shfl_xor_sync(0xffffffffu, mA, 1));
            mA = fmaxf(mA, __shfl_xor_sync(0xffffffffu, mA, 2));
            mB = fmaxf(mB, __shfl_xor_sync(0xffffffffu, mB, 1));
            mB = fmaxf(mB, __shfl_xor_sync(0xffffffffu, mB, 2));
            const float mnA = fmaxf(mrA, mA), mnB = fmaxf(mrB, mB);
            const float aA = __expf(mrA - mnA), aB = __expf(mrB - mnB);
            float rsA = 0.f, rsB = 0.f;
            const int prow = wid * 16 + gr;
#pragma unroll
            for (int nf = 0; nf < 8; nf++) {
                float p0 = __expf(S[nf][0] - mnA);
                float p1 = __expf(S[nf][1] - mnA);
                float p2 = __expf(S[nf][2] - mnB);
                float p3 = __expf(S[nf][3] - mnB);
                rsA += p0 + p1; rsB += p2 + p3;
                const int pc = nf * 8 + gc;
                split_store2(sPh + prow * 72 + pc, sPl + prow * 72 + pc, p0, p1);
                split_store2(sPh + (prow + 8) * 72 + pc, sPl + (prow + 8) * 72 + pc, p2, p3);
            }
            rsA += __shfl_xor_sync(0xffffffffu, rsA, 1);
            rsA += __shfl_xor_sync(0xffffffffu, rsA, 2);
            rsB += __shfl_xor_sync(0xffffffffu, rsB, 1);
            rsB += __shfl_xor_sync(0xffffffffu, rsB, 2);
            lrA = lrA * aA + rsA; mrA = mnA;
            lrB = lrB * aB + rsB; mrB = mnB;
#pragma unroll
            for (int df = 0; df < 8; df++) {
                O[df][0] *= aA; O[df][1] *= aA;
                O[df][2] *= aB; O[df][3] *= aB;
            }
            __syncwarp();

            // ---- O += P V ----
#pragma unroll
            for (int ks = 0; ks < 4; ks++) {
                uint32_t ph[4], pl[4];
                const uint32_t pad = sPb + (uint32_t)((wid * 16 + a_row) * 72 + ks * 16 + a_colo) * 2;
                ldsm_x4(ph, pad);
                ldsm_x4(pl, pad + A_QP * 2);
#pragma unroll
                for (int pr = 0; pr < 4; pr++) {
                    uint32_t vh[4], vl[4];
                    const uint32_t vad = sv0 + (uint32_t)((pr * 16 + b_row) * 72 + ks * 16 + b_colo) * 2;
                    ldsm_x4(vh, vad);
                    ldsm_x4(vl, vad + A_KP * 2);
                    mma_bf16(O[2 * pr], ph, vh[0], vh[1]);
                    mma_bf16(O[2 * pr], ph, vl[0], vl[1]);
                    mma_bf16(O[2 * pr], pl, vh[0], vh[1]);
                    mma_bf16(O[2 * pr + 1], ph, vh[2], vh[3]);
                    mma_bf16(O[2 * pr + 1], ph, vl[2], vl[3]);
                    mma_bf16(O[2 * pr + 1], pl, vh[2], vh[3]);
                }
            }
        }
        __syncthreads();
    }

    // ---- epilogue ----
    const float iA = 1.0f / lrA, iB = 1.0f / lrB;
    const size_t baseA = ((size_t)b * NS + growA) * ND + h * NDK;
    const size_t baseB = ((size_t)b * NS + growB) * ND + h * NDK;
#pragma unroll
    for (int df = 0; df < 8; df++) {
        const int col = df * 8 + gc;
        split_store2(Xh + baseA + col, Xl + baseA + col, O[df][0] * iA, O[df][1] * iA);
        split_store2(Xh + baseB + col, Xl + baseB + col, O[df][2] * iB, O[df][3] * iB);
    }
}

// ---------------- launch ----------------
extern "C" void kernel_launch(void* const* d_in, const int* in_sizes, int n_in,
                              void* d_out, int out_size) {
    const float* q = (const float*)d_in[0];
    const float* k = (const float*)d_in[1];
    const float* v = (const float*)d_in[2];
    const float* wq = (const float*)d_in[4];
    const float* wk = (const float*)d_in[5];
    const float* wv = (const float*)d_in[6];
    const float* wo = (const float*)d_in[7];
    float* out = (float*)d_out;

    __nv_bfloat16 *qh, *ql, *kh, *kl, *vh, *vl;
    __nv_bfloat16 *wqh, *wql, *wkh, *wkl, *wvh, *wvl, *woh, *wol;
    __nv_bfloat16 *Qh, *Ql, *Kh, *Kl, *Vh, *Vl, *Xh, *Xl;
    cudaGetSymbolAddress((void**)&qh, g_qh);   cudaGetSymbolAddress((void**)&ql, g_ql);
    cudaGetSymbolAddress((void**)&kh, g_kh);   cudaGetSymbolAddress((void**)&kl, g_kl);
    cudaGetSymbolAddress((void**)&vh, g_vh);   cudaGetSymbolAddress((void**)&vl, g_vl);
    cudaGetSymbolAddress((void**)&wqh, g_wqh); cudaGetSymbolAddress((void**)&wql, g_wql);
    cudaGetSymbolAddress((void**)&wkh, g_wkh); cudaGetSymbolAddress((void**)&wkl, g_wkl);
    cudaGetSymbolAddress((void**)&wvh, g_wvh); cudaGetSymbolAddress((void**)&wvl, g_wvl);
    cudaGetSymbolAddress((void**)&woh, g_woh); cudaGetSymbolAddress((void**)&wol, g_wol);
    cudaGetSymbolAddress((void**)&Qh, g_Qh);   cudaGetSymbolAddress((void**)&Ql, g_Ql);
    cudaGetSymbolAddress((void**)&Kh, g_Kh);   cudaGetSymbolAddress((void**)&Kl, g_Kl);
    cudaGetSymbolAddress((void**)&Vh, g_Vh);   cudaGetSymbolAddress((void**)&Vl, g_Vl);
    cudaGetSymbolAddress((void**)&Xh, g_Xh);   cudaGetSymbolAddress((void**)&Xl, g_Xl);

    cudaFuncSetAttribute(gemm_bf16x2<0>, cudaFuncAttributeMaxDynamicSharedMemorySize, GEMM_SMEM);
    cudaFuncSetAttribute(gemm_bf16x2<1>, cudaFuncAttributeMaxDynamicSharedMemorySize, GEMM_SMEM);
    cudaFuncSetAttribute(gemm_bf16x2<2>, cudaFuncAttributeMaxDynamicSharedMemorySize, GEMM_SMEM);
    cudaFuncSetAttribute(attn_kernel, cudaFuncAttributeMaxDynamicSharedMemorySize, ATT_SMEM);

    const int nA = NM * ND, nW = ND * ND;
    split3_kernel<<<dim3(nA / 4 / 256, 3), 256>>>(q, k, v, qh, ql, kh, kl, vh, vl, nA);
    split4_kernel<<<dim3(nW / 4 / 256, 4), 256>>>(wq, wk, wv, wo,
                                                  wqh, wql, wkh, wkl, wvh, wvl, woh, wol, nW);

    dim3 pg(ND / 128, NM / 128);  // (8, 64)
    gemm_bf16x2<0><<<pg, 256, GEMM_SMEM>>>(qh, ql, wqh, wql, Qh, Ql, nullptr);
    gemm_bf16x2<0><<<pg, 256, GEMM_SMEM>>>(kh, kl, wkh, wkl, Kh, Kl, nullptr);
    gemm_bf16x2<1><<<pg, 256, GEMM_SMEM>>>(vh, vl, wvh, wvl, Vh, Vl, nullptr);

    attn_kernel<<<dim3(NS / 128, NH, NB), 256, ATT_SMEM>>>(Qh, Ql, Kh, Kl, Vh, Vl, Xh, Xl);

    gemm_bf16x2<2><<<pg, 256, GEMM_SMEM>>>(Xh, Xl, woh, wol, nullptr, nullptr, out);
}

// round 9
// speedup vs baseline: 2.8341x; 1.0020x over previous
#include <cuda_runtime.h>
#include <cuda_bf16.h>
#include <math.h>
#include <stdint.h>

#define NB 4
#define NS 2048
#define ND 1024
#define NH 16
#define NDK 64
#define NM (NB * NS)  // 8192

// ---------------- device scratch (allocation-free rule) ----------------
__device__ __nv_bfloat16 g_qh[NM * ND], g_ql[NM * ND];
__device__ __nv_bfloat16 g_kh[NM * ND], g_kl[NM * ND];
__device__ __nv_bfloat16 g_vh[NM * ND], g_vl[NM * ND];
__device__ __nv_bfloat16 g_wqh[ND * ND], g_wql[ND * ND];
__device__ __nv_bfloat16 g_wkh[ND * ND], g_wkl[ND * ND];
__device__ __nv_bfloat16 g_wvh[ND * ND], g_wvl[ND * ND];
__device__ __nv_bfloat16 g_woh[ND * ND], g_wol[ND * ND];
__device__ __nv_bfloat16 g_Qh[NM * ND], g_Ql[NM * ND];
__device__ __nv_bfloat16 g_Kh[NM * ND], g_Kl[NM * ND];
__device__ __nv_bfloat16 g_Vh[NM * ND], g_Vl[NM * ND];   // [B,H,DK,S]
__device__ __nv_bfloat16 g_Xh[NM * ND], g_Xl[NM * ND];

// ---------------- helpers ----------------
__device__ __forceinline__ uint32_t smem_u32(const void* p) {
    return (uint32_t)__cvta_generic_to_shared(p);
}

__device__ __forceinline__ void mma_bf16(float* d, const uint32_t* a, uint32_t b0, uint32_t b1) {
    asm volatile(
        "mma.sync.aligned.m16n8k16.row.col.f32.bf16.bf16.f32 "
        "{%0,%1,%2,%3}, {%4,%5,%6,%7}, {%8,%9}, {%0,%1,%2,%3};\n"
        : "+f"(d[0]), "+f"(d[1]), "+f"(d[2]), "+f"(d[3])
        : "r"(a[0]), "r"(a[1]), "r"(a[2]), "r"(a[3]), "r"(b0), "r"(b1));
}

__device__ __forceinline__ void ldsm_x4(uint32_t* r, uint32_t addr) {
    asm volatile("ldmatrix.sync.aligned.m8n8.x4.shared.b16 {%0,%1,%2,%3}, [%4];"
                 : "=r"(r[0]), "=r"(r[1]), "=r"(r[2]), "=r"(r[3])
                 : "r"(addr));
}

__device__ __forceinline__ void cpa16(__nv_bfloat16* dst, const __nv_bfloat16* src) {
    uint32_t d = (uint32_t)__cvta_generic_to_shared(dst);
    asm volatile("cp.async.ca.shared.global [%0], [%1], 16;\n" ::"r"(d), "l"(src));
}
#define CP_COMMIT() asm volatile("cp.async.commit_group;\n")
template <int N>
__device__ __forceinline__ void cp_wait() {
    asm volatile("cp.async.wait_group %0;\n" ::"n"(N));
}

__device__ __forceinline__ void split_store2(__nv_bfloat16* ph, __nv_bfloat16* pl,
                                             float x, float y) {
    __nv_bfloat16 hx = __float2bfloat16(x), hy = __float2bfloat16(y);
    __nv_bfloat162 h2; h2.x = hx; h2.y = hy;
    *(__nv_bfloat162*)ph = h2;
    __nv_bfloat162 l2;
    l2.x = __float2bfloat16(x - __bfloat162float(hx));
    l2.y = __float2bfloat16(y - __bfloat162float(hy));
    *(__nv_bfloat162*)pl = l2;
}

// ---------------- prep: fp32 -> bf16 hi/lo planes (fused) ----------------
__global__ void split3_kernel(const float* s0, const float* s1, const float* s2,
                              __nv_bfloat16* h0, __nv_bfloat16* l0,
                              __nv_bfloat16* h1, __nv_bfloat16* l1,
                              __nv_bfloat16* h2, __nv_bfloat16* l2, int n) {
    const float* s = (blockIdx.y == 0) ? s0 : (blockIdx.y == 1) ? s1 : s2;
    __nv_bfloat16* h = (blockIdx.y == 0) ? h0 : (blockIdx.y == 1) ? h1 : h2;
    __nv_bfloat16* l = (blockIdx.y == 0) ? l0 : (blockIdx.y == 1) ? l1 : l2;
    int i = (blockIdx.x * blockDim.x + threadIdx.x) * 4;
    if (i < n) {
        float4 v = *(const float4*)(s + i);
        split_store2(h + i, l + i, v.x, v.y);
        split_store2(h + i + 2, l + i + 2, v.z, v.w);
    }
}
__global__ void split4_kernel(const float* s0, const float* s1, const float* s2, const float* s3,
                              __nv_bfloat16* h0, __nv_bfloat16* l0,
                              __nv_bfloat16* h1, __nv_bfloat16* l1,
                              __nv_bfloat16* h2, __nv_bfloat16* l2,
                              __nv_bfloat16* h3, __nv_bfloat16* l3, int n) {
    const float* s = (blockIdx.y == 0) ? s0 : (blockIdx.y == 1) ? s1 : (blockIdx.y == 2) ? s2 : s3;
    __nv_bfloat16* h = (blockIdx.y == 0) ? h0 : (blockIdx.y == 1) ? h1 : (blockIdx.y == 2) ? h2 : h3;
    __nv_bfloat16* l = (blockIdx.y == 0) ? l0 : (blockIdx.y == 1) ? l1 : (blockIdx.y == 2) ? l2 : l3;
    int i = (blockIdx.x * blockDim.x + threadIdx.x) * 4;
    if (i < n) {
        float4 v = *(const float4*)(s + i);
        split_store2(h + i, l + i, v.x, v.y);
        split_store2(h + i + 2, l + i + 2, v.z, v.w);
    }
}

// ---------------- GEMM: C[m,n] = sum_k A[m,k] * W[n,k], bf16x2 3-pass, ldmatrix ----------------
#define G_PL (128 * 40)
#define G_SA (2 * G_PL)
#define GEMM_SMEM (4 * G_SA * 2)

template <int MODE>
__global__ __launch_bounds__(256) void gemm_bf16x2(
    const __nv_bfloat16* __restrict__ Ah, const __nv_bfloat16* __restrict__ Al,
    const __nv_bfloat16* __restrict__ Wh, const __nv_bfloat16* __restrict__ Wl,
    __nv_bfloat16* __restrict__ Oh, __nv_bfloat16* __restrict__ Ol,
    float* __restrict__ Of) {
    extern __shared__ __nv_bfloat16 sm[];
    __nv_bfloat16* sA = sm;
    __nv_bfloat16* sW = sm + 2 * G_SA;

    const int tid = threadIdx.x;
    const int lane = tid & 31, wid = tid >> 5;
    const int wm = (wid >> 2) * 64, wn = (wid & 3) * 32;
    const int gr = lane >> 2, gc = (lane & 3) * 2;
    const int m0 = blockIdx.y * 128, n0 = blockIdx.x * 128;

    const int lrow = tid >> 2;
    const int lseg = (tid & 3) << 3;

    const int a_row = lane & 15, a_colo = (lane >> 4) << 3;
    const int b_row = ((lane >> 4) << 3) + (lane & 7), b_colo = ((lane >> 3) & 1) << 3;
    const uint32_t sAb = smem_u32(sA);
    const uint32_t sWb = smem_u32(sW);

    float acc[4][4][4];
#pragma unroll
    for (int i = 0; i < 4; i++)
#pragma unroll
        for (int j = 0; j < 4; j++)
#pragma unroll
            for (int c = 0; c < 4; c++) acc[i][j][c] = 0.f;

    auto load_stage = [&](int st, int k0) {
#pragma unroll
        for (int i = 0; i < 2; i++) {
            int row = lrow + i * 64;
            __nv_bfloat16* da = sA + st * G_SA + row * 40 + lseg;
            cpa16(da, Ah + (size_t)(m0 + row) * ND + k0 + lseg);
            cpa16(da + G_PL, Al + (size_t)(m0 + row) * ND + k0 + lseg);
            __nv_bfloat16* dw = sW + st * G_SA + row * 40 + lseg;
            cpa16(dw, Wh + (size_t)(n0 + row) * ND + k0 + lseg);
            cpa16(dw + G_PL, Wl + (size_t)(n0 + row) * ND + k0 + lseg);
        }
    };

    load_stage(0, 0);
    CP_COMMIT();

    for (int k0 = 0; k0 < ND; k0 += 32) {
        const int st = (k0 >> 5) & 1;
        if (k0 + 32 < ND) load_stage(st ^ 1, k0 + 32);
        CP_COMMIT();
        cp_wait<1>();
        __syncthreads();

        const uint32_t sa0 = sAb + (uint32_t)(st * G_SA) * 2;
        const uint32_t sw0 = sWb + (uint32_t)(st * G_SA) * 2;

#pragma unroll
        for (int kk = 0; kk < 2; kk++) {
            const int kb = kk * 16;
            uint32_t bh[4][2], bl[4][2], t[4];
#pragma unroll
            for (int p2 = 0; p2 < 2; p2++) {
                const uint32_t ad = sw0 + (uint32_t)((wn + p2 * 16 + b_row) * 40 + kb + b_colo) * 2;
                ldsm_x4(t, ad);
                bh[2 * p2][0] = t[0]; bh[2 * p2][1] = t[1];
                bh[2 * p2 + 1][0] = t[2]; bh[2 * p2 + 1][1] = t[3];
                ldsm_x4(t, ad + G_PL * 2);
                bl[2 * p2][0] = t[0]; bl[2 * p2][1] = t[1];
                bl[2 * p2 + 1][0] = t[2]; bl[2 * p2 + 1][1] = t[3];
            }
#pragma unroll
            for (int mf = 0; mf < 4; mf++) {
                uint32_t ah[4], al[4];
                const uint32_t ad = sa0 + (uint32_t)((wm + mf * 16 + a_row) * 40 + kb + a_colo) * 2;
                ldsm_x4(ah, ad);
                ldsm_x4(al, ad + G_PL * 2);
                // pass-major ordering: each acc reuse separated by 4 independent MMAs
#pragma unroll
                for (int nf = 0; nf < 4; nf++) mma_bf16(acc[mf][nf], ah, bh[nf][0], bh[nf][1]);
#pragma unroll
                for (int nf = 0; nf < 4; nf++) mma_bf16(acc[mf][nf], ah, bl[nf][0], bl[nf][1]);
#pragma unroll
                for (int nf = 0; nf < 4; nf++) mma_bf16(acc[mf][nf], al, bh[nf][0], bh[nf][1]);
            }
        }
        __syncthreads();
    }

    // epilogue
#pragma unroll
    for (int mf = 0; mf < 4; mf++) {
        const int r0 = m0 + wm + mf * 16 + gr;
#pragma unroll
        for (int nf = 0; nf < 4; nf++) {
            const int c0 = n0 + wn + nf * 8 + gc;
            float* a = acc[mf][nf];
            if (MODE == 2) {
                float2 v0 = make_float2(a[0], a[1]);
                float2 v1 = make_float2(a[2], a[3]);
                *(float2*)&Of[(size_t)r0 * ND + c0] = v0;
                *(float2*)&Of[(size_t)(r0 + 8) * ND + c0] = v1;
            } else {
                const int bb = r0 >> 11, ss = r0 & (NS - 1);
                const int hh = c0 >> 6, dk = c0 & 63;
                if (MODE == 0) {
                    size_t b0 = (((size_t)bb * NH + hh) * NS + ss) * NDK + dk;
                    size_t b1 = (((size_t)bb * NH + hh) * NS + ss + 8) * NDK + dk;
                    split_store2(Oh + b0, Ol + b0, a[0], a[1]);
                    split_store2(Oh + b1, Ol + b1, a[2], a[3]);
                } else {  // MODE 1: [B,H,DK,S]
                    size_t base = (((size_t)bb * NH + hh) * NDK + dk) * NS + ss;
                    __nv_bfloat16 h0 = __float2bfloat16(a[0]);
                    __nv_bfloat16 h1 = __float2bfloat16(a[1]);
                    __nv_bfloat16 h2 = __float2bfloat16(a[2]);
                    __nv_bfloat16 h3 = __float2bfloat16(a[3]);
                    Oh[base] = h0;          Ol[base] = __float2bfloat16(a[0] - __bfloat162float(h0));
                    Oh[base + NS] = h1;     Ol[base + NS] = __float2bfloat16(a[1] - __bfloat162float(h1));
                    Oh[base + 8] = h2;      Ol[base + 8] = __float2bfloat16(a[2] - __bfloat162float(h2));
                    Oh[base + NS + 8] = h3; Ol[base + NS + 8] = __float2bfloat16(a[3] - __bfloat162float(h3));
                }
            }
        }
    }
}

// ---------------- flash attention, bf16x2 3-pass mma, ldmatrix ----------------
#define A_QP (128 * 72)
#define A_KP (64 * 72)
#define A_KS (2 * A_KP)
#define ATT_SMEM ((2 * A_QP + 2 * A_KS + 2 * A_KS) * 2)

__global__ __launch_bounds__(256) void attn_kernel(
    const __nv_bfloat16* __restrict__ Qh, const __nv_bfloat16* __restrict__ Ql,
    const __nv_bfloat16* __restrict__ Kh, const __nv_bfloat16* __restrict__ Kl,
    const __nv_bfloat16* __restrict__ Vh, const __nv_bfloat16* __restrict__ Vl,
    __nv_bfloat16* __restrict__ Xh, __nv_bfloat16* __restrict__ Xl) {
    extern __shared__ __nv_bfloat16 sm[];
    __nv_bfloat16* sQ = sm;
    __nv_bfloat16* sK = sm + 2 * A_QP;
    __nv_bfloat16* sV = sK + 2 * A_KS;

    const int tid = threadIdx.x;
    const int lane = tid & 31, wid = tid >> 5;
    const int gr = lane >> 2, gc = (lane & 3) * 2;
    const int qb = (gridDim.x - 1) - blockIdx.x;
    const int h = blockIdx.y, b = blockIdx.z;

    const size_t bqk = ((size_t)b * NH + h) * NS * NDK;
    const size_t bv = ((size_t)b * NH + h) * NDK * NS;
    const size_t qoff = bqk + (size_t)qb * 128 * NDK;

    const int a_row = lane & 15, a_colo = (lane >> 4) << 3;
    const int b_row = ((lane >> 4) << 3) + (lane & 7), b_colo = ((lane >> 3) & 1) << 3;
    const uint32_t sKb = smem_u32(sK);
    const uint32_t sVb = smem_u32(sV);
    const uint32_t sPb = smem_u32(sQ);

    auto load_kv = [&](int st, int kt) {
#pragma unroll
        for (int i = 0; i < 4; i++) {
            int idx = tid + 256 * i;
            int p = idx >> 9, r = (idx >> 3) & 63, seg = (idx & 7) * 8;
            cpa16(sK + st * A_KS + p * A_KP + r * 72 + seg,
                  (p ? Kl : Kh) + bqk + (size_t)(kt * 64 + r) * NDK + seg);
            cpa16(sV + st * A_KS + p * A_KP + r * 72 + seg,
                  (p ? Vl : Vh) + bv + (size_t)r * NS + kt * 64 + seg);
        }
    };

#pragma unroll
    for (int i = 0; i < 8; i++) {
        int idx = tid + 256 * i;
        int p = idx >> 10, r = (idx >> 3) & 127, seg = (idx & 7) * 8;
        cpa16(sQ + p * A_QP + r * 72 + seg, (p ? Ql : Qh) + qoff + (size_t)r * NDK + seg);
    }
    load_kv(0, 0);
    CP_COMMIT();
    cp_wait<0>();
    __syncthreads();

    uint32_t qfh[4][4], qfl[4][4];
#pragma unroll
    for (int df = 0; df < 4; df++) {
        const uint32_t ad = sPb + (uint32_t)((wid * 16 + a_row) * 72 + df * 16 + a_colo) * 2;
        ldsm_x4(qfh[df], ad);
        ldsm_x4(qfl[df], ad + A_QP * 2);
    }
    __syncthreads();
    __nv_bfloat16* sPh = sQ;
    __nv_bfloat16* sPl = sQ + A_QP;

    float O[8][4];
#pragma unroll
    for (int i = 0; i < 8; i++)
#pragma unroll
        for (int j = 0; j < 4; j++) O[i][j] = 0.f;
    float mrA = -INFINITY, mrB = -INFINITY, lrA = 0.f, lrB = 0.f;

    const int nkt = 2 * qb + 2;
    const int growA = qb * 128 + wid * 16 + gr;
    const int growB = growA + 8;

    for (int kt = 0; kt < nkt; kt++) {
        const int st = kt & 1;
        if (kt + 1 < nkt) load_kv(st ^ 1, kt + 1);
        CP_COMMIT();
        cp_wait<1>();
        __syncthreads();

        const bool act = !(kt == 2 * qb + 1 && wid < 4);
        if (act) {
            const uint32_t sk0 = sKb + (uint32_t)(st * A_KS) * 2;
            const uint32_t sv0 = sVb + (uint32_t)(st * A_KS) * 2;

            // ---- S = Q K^T ----  (pass-interleaved: acc reuse distance 2)
            float S[8][4];
#pragma unroll
            for (int i = 0; i < 8; i++)
#pragma unroll
                for (int j = 0; j < 4; j++) S[i][j] = 0.f;
#pragma unroll
            for (int df = 0; df < 4; df++) {
#pragma unroll
                for (int pr = 0; pr < 4; pr++) {
                    uint32_t th[4], tl[4];
                    const uint32_t ad = sk0 + (uint32_t)((pr * 16 + b_row) * 72 + df * 16 + b_colo) * 2;
                    ldsm_x4(th, ad);
                    ldsm_x4(tl, ad + A_KP * 2);
                    mma_bf16(S[2 * pr],     qfh[df], th[0], th[1]);
                    mma_bf16(S[2 * pr + 1], qfh[df], th[2], th[3]);
                    mma_bf16(S[2 * pr],     qfh[df], tl[0], tl[1]);
                    mma_bf16(S[2 * pr + 1], qfh[df], tl[2], tl[3]);
                    mma_bf16(S[2 * pr],     qfl[df], th[0], th[1]);
                    mma_bf16(S[2 * pr + 1], qfl[df], th[2], th[3]);
                }
            }

            // ---- scale + mask ----
            const float sc = 0.125f;
#pragma unroll
            for (int nf = 0; nf < 8; nf++)
#pragma unroll
                for (int j = 0; j < 4; j++) S[nf][j] *= sc;
            if (kt >= 2 * qb) {
#pragma unroll
                for (int nf = 0; nf < 8; nf++) {
                    const int col = kt * 64 + nf * 8 + gc;
                    if (col > growA) S[nf][0] = -1e30f;
                    if (col + 1 > growA) S[nf][1] = -1e30f;
                    if (col > growB) S[nf][2] = -1e30f;
                    if (col + 1 > growB) S[nf][3] = -1e30f;
                }
            }

            // ---- online softmax ----
            float mA = -INFINITY, mB = -INFINITY;
#pragma unroll
            for (int nf = 0; nf < 8; nf++) {
                mA = fmaxf(mA, fmaxf(S[nf][0], S[nf][1]));
                mB = fmaxf(mB, fmaxf(S[nf][2], S[nf][3]));
            }
            mA = fmaxf(mA, __shfl_xor_sync(0xffffffffu, mA, 1));
            mA = fmaxf(mA, __shfl_xor_sync(0xffffffffu, mA, 2));
            mB = fmaxf(mB, __shfl_xor_sync(0xffffffffu, mB, 1));
            mB = fmaxf(mB, __shfl_xor_sync(0xffffffffu, mB, 2));
            const float mnA = fmaxf(mrA, mA), mnB = fmaxf(mrB, mB);
            const float aA = __expf(mrA - mnA), aB = __expf(mrB - mnB);
            float rsA = 0.f, rsB = 0.f;
            const int prow = wid * 16 + gr;
#pragma unroll
            for (int nf = 0; nf < 8; nf++) {
                float p0 = __expf(S[nf][0] - mnA);
                float p1 = __expf(S[nf][1] - mnA);
                float p2 = __expf(S[nf][2] - mnB);
                float p3 = __expf(S[nf][3] - mnB);
                rsA += p0 + p1; rsB += p2 + p3;
                const int pc = nf * 8 + gc;
                split_store2(sPh + prow * 72 + pc, sPl + prow * 72 + pc, p0, p1);
                split_store2(sPh + (prow + 8) * 72 + pc, sPl + (prow + 8) * 72 + pc, p2, p3);
            }
            rsA += __shfl_xor_sync(0xffffffffu, rsA, 1);
            rsA += __shfl_xor_sync(0xffffffffu, rsA, 2);
            rsB += __shfl_xor_sync(0xffffffffu, rsB, 1);
            rsB += __shfl_xor_sync(0xffffffffu, rsB, 2);
            lrA = lrA * aA + rsA; mrA = mnA;
            lrB = lrB * aB + rsB; mrB = mnB;
#pragma unroll
            for (int df = 0; df < 8; df++) {
                O[df][0] *= aA; O[df][1] *= aA;
                O[df][2] *= aB; O[df][3] *= aB;
            }
            __syncwarp();

            // ---- O += P V ----  (pass-interleaved)
#pragma unroll
            for (int ks = 0; ks < 4; ks++) {
                uint32_t ph[4], pl[4];
                const uint32_t pad = sPb + (uint32_t)((wid * 16 + a_row) * 72 + ks * 16 + a_colo) * 2;
                ldsm_x4(ph, pad);
                ldsm_x4(pl, pad + A_QP * 2);
#pragma unroll
                for (int pr = 0; pr < 4; pr++) {
                    uint32_t vh[4], vl[4];
                    const uint32_t vad = sv0 + (uint32_t)((pr * 16 + b_row) * 72 + ks * 16 + b_colo) * 2;
                    ldsm_x4(vh, vad);
                    ldsm_x4(vl, vad + A_KP * 2);
                    mma_bf16(O[2 * pr],     ph, vh[0], vh[1]);
                    mma_bf16(O[2 * pr + 1], ph, vh[2], vh[3]);
                    mma_bf16(O[2 * pr],     ph, vl[0], vl[1]);
                    mma_bf16(O[2 * pr + 1], ph, vl[2], vl[3]);
                    mma_bf16(O[2 * pr],     pl, vh[0], vh[1]);
                    mma_bf16(O[2 * pr + 1], pl, vh[2], vh[3]);
                }
            }
        }
        __syncthreads();
    }

    // ---- epilogue ----
    const float iA = 1.0f / lrA, iB = 1.0f / lrB;
    const size_t baseA = ((size_t)b * NS + growA) * ND + h * NDK;
    const size_t baseB = ((size_t)b * NS + growB) * ND + h * NDK;
#pragma unroll
    for (int df = 0; df < 8; df++) {
        const int col = df * 8 + gc;
        split_store2(Xh + baseA + col, Xl + baseA + col, O[df][0] * iA, O[df][1] * iA);
        split_store2(Xh + baseB + col, Xl + baseB + col, O[df][2] * iB, O[df][3] * iB);
    }
}

// ---------------- launch ----------------
extern "C" void kernel_launch(void* const* d_in, const int* in_sizes, int n_in,
                              void* d_out, int out_size) {
    const float* q = (const float*)d_in[0];
    const float* k = (const float*)d_in[1];
    const float* v = (const float*)d_in[2];
    const float* wq = (const float*)d_in[4];
    const float* wk = (const float*)d_in[5];
    const float* wv = (const float*)d_in[6];
    const float* wo = (const float*)d_in[7];
    float* out = (float*)d_out;

    __nv_bfloat16 *qh, *ql, *kh, *kl, *vh, *vl;
    __nv_bfloat16 *wqh, *wql, *wkh, *wkl, *wvh, *wvl, *woh, *wol;
    __nv_bfloat16 *Qh, *Ql, *Kh, *Kl, *Vh, *Vl, *Xh, *Xl;
    cudaGetSymbolAddress((void**)&qh, g_qh);   cudaGetSymbolAddress((void**)&ql, g_ql);
    cudaGetSymbolAddress((void**)&kh, g_kh);   cudaGetSymbolAddress((void**)&kl, g_kl);
    cudaGetSymbolAddress((void**)&vh, g_vh);   cudaGetSymbolAddress((void**)&vl, g_vl);
    cudaGetSymbolAddress((void**)&wqh, g_wqh); cudaGetSymbolAddress((void**)&wql, g_wql);
    cudaGetSymbolAddress((void**)&wkh, g_wkh); cudaGetSymbolAddress((void**)&wkl, g_wkl);
    cudaGetSymbolAddress((void**)&wvh, g_wvh); cudaGetSymbolAddress((void**)&wvl, g_wvl);
    cudaGetSymbolAddress((void**)&woh, g_woh); cudaGetSymbolAddress((void**)&wol, g_wol);
    cudaGetSymbolAddress((void**)&Qh, g_Qh);   cudaGetSymbolAddress((void**)&Ql, g_Ql);
    cudaGetSymbolAddress((void**)&Kh, g_Kh);   cudaGetSymbolAddress((void**)&Kl, g_Kl);
    cudaGetSymbolAddress((void**)&Vh, g_Vh);   cudaGetSymbolAddress((void**)&Vl, g_Vl);
    cudaGetSymbolAddress((void**)&Xh, g_Xh);   cudaGetSymbolAddress((void**)&Xl, g_Xl);

    cudaFuncSetAttribute(gemm_bf16x2<0>, cudaFuncAttributeMaxDynamicSharedMemorySize, GEMM_SMEM);
    cudaFuncSetAttribute(gemm_bf16x2<1>, cudaFuncAttributeMaxDynamicSharedMemorySize, GEMM_SMEM);
    cudaFuncSetAttribute(gemm_bf16x2<2>, cudaFuncAttributeMaxDynamicSharedMemorySize, GEMM_SMEM);
    cudaFuncSetAttribute(attn_kernel, cudaFuncAttributeMaxDynamicSharedMemorySize, ATT_SMEM);

    const int nA = NM * ND, nW = ND * ND;
    split3_kernel<<<dim3(nA / 4 / 256, 3), 256>>>(q, k, v, qh, ql, kh, kl, vh, vl, nA);
    split4_kernel<<<dim3(nW / 4 / 256, 4), 256>>>(wq, wk, wv, wo,
                                                  wqh, wql, wkh, wkl, wvh, wvl, woh, wol, nW);

    dim3 pg(ND / 128, NM / 128);  // (8, 64)
    gemm_bf16x2<0><<<pg, 256, GEMM_SMEM>>>(qh, ql, wqh, wql, Qh, Ql, nullptr);
    gemm_bf16x2<0><<<pg, 256, GEMM_SMEM>>>(kh, kl, wkh, wkl, Kh, Kl, nullptr);
    gemm_bf16x2<1><<<pg, 256, GEMM_SMEM>>>(vh, vl, wvh, wvl, Vh, Vl, nullptr);

    attn_kernel<<<dim3(NS / 128, NH, NB), 256, ATT_SMEM>>>(Qh, Ql, Kh, Kl, Vh, Vl, Xh, Xl);

    gemm_bf16x2<2><<<pg, 256, GEMM_SMEM>>>(Xh, Xl, woh, wol, nullptr, nullptr, out);
}

// round 11
// speedup vs baseline: 3.2560x; 1.1489x over previous
#include <cuda_runtime.h>
#include <cuda_bf16.h>
#include <math.h>
#include <stdint.h>

#define NB 4
#define NS 2048
#define ND 1024
#define NH 16
#define NDK 64
#define NM (NB * NS)  // 8192
#define NKB (ND / 64) // 16 k-blocks

// ---------------- device scratch: all planes in 64x64 swizzled tiles ----------------
// tile(m,k): elem = ((m>>6)*NKB + (k>>6))*4096 + (m&63)*64 + ((k&63) ^ ((m&7)<<3))
__device__ __align__(128) __nv_bfloat16 g_qh[NM * ND], g_ql[NM * ND];
__device__ __align__(128) __nv_bfloat16 g_kh[NM * ND], g_kl[NM * ND];
__device__ __align__(128) __nv_bfloat16 g_vh[NM * ND], g_vl[NM * ND];
__device__ __align__(128) __nv_bfloat16 g_wqh[ND * ND], g_wql[ND * ND];
__device__ __align__(128) __nv_bfloat16 g_wkh[ND * ND], g_wkl[ND * ND];
__device__ __align__(128) __nv_bfloat16 g_wvh[ND * ND], g_wvl[ND * ND];
__device__ __align__(128) __nv_bfloat16 g_woh[ND * ND], g_wol[ND * ND];
// Q,K: per (b,h): [32 s-tiles][64][64]  (tile index (b*16+h)*32+st)
__device__ __align__(128) __nv_bfloat16 g_Qh[NM * ND], g_Ql[NM * ND];
__device__ __align__(128) __nv_bfloat16 g_Kh[NM * ND], g_Kl[NM * ND];
// V: [h(16)][token-block(128)][64 dk][64 tok]
__device__ __align__(128) __nv_bfloat16 g_Vh[NM * ND], g_Vl[NM * ND];
// X: standard GEMM-A tiling over (token 8192, feature 1024)
__device__ __align__(128) __nv_bfloat16 g_Xh[NM * ND], g_Xl[NM * ND];

// ---------------- helpers ----------------
__device__ __forceinline__ uint32_t smem_u32(const void* p) {
    return (uint32_t)__cvta_generic_to_shared(p);
}
__device__ __forceinline__ void mma_bf16(float* d, const uint32_t* a, uint32_t b0, uint32_t b1) {
    asm volatile(
        "mma.sync.aligned.m16n8k16.row.col.f32.bf16.bf16.f32 "
        "{%0,%1,%2,%3}, {%4,%5,%6,%7}, {%8,%9}, {%0,%1,%2,%3};\n"
        : "+f"(d[0]), "+f"(d[1]), "+f"(d[2]), "+f"(d[3])
        : "r"(a[0]), "r"(a[1]), "r"(a[2]), "r"(a[3]), "r"(b0), "r"(b1));
}
__device__ __forceinline__ void ldsm_x4(uint32_t* r, uint32_t addr) {
    asm volatile("ldmatrix.sync.aligned.m8n8.x4.shared.b16 {%0,%1,%2,%3}, [%4];"
                 : "=r"(r[0]), "=r"(r[1]), "=r"(r[2]), "=r"(r[3])
                 : "r"(addr));
}
__device__ __forceinline__ void bulk_g2s(uint32_t dst, const void* src, uint32_t bytes,
                                         uint32_t mbar) {
    asm volatile(
        "cp.async.bulk.shared::cluster.global.mbarrier::complete_tx::bytes [%0], [%1], %2, [%3];"
        ::"r"(dst), "l"(src), "r"(bytes), "r"(mbar) : "memory");
}
__device__ __forceinline__ void mbar_init(uint32_t addr, uint32_t cnt) {
    asm volatile("mbarrier.init.shared.b64 [%0], %1;" ::"r"(addr), "r"(cnt) : "memory");
}
__device__ __forceinline__ void mbar_expect(uint32_t addr, uint32_t bytes) {
    asm volatile("mbarrier.arrive.expect_tx.shared.b64 _, [%0], %1;"
                 ::"r"(addr), "r"(bytes) : "memory");
}
__device__ __forceinline__ void mbar_wait(uint32_t addr, uint32_t parity) {
    asm volatile(
        "{\n\t.reg .pred P;\n\tWL_%=:\n\t"
        "mbarrier.try_wait.parity.acquire.cta.shared::cta.b64 P, [%0], %1, 0x989680;\n\t"
        "@P bra.uni WD_%=;\n\tbra.uni WL_%=;\n\tWD_%=:\n\t}"
        ::"r"(addr), "r"(parity) : "memory");
}

__device__ __forceinline__ void split_store2(__nv_bfloat16* ph, __nv_bfloat16* pl,
                                             float x, float y) {
    __nv_bfloat16 hx = __float2bfloat16(x), hy = __float2bfloat16(y);
    __nv_bfloat162 h2; h2.x = hx; h2.y = hy;
    *(__nv_bfloat162*)ph = h2;
    __nv_bfloat162 l2;
    l2.x = __float2bfloat16(x - __bfloat162float(hx));
    l2.y = __float2bfloat16(y - __bfloat162float(hy));
    *(__nv_bfloat162*)pl = l2;
}

// ---------------- split: fp32 row-major -> tiled swizzled bf16 hi/lo planes ----------------
__device__ __forceinline__ void split_one(const float* s, __nv_bfloat16* h, __nv_bfloat16* l,
                                          int g) {
    const int m = g >> 8;            // row
    const int k4 = (g & 255) << 2;   // 4 consecutive k
    float4 v = *(const float4*)(s + (size_t)m * ND + k4);
    size_t dst = ((size_t)((m >> 6) * NKB + (k4 >> 6))) * 4096 + (m & 63) * 64 +
                 ((k4 & 63) ^ ((m & 7) << 3));
    split_store2(h + dst, l + dst, v.x, v.y);
    split_store2(h + dst + 2, l + dst + 2, v.z, v.w);
}
__global__ void split3_kernel(const float* s0, const float* s1, const float* s2,
                              __nv_bfloat16* h0, __nv_bfloat16* l0,
                              __nv_bfloat16* h1, __nv_bfloat16* l1,
                              __nv_bfloat16* h2, __nv_bfloat16* l2) {
    int g = blockIdx.x * blockDim.x + threadIdx.x;
    const float* s = (blockIdx.y == 0) ? s0 : (blockIdx.y == 1) ? s1 : s2;
    __nv_bfloat16* h = (blockIdx.y == 0) ? h0 : (blockIdx.y == 1) ? h1 : h2;
    __nv_bfloat16* l = (blockIdx.y == 0) ? l0 : (blockIdx.y == 1) ? l1 : l2;
    split_one(s, h, l, g);
}
__global__ void split4_kernel(const float* s0, const float* s1, const float* s2, const float* s3,
                              __nv_bfloat16* h0, __nv_bfloat16* l0,
                              __nv_bfloat16* h1, __nv_bfloat16* l1,
                              __nv_bfloat16* h2, __nv_bfloat16* l2,
                              __nv_bfloat16* h3, __nv_bfloat16* l3) {
    int g = blockIdx.x * blockDim.x + threadIdx.x;
    const float* s = (blockIdx.y == 0) ? s0 : (blockIdx.y == 1) ? s1 : (blockIdx.y == 2) ? s2 : s3;
    __nv_bfloat16* h = (blockIdx.y == 0) ? h0 : (blockIdx.y == 1) ? h1 : (blockIdx.y == 2) ? h2 : h3;
    __nv_bfloat16* l = (blockIdx.y == 0) ? l0 : (blockIdx.y == 1) ? l1 : (blockIdx.y == 2) ? l2 : l3;
    split_one(s, h, l, g);
}

// ---------------- GEMM: D[m(128), n(128)] = sum_k A[m,k] B[n,k], TMA-bulk + bf16x2 3-pass ----
// stage: [Ah 16K][Al 16K][Bh 16K][Bl 16K] = 64KB; double-buffered.
#define GS_STAGE 65536
#define GS_MBAR (2 * GS_STAGE)
#define GEMM_SMEM (GS_MBAR + 16)

template <int MODE>  // 0: Q/K tiled out ; 1: V transposed tiled out ; 2: fp32 row-major out
__global__ __launch_bounds__(256) void gemm_tma(
    const __nv_bfloat16* __restrict__ Ah_, const __nv_bfloat16* __restrict__ Al_,
    const __nv_bfloat16* __restrict__ Bh_, const __nv_bfloat16* __restrict__ Bl_,
    __nv_bfloat16* __restrict__ Oh, __nv_bfloat16* __restrict__ Ol,
    float* __restrict__ Of) {
    extern __shared__ char smc[];
    const uint32_t sb = smem_u32(smc);
    const int tid = threadIdx.x;
    const int lane = tid & 31, wid = tid >> 5;
    const int wm = (wid >> 2) * 64, wn = (wid & 3) * 32;
    const int gr = lane >> 2, gc = (lane & 3) * 2;
    const int bx = blockIdx.x, by = blockIdx.y;

    const uint32_t mb0 = sb + GS_MBAR;
    if (tid == 0) { mbar_init(mb0, 1); mbar_init(mb0 + 8, 1); }
    __syncthreads();

    auto issue = [&](int st, int s) {
        if (tid == 0) {
            const uint32_t mb = mb0 + st * 8;
            mbar_expect(mb, 65536);
            const uint32_t d = sb + st * GS_STAGE;
#pragma unroll
            for (int t = 0; t < 2; t++) {
                bulk_g2s(d + t * 8192,         Ah_ + (size_t)((2 * by + t) * NKB + s) * 4096, 8192, mb);
                bulk_g2s(d + 16384 + t * 8192, Al_ + (size_t)((2 * by + t) * NKB + s) * 4096, 8192, mb);
                bulk_g2s(d + 32768 + t * 8192, Bh_ + (size_t)((2 * bx + t) * NKB + s) * 4096, 8192, mb);
                bulk_g2s(d + 49152 + t * 8192, Bl_ + (size_t)((2 * bx + t) * NKB + s) * 4096, 8192, mb);
            }
        }
    };
    issue(0, 0);
    issue(1, 1);

    const int arow_l = lane & 15;
    const uint32_t acol = (lane >> 4) << 4;              // byte
    const int brow_l = ((lane >> 4) << 3) + (lane & 7);
    const uint32_t bcol = ((lane >> 3) & 1) << 4;        // byte

    float acc[4][4][4];
#pragma unroll
    for (int i = 0; i < 4; i++)
#pragma unroll
        for (int j = 0; j < 4; j++)
#pragma unroll
            for (int c = 0; c < 4; c++) acc[i][j][c] = 0.f;

    uint32_t ph[2] = {0, 0};
    for (int s = 0; s < NKB; s++) {
        const int st = s & 1;
        mbar_wait(mb0 + st * 8, ph[st]);
        ph[st] ^= 1;
        const uint32_t base = sb + st * GS_STAGE;

#pragma unroll
        for (int kk = 0; kk < 4; kk++) {
            const uint32_t kb = kk * 32;  // byte offset of 16-k chunk
            uint32_t bh[4][2], bl[4][2], t[4];
#pragma unroll
            for (int p2 = 0; p2 < 2; p2++) {
                const int row = wn + p2 * 16 + brow_l;
                const uint32_t ad = base + 32768 + ((row >> 6) << 13) + ((row & 63) << 7) +
                                    ((kb + bcol) ^ ((row & 7) << 4));
                ldsm_x4(t, ad);
                bh[2 * p2][0] = t[0]; bh[2 * p2][1] = t[1];
                bh[2 * p2 + 1][0] = t[2]; bh[2 * p2 + 1][1] = t[3];
                ldsm_x4(t, ad + 16384);
                bl[2 * p2][0] = t[0]; bl[2 * p2][1] = t[1];
                bl[2 * p2 + 1][0] = t[2]; bl[2 * p2 + 1][1] = t[3];
            }
#pragma unroll
            for (int mf = 0; mf < 4; mf++) {
                const int row = wm + mf * 16 + arow_l;
                const uint32_t ad = base + ((row >> 6) << 13) + ((row & 63) << 7) +
                                    ((kb + acol) ^ ((row & 7) << 4));
                uint32_t ah[4], al[4];
                ldsm_x4(ah, ad);
                ldsm_x4(al, ad + 16384);
#pragma unroll
                for (int nf = 0; nf < 4; nf++) mma_bf16(acc[mf][nf], ah, bh[nf][0], bh[nf][1]);
#pragma unroll
                for (int nf = 0; nf < 4; nf++) mma_bf16(acc[mf][nf], ah, bl[nf][0], bl[nf][1]);
#pragma unroll
                for (int nf = 0; nf < 4; nf++) mma_bf16(acc[mf][nf], al, bh[nf][0], bh[nf][1]);
            }
        }
        __syncthreads();
        if (s + 2 < NKB) issue(st, s + 2);
    }

    // epilogue
#pragma unroll
    for (int mf = 0; mf < 4; mf++) {
        const int rowg = by * 128 + wm + mf * 16 + gr;
#pragma unroll
        for (int nf = 0; nf < 4; nf++) {
            const int col = bx * 128 + wn + nf * 8 + gc;
            float* a = acc[mf][nf];
            if (MODE == 2) {
                *(float2*)&Of[(size_t)rowg * ND + col] = make_float2(a[0], a[1]);
                *(float2*)&Of[(size_t)(rowg + 8) * ND + col] = make_float2(a[2], a[3]);
            } else if (MODE == 0) {
                const int b = rowg >> 11, s_ = rowg & (NS - 1);
                const int st_ = s_ >> 6, r = s_ & 63;
                const int h = col >> 6, dk = col & 63;
                size_t e0 = ((size_t)((b * NH + h) * 32 + st_) * 64 + r) * 64 +
                            (dk ^ ((r & 7) << 3));
                split_store2(Oh + e0, Ol + e0, a[0], a[1]);
                split_store2(Oh + e0 + 512, Ol + e0 + 512, a[2], a[3]);  // row+8
            } else {  // MODE 1: V transposed. rows = feature, cols = token
                const int h = rowg >> 6, fr = rowg & 63;
                const int tb = col >> 6, tc = col & 63;
                size_t e0 = ((size_t)(h * 128 + tb) * 64 + fr) * 64 + (tc ^ ((fr & 7) << 3));
                split_store2(Oh + e0, Ol + e0, a[0], a[1]);
                split_store2(Oh + e0 + 512, Ol + e0 + 512, a[2], a[3]);  // feat+8
            }
        }
    }
}

// ---------------- flash attention: TMA-bulk KV, bf16x2 3-pass, ldmatrix ----------------
// smem: [Q/P: plane-h 16K | plane-l 16K][KV stage0 32K][KV stage1 32K][mbar]
// KV stage: [Kh 8K][Kl 8K][Vh 8K][Vl 8K]
#define AT_KV 32768
#define AT_STG 32768
#define AT_MBAR (AT_KV + 2 * AT_STG)  // 98304
#define ATT_SMEM (AT_MBAR + 16)

__global__ __launch_bounds__(256) void attn_kernel(
    const __nv_bfloat16* __restrict__ Qh_, const __nv_bfloat16* __restrict__ Ql_,
    const __nv_bfloat16* __restrict__ Kh_, const __nv_bfloat16* __restrict__ Kl_,
    const __nv_bfloat16* __restrict__ Vh_, const __nv_bfloat16* __restrict__ Vl_,
    __nv_bfloat16* __restrict__ Xh, __nv_bfloat16* __restrict__ Xl) {
    extern __shared__ char smc[];
    const uint32_t sb = smem_u32(smc);
    __nv_bfloat16* smb = (__nv_bfloat16*)smc;

    const int tid = threadIdx.x;
    const int lane = tid & 31, wid = tid >> 5;
    const int gr = lane >> 2, gc = (lane & 3) * 2;
    const int qb = (gridDim.x - 1) - blockIdx.x;  // longest first
    const int h = blockIdx.y, b = blockIdx.z;

    const int qkbase = (b * NH + h) * 32;   // tile-index base for Q/K planes
    const int vbase = h * 128 + b * 32;     // tile-index base for V planes

    const uint32_t mb0 = sb + AT_MBAR;
    if (tid == 0) { mbar_init(mb0, 1); mbar_init(mb0 + 8, 1); }
    __syncthreads();

    auto issueKV = [&](int st, int kt, bool withQ) {
        if (tid == 0) {
            const uint32_t mb = mb0 + st * 8;
            mbar_expect(mb, withQ ? 65536u : 32768u);
            if (withQ) {
#pragma unroll
                for (int t = 0; t < 2; t++) {
                    bulk_g2s(sb + t * 8192,         Qh_ + (size_t)(qkbase + 2 * qb + t) * 4096, 8192, mb);
                    bulk_g2s(sb + 16384 + t * 8192, Ql_ + (size_t)(qkbase + 2 * qb + t) * 4096, 8192, mb);
                }
            }
            const uint32_t d = sb + AT_KV + st * AT_STG;
            bulk_g2s(d,         Kh_ + (size_t)(qkbase + kt) * 4096, 8192, mb);
            bulk_g2s(d + 8192,  Kl_ + (size_t)(qkbase + kt) * 4096, 8192, mb);
            bulk_g2s(d + 16384, Vh_ + (size_t)(vbase + kt) * 4096, 8192, mb);
            bulk_g2s(d + 24576, Vl_ + (size_t)(vbase + kt) * 4096, 8192, mb);
        }
    };
    const int nkt = 2 * qb + 2;
    issueKV(0, 0, true);
    issueKV(1, 1, false);

    const int arow_l = lane & 15;
    const uint32_t acol = (lane >> 4) << 4;
    const int brow_l = ((lane >> 4) << 3) + (lane & 7);
    const uint32_t bcol = ((lane >> 3) & 1) << 4;

    uint32_t qfh[4][4], qfl[4][4];
    float O[8][4];
#pragma unroll
    for (int i = 0; i < 8; i++)
#pragma unroll
        for (int j = 0; j < 4; j++) O[i][j] = 0.f;
    float mrA = -INFINITY, mrB = -INFINITY, lrA = 0.f, lrB = 0.f;

    const int growA = qb * 128 + wid * 16 + gr;  // local q row (within b,h)
    const int growB = growA + 8;
    const int prow = wid * 16 + gr;

    uint32_t ph[2] = {0, 0};
    for (int kt = 0; kt < nkt; kt++) {
        const int st = kt & 1;
        mbar_wait(mb0 + st * 8, ph[st]);
        ph[st] ^= 1;

        if (kt == 0) {
            // extract Q fragments from tiled sQ (then region becomes P)
            const int row = wid * 16 + arow_l;
            const uint32_t rq = ((row >> 6) << 13) + ((row & 63) << 7);
#pragma unroll
            for (int df = 0; df < 4; df++) {
                const uint32_t ad = sb + rq + (((uint32_t)(df * 32) + acol) ^ ((row & 7) << 4));
                ldsm_x4(qfh[df], ad);
                ldsm_x4(qfl[df], ad + 16384);
            }
            __syncthreads();
        }

        const uint32_t kvb = sb + AT_KV + st * AT_STG;
        const bool act = !(kt == 2 * qb + 1 && wid < 4);
        if (act) {
            // ---- S = Q K^T ----
            float S[8][4];
#pragma unroll
            for (int i = 0; i < 8; i++)
#pragma unroll
                for (int j = 0; j < 4; j++) S[i][j] = 0.f;
#pragma unroll
            for (int df = 0; df < 4; df++) {
#pragma unroll
                for (int pr = 0; pr < 4; pr++) {
                    const int row = pr * 16 + brow_l;
                    const uint32_t ad = kvb + (row << 7) +
                                        (((uint32_t)(df * 32) + bcol) ^ ((row & 7) << 4));
                    uint32_t th[4], tl[4];
                    ldsm_x4(th, ad);
                    ldsm_x4(tl, ad + 8192);
                    mma_bf16(S[2 * pr],     qfh[df], th[0], th[1]);
                    mma_bf16(S[2 * pr + 1], qfh[df], th[2], th[3]);
                    mma_bf16(S[2 * pr],     qfh[df], tl[0], tl[1]);
                    mma_bf16(S[2 * pr + 1], qfh[df], tl[2], tl[3]);
                    mma_bf16(S[2 * pr],     qfl[df], th[0], th[1]);
                    mma_bf16(S[2 * pr + 1], qfl[df], th[2], th[3]);
                }
            }

            // ---- scale + causal mask ----
            const float sc = 0.125f;
#pragma unroll
            for (int nf = 0; nf < 8; nf++)
#pragma unroll
                for (int j = 0; j < 4; j++) S[nf][j] *= sc;
            if (kt >= 2 * qb) {
#pragma unroll
                for (int nf = 0; nf < 8; nf++) {
                    const int col = kt * 64 + nf * 8 + gc;
                    if (col > growA) S[nf][0] = -1e30f;
                    if (col + 1 > growA) S[nf][1] = -1e30f;
                    if (col > growB) S[nf][2] = -1e30f;
                    if (col + 1 > growB) S[nf][3] = -1e30f;
                }
            }

            // ---- online softmax ----
            float mA = -INFINITY, mB = -INFINITY;
#pragma unroll
            for (int nf = 0; nf < 8; nf++) {
                mA = fmaxf(mA, fmaxf(S[nf][0], S[nf][1]));
                mB = fmaxf(mB, fmaxf(S[nf][2], S[nf][3]));
            }
            mA = fmaxf(mA, __shfl_xor_sync(0xffffffffu, mA, 1));
            mA = fmaxf(mA, __shfl_xor_sync(0xffffffffu, mA, 2));
            mB = fmaxf(mB, __shfl_xor_sync(0xffffffffu, mB, 1));
            mB = fmaxf(mB, __shfl_xor_sync(0xffffffffu, mB, 2));
            const float mnA = fmaxf(mrA, mA), mnB = fmaxf(mrB, mB);
            const float aA = __expf(mrA - mnA), aB = __expf(mrB - mnB);
            float rsA = 0.f, rsB = 0.f;
            const uint32_t sA0 = (uint32_t)prow * 64;
            const uint32_t sB0 = (uint32_t)(prow + 8) * 64;
            const uint32_t swA = (uint32_t)((prow & 7) << 3);
#pragma unroll
            for (int nf = 0; nf < 8; nf++) {
                float p0 = __expf(S[nf][0] - mnA);
                float p1 = __expf(S[nf][1] - mnA);
                float p2 = __expf(S[nf][2] - mnB);
                float p3 = __expf(S[nf][3] - mnB);
                rsA += p0 + p1; rsB += p2 + p3;
                const uint32_t pc = (uint32_t)(nf * 8 + gc);
                const uint32_t eA = sA0 + (pc ^ swA);
                const uint32_t eB = sB0 + (pc ^ swA);  // (prow+8)&7 == prow&7
                split_store2(smb + eA, smb + 8192 + eA, p0, p1);
                split_store2(smb + eB, smb + 8192 + eB, p2, p3);
            }
            rsA += __shfl_xor_sync(0xffffffffu, rsA, 1);
            rsA += __shfl_xor_sync(0xffffffffu, rsA, 2);
            rsB += __shfl_xor_sync(0xffffffffu, rsB, 1);
            rsB += __shfl_xor_sync(0xffffffffu, rsB, 2);
            lrA = lrA * aA + rsA; mrA = mnA;
            lrB = lrB * aB + rsB; mrB = mnB;
#pragma unroll
            for (int df = 0; df < 8; df++) {
                O[df][0] *= aA; O[df][1] *= aA;
                O[df][2] *= aB; O[df][3] *= aB;
            }
            __syncwarp();

            // ---- O += P V ----
            const int prowf = wid * 16 + arow_l;
            const uint32_t pbase = sb + (uint32_t)(prowf << 7);
#pragma unroll
            for (int ks = 0; ks < 4; ks++) {
                uint32_t ph_[4], pl_[4];
                const uint32_t pad = pbase + (((uint32_t)(ks * 32) + acol) ^ ((prowf & 7) << 4));
                ldsm_x4(ph_, pad);
                ldsm_x4(pl_, pad + 16384);
#pragma unroll
                for (int pr = 0; pr < 4; pr++) {
                    const int row = pr * 16 + brow_l;  // dk row
                    const uint32_t vad = kvb + 16384 + (row << 7) +
                                         (((uint32_t)(ks * 32) + bcol) ^ ((row & 7) << 4));
                    uint32_t vh[4], vl[4];
                    ldsm_x4(vh, vad);
                    ldsm_x4(vl, vad + 8192);
                    mma_bf16(O[2 * pr],     ph_, vh[0], vh[1]);
                    mma_bf16(O[2 * pr + 1], ph_, vh[2], vh[3]);
                    mma_bf16(O[2 * pr],     ph_, vl[0], vl[1]);
                    mma_bf16(O[2 * pr + 1], ph_, vl[2], vl[3]);
                    mma_bf16(O[2 * pr],     pl_, vh[0], vh[1]);
                    mma_bf16(O[2 * pr + 1], pl_, vh[2], vh[3]);
                }
            }
        }
        __syncthreads();
        if (kt + 2 < nkt) issueKV(st, kt + 2, false);
    }

    // ---- epilogue: X in GEMM-A tiled layout over (token, feature) ----
    const float iA = 1.0f / lrA, iB = 1.0f / lrB;
    const int gA = b * NS + growA;  // global token row
    const int r = gA & 63;
    const size_t e0 = ((size_t)((gA >> 6) * NKB + h) * 64 + r) * 64;
    const uint32_t sw = (uint32_t)((r & 7) << 3);
#pragma unroll
    for (int df = 0; df < 8; df++) {
        const uint32_t c = (uint32_t)(df * 8 + gc);
        const size_t eA = e0 + (c ^ sw);
        const size_t eB = eA + 512;  // row+8, same swizzle
        split_store2(Xh + eA, Xl + eA, O[df][0] * iA, O[df][1] * iA);
        split_store2(Xh + eB, Xl + eB, O[df][2] * iB, O[df][3] * iB);
    }
}

// ---------------- launch ----------------
extern "C" void kernel_launch(void* const* d_in, const int* in_sizes, int n_in,
                              void* d_out, int out_size) {
    const float* q = (const float*)d_in[0];
    const float* k = (const float*)d_in[1];
    const float* v = (const float*)d_in[2];
    const float* wq = (const float*)d_in[4];
    const float* wk = (const float*)d_in[5];
    const float* wv = (const float*)d_in[6];
    const float* wo = (const float*)d_in[7];
    float* out = (float*)d_out;

    __nv_bfloat16 *qh, *ql, *kh, *kl, *vh, *vl;
    __nv_bfloat16 *wqh, *wql, *wkh, *wkl, *wvh, *wvl, *woh, *wol;
    __nv_bfloat16 *Qh, *Ql, *Kh, *Kl, *Vh, *Vl, *Xh, *Xl;
    cudaGetSymbolAddress((void**)&qh, g_qh);   cudaGetSymbolAddress((void**)&ql, g_ql);
    cudaGetSymbolAddress((void**)&kh, g_kh);   cudaGetSymbolAddress((void**)&kl, g_kl);
    cudaGetSymbolAddress((void**)&vh, g_vh);   cudaGetSymbolAddress((void**)&vl, g_vl);
    cudaGetSymbolAddress((void**)&wqh, g_wqh); cudaGetSymbolAddress((void**)&wql, g_wql);
    cudaGetSymbolAddress((void**)&wkh, g_wkh); cudaGetSymbolAddress((void**)&wkl, g_wkl);
    cudaGetSymbolAddress((void**)&wvh, g_wvh); cudaGetSymbolAddress((void**)&wvl, g_wvl);
    cudaGetSymbolAddress((void**)&woh, g_woh); cudaGetSymbolAddress((void**)&wol, g_wol);
    cudaGetSymbolAddress((void**)&Qh, g_Qh);   cudaGetSymbolAddress((void**)&Ql, g_Ql);
    cudaGetSymbolAddress((void**)&Kh, g_Kh);   cudaGetSymbolAddress((void**)&Kl, g_Kl);
    cudaGetSymbolAddress((void**)&Vh, g_Vh);   cudaGetSymbolAddress((void**)&Vl, g_Vl);
    cudaGetSymbolAddress((void**)&Xh, g_Xh);   cudaGetSymbolAddress((void**)&Xl, g_Xl);

    cudaFuncSetAttribute(gemm_tma<0>, cudaFuncAttributeMaxDynamicSharedMemorySize, GEMM_SMEM);
    cudaFuncSetAttribute(gemm_tma<1>, cudaFuncAttributeMaxDynamicSharedMemorySize, GEMM_SMEM);
    cudaFuncSetAttribute(gemm_tma<2>, cudaFuncAttributeMaxDynamicSharedMemorySize, GEMM_SMEM);
    cudaFuncSetAttribute(attn_kernel, cudaFuncAttributeMaxDynamicSharedMemorySize, ATT_SMEM);

    // splits: one thread per 4 elems
    split3_kernel<<<dim3(NM * ND / 4 / 256, 3), 256>>>(q, k, v, qh, ql, kh, kl, vh, vl);
    split4_kernel<<<dim3(ND * ND / 4 / 256, 4), 256>>>(wq, wk, wv, wo,
                                                       wqh, wql, wkh, wkl, wvh, wvl, woh, wol);

    dim3 pg(ND / 128, NM / 128);  // (8, 64)
    gemm_tma<0><<<pg, 256, GEMM_SMEM>>>(qh, ql, wqh, wql, Qh, Ql, nullptr);
    gemm_tma<0><<<pg, 256, GEMM_SMEM>>>(kh, kl, wkh, wkl, Kh, Kl, nullptr);
    // V: A = weights (feature rows), B = activations (token rows) -> D[feat][tok]
    dim3 gv(NM / 128, ND / 128);  // (64, 8)
    gemm_tma<1><<<gv, 256, GEMM_SMEM>>>(wvh, wvl, vh, vl, Vh, Vl, nullptr);

    attn_kernel<<<dim3(NS / 128, NH, NB), 256, ATT_SMEM>>>(Qh, Ql, Kh, Kl, Vh, Vl, Xh, Xl);

    gemm_tma<2><<<pg, 256, GEMM_SMEM>>>(Xh, Xl, woh, wol, nullptr, nullptr, out);
}

// round 14
// speedup vs baseline: 3.4211x; 1.0507x over previous
#include <cuda_runtime.h>
#include <cuda_bf16.h>
#include <math.h>
#include <stdint.h>

#define NB 4
#define NS 2048
#define ND 1024
#define NH 16
#define NDK 64
#define NM (NB * NS)  // 8192
#define NKB (ND / 64) // 16 k-blocks

// ---------------- device scratch: all planes in 64x64 swizzled tiles ----------------
// tile(m,k): elem = ((m>>6)*NKB + (k>>6))*4096 + (m&63)*64 + ((k&63) ^ ((m&7)<<3))
__device__ __align__(128) __nv_bfloat16 g_qh[NM * ND], g_ql[NM * ND];
__device__ __align__(128) __nv_bfloat16 g_kh[NM * ND], g_kl[NM * ND];
__device__ __align__(128) __nv_bfloat16 g_vh[NM * ND], g_vl[NM * ND];
__device__ __align__(128) __nv_bfloat16 g_wqh[ND * ND], g_wql[ND * ND];
__device__ __align__(128) __nv_bfloat16 g_wkh[ND * ND], g_wkl[ND * ND];
__device__ __align__(128) __nv_bfloat16 g_wvh[ND * ND], g_wvl[ND * ND];
__device__ __align__(128) __nv_bfloat16 g_woh[ND * ND], g_wol[ND * ND];
// Q,K,V: per (b,h): [32 s-tiles][64 tok][64 dk]  (tile index (b*16+h)*32+st)
__device__ __align__(128) __nv_bfloat16 g_Qh[NM * ND], g_Ql[NM * ND];
__device__ __align__(128) __nv_bfloat16 g_Kh[NM * ND], g_Kl[NM * ND];
__device__ __align__(128) __nv_bfloat16 g_Vh[NM * ND], g_Vl[NM * ND];
// X: GEMM-A tiling over (token 8192, feature 1024)
__device__ __align__(128) __nv_bfloat16 g_Xh[NM * ND], g_Xl[NM * ND];

// ---------------- helpers ----------------
__device__ __forceinline__ uint32_t smem_u32(const void* p) {
    return (uint32_t)__cvta_generic_to_shared(p);
}
__device__ __forceinline__ void mma_bf16(float* d, const uint32_t* a, uint32_t b0, uint32_t b1) {
    asm volatile(
        "mma.sync.aligned.m16n8k16.row.col.f32.bf16.bf16.f32 "
        "{%0,%1,%2,%3}, {%4,%5,%6,%7}, {%8,%9}, {%0,%1,%2,%3};\n"
        : "+f"(d[0]), "+f"(d[1]), "+f"(d[2]), "+f"(d[3])
        : "r"(a[0]), "r"(a[1]), "r"(a[2]), "r"(a[3]), "r"(b0), "r"(b1));
}
__device__ __forceinline__ void ldsm_x4(uint32_t* r, uint32_t addr) {
    asm volatile("ldmatrix.sync.aligned.m8n8.x4.shared.b16 {%0,%1,%2,%3}, [%4];"
                 : "=r"(r[0]), "=r"(r[1]), "=r"(r[2]), "=r"(r[3])
                 : "r"(addr));
}
__device__ __forceinline__ void ldsm_x4_t(uint32_t* r, uint32_t addr) {
    asm volatile("ldmatrix.sync.aligned.m8n8.x4.trans.shared.b16 {%0,%1,%2,%3}, [%4];"
                 : "=r"(r[0]), "=r"(r[1]), "=r"(r[2]), "=r"(r[3])
                 : "r"(addr));
}
__device__ __forceinline__ void bulk_g2s(uint32_t dst, const void* src, uint32_t bytes,
                                         uint32_t mbar) {
    asm volatile(
        "cp.async.bulk.shared::cluster.global.mbarrier::complete_tx::bytes [%0], [%1], %2, [%3];"
        ::"r"(dst), "l"(src), "r"(bytes), "r"(mbar) : "memory");
}
__device__ __forceinline__ void mbar_init(uint32_t addr, uint32_t cnt) {
    asm volatile("mbarrier.init.shared.b64 [%0], %1;" ::"r"(addr), "r"(cnt) : "memory");
}
__device__ __forceinline__ void mbar_expect(uint32_t addr, uint32_t bytes) {
    asm volatile("mbarrier.arrive.expect_tx.shared.b64 _, [%0], %1;"
                 ::"r"(addr), "r"(bytes) : "memory");
}
__device__ __forceinline__ void mbar_wait(uint32_t addr, uint32_t parity) {
    asm volatile(
        "{\n\t.reg .pred P;\n\tWL_%=:\n\t"
        "mbarrier.try_wait.parity.acquire.cta.shared::cta.b64 P, [%0], %1, 0x989680;\n\t"
        "@P bra.uni WD_%=;\n\tbra.uni WL_%=;\n\tWD_%=:\n\t}"
        ::"r"(addr), "r"(parity) : "memory");
}
__device__ __forceinline__ void split_store2(__nv_bfloat16* ph, __nv_bfloat16* pl,
                                             float x, float y) {
    __nv_bfloat16 hx = __float2bfloat16(x), hy = __float2bfloat16(y);
    __nv_bfloat162 h2; h2.x = hx; h2.y = hy;
    *(__nv_bfloat162*)ph = h2;
    __nv_bfloat162 l2;
    l2.x = __float2bfloat16(x - __bfloat162float(hx));
    l2.y = __float2bfloat16(y - __bfloat162float(hy));
    *(__nv_bfloat162*)pl = l2;
}

// ---------------- split: fp32 row-major -> tiled swizzled bf16 hi/lo planes ----------------
__device__ __forceinline__ void split_one(const float* s, __nv_bfloat16* h, __nv_bfloat16* l,
                                          int g) {
    const int m = g >> 8;
    const int k4 = (g & 255) << 2;
    float4 v = *(const float4*)(s + (size_t)m * ND + k4);
    size_t dst = ((size_t)((m >> 6) * NKB + (k4 >> 6))) * 4096 + (m & 63) * 64 +
                 ((k4 & 63) ^ ((m & 7) << 3));
    split_store2(h + dst, l + dst, v.x, v.y);
    split_store2(h + dst + 2, l + dst + 2, v.z, v.w);
}
__global__ void split3_kernel(const float* s0, const float* s1, const float* s2,
                              __nv_bfloat16* h0, __nv_bfloat16* l0,
                              __nv_bfloat16* h1, __nv_bfloat16* l1,
                              __nv_bfloat16* h2, __nv_bfloat16* l2) {
    int g = blockIdx.x * blockDim.x + threadIdx.x;
    const float* s = (blockIdx.y == 0) ? s0 : (blockIdx.y == 1) ? s1 : s2;
    __nv_bfloat16* h = (blockIdx.y == 0) ? h0 : (blockIdx.y == 1) ? h1 : h2;
    __nv_bfloat16* l = (blockIdx.y == 0) ? l0 : (blockIdx.y == 1) ? l1 : l2;
    split_one(s, h, l, g);
}
__global__ void split4_kernel(const float* s0, const float* s1, const float* s2, const float* s3,
                              __nv_bfloat16* h0, __nv_bfloat16* l0,
                              __nv_bfloat16* h1, __nv_bfloat16* l1,
                              __nv_bfloat16* h2, __nv_bfloat16* l2,
                              __nv_bfloat16* h3, __nv_bfloat16* l3) {
    int g = blockIdx.x * blockDim.x + threadIdx.x;
    const float* s = (blockIdx.y == 0) ? s0 : (blockIdx.y == 1) ? s1 : (blockIdx.y == 2) ? s2 : s3;
    __nv_bfloat16* h = (blockIdx.y == 0) ? h0 : (blockIdx.y == 1) ? h1 : (blockIdx.y == 2) ? h2 : h3;
    __nv_bfloat16* l = (blockIdx.y == 0) ? l0 : (blockIdx.y == 1) ? l1 : (blockIdx.y == 2) ? l2 : l3;
    split_one(s, h, l, g);
}

// ---------------- GEMM core: D[m(128), n(128)] = sum_k A[m,k] B[n,k] ----------------
#define GS_STAGE 65536
#define GS_MBAR (2 * GS_STAGE)
#define GEMM_SMEM (GS_MBAR + 16)

struct QKVParams {
    const __nv_bfloat16 *ah[3], *al[3], *bh[3], *bl[3];
    __nv_bfloat16 *oh[3], *ol[3];
};

__device__ __forceinline__ void gemm_mainloop(
    uint32_t sb, const __nv_bfloat16* Ah_, const __nv_bfloat16* Al_,
    const __nv_bfloat16* Bh_, const __nv_bfloat16* Bl_, int bx, int by,
    float acc[4][4][4]) {
    const int tid = threadIdx.x;
    const int lane = tid & 31, wid = tid >> 5;
    const int wm = (wid >> 2) * 64, wn = (wid & 3) * 32;

    const uint32_t mb0 = sb + GS_MBAR;
    if (tid == 0) { mbar_init(mb0, 1); mbar_init(mb0 + 8, 1); }
    __syncthreads();

    auto issue = [&](int st, int s) {
        if (tid == 0) {
            const uint32_t mb = mb0 + st * 8;
            mbar_expect(mb, 65536);
            const uint32_t d = sb + st * GS_STAGE;
#pragma unroll
            for (int t = 0; t < 2; t++) {
                bulk_g2s(d + t * 8192,         Ah_ + (size_t)((2 * by + t) * NKB + s) * 4096, 8192, mb);
                bulk_g2s(d + 16384 + t * 8192, Al_ + (size_t)((2 * by + t) * NKB + s) * 4096, 8192, mb);
                bulk_g2s(d + 32768 + t * 8192, Bh_ + (size_t)((2 * bx + t) * NKB + s) * 4096, 8192, mb);
                bulk_g2s(d + 49152 + t * 8192, Bl_ + (size_t)((2 * bx + t) * NKB + s) * 4096, 8192, mb);
            }
        }
    };
    issue(0, 0);
    issue(1, 1);

    const int arow_l = lane & 15;
    const uint32_t acol = (lane >> 4) << 4;
    const int brow_l = ((lane >> 4) << 3) + (lane & 7);
    const uint32_t bcol = ((lane >> 3) & 1) << 4;

    uint32_t ph[2] = {0, 0};
    for (int s = 0; s < NKB; s++) {
        const int st = s & 1;
        mbar_wait(mb0 + st * 8, ph[st]);
        ph[st] ^= 1;
        const uint32_t base = sb + st * GS_STAGE;

#pragma unroll
        for (int kk = 0; kk < 4; kk++) {
            const uint32_t kb = kk * 32;
            // ---- batch ALL loads first ----
            uint32_t bh[4][2], bl[4][2], t[4];
            uint32_t ah[4][4], al[4][4];
#pragma unroll
            for (int p2 = 0; p2 < 2; p2++) {
                const int row = wn + p2 * 16 + brow_l;
                const uint32_t ad = base + 32768 + ((row >> 6) << 13) + ((row & 63) << 7) +
                                    ((kb + bcol) ^ ((row & 7) << 4));
                ldsm_x4(t, ad);
                bh[2 * p2][0] = t[0]; bh[2 * p2][1] = t[1];
                bh[2 * p2 + 1][0] = t[2]; bh[2 * p2 + 1][1] = t[3];
                ldsm_x4(t, ad + 16384);
                bl[2 * p2][0] = t[0]; bl[2 * p2][1] = t[1];
                bl[2 * p2 + 1][0] = t[2]; bl[2 * p2 + 1][1] = t[3];
            }
#pragma unroll
            for (int mf = 0; mf < 4; mf++) {
                const int row = wm + mf * 16 + arow_l;
                const uint32_t ad = base + ((row >> 6) << 13) + ((row & 63) << 7) +
                                    ((kb + acol) ^ ((row & 7) << 4));
                ldsm_x4(ah[mf], ad);
                ldsm_x4(al[mf], ad + 16384);
            }
            // ---- then 48 dependency-free MMAs ----
#pragma unroll
            for (int mf = 0; mf < 4; mf++) {
#pragma unroll
                for (int nf = 0; nf < 4; nf++) mma_bf16(acc[mf][nf], ah[mf], bh[nf][0], bh[nf][1]);
#pragma unroll
                for (int nf = 0; nf < 4; nf++) mma_bf16(acc[mf][nf], ah[mf], bl[nf][0], bl[nf][1]);
#pragma unroll
                for (int nf = 0; nf < 4; nf++) mma_bf16(acc[mf][nf], al[mf], bh[nf][0], bh[nf][1]);
            }
        }
        __syncthreads();
        if (s + 2 < NKB) issue(st, s + 2);
    }
}

// merged Q/K/V projection: grid (8, 64, 3)
__global__ __launch_bounds__(256) void gemm_qkv(QKVParams prm) {
    extern __shared__ char smc[];
    const uint32_t sb = smem_u32(smc);
    const int z = blockIdx.z;
    const int bx = blockIdx.x, by = blockIdx.y;
    const int tid = threadIdx.x;
    const int lane = tid & 31, wid = tid >> 5;
    const int wm = (wid >> 2) * 64, wn = (wid & 3) * 32;
    const int gr = lane >> 2, gc = (lane & 3) * 2;

    float acc[4][4][4];
#pragma unroll
    for (int i = 0; i < 4; i++)
#pragma unroll
        for (int j = 0; j < 4; j++)
#pragma unroll
            for (int c = 0; c < 4; c++) acc[i][j][c] = 0.f;

    gemm_mainloop(sb, prm.ah[z], prm.al[z], prm.bh[z], prm.bl[z], bx, by, acc);

    __nv_bfloat16* Oh = prm.oh[z];
    __nv_bfloat16* Ol = prm.ol[z];
#pragma unroll
    for (int mf = 0; mf < 4; mf++) {
        const int rowg = by * 128 + wm + mf * 16 + gr;
#pragma unroll
        for (int nf = 0; nf < 4; nf++) {
            const int col = bx * 128 + wn + nf * 8 + gc;
            float* a = acc[mf][nf];
            const int b = rowg >> 11, s_ = rowg & (NS - 1);
            const int st_ = s_ >> 6, r = s_ & 63;
            const int h = col >> 6, dk = col & 63;
            size_t e0 = ((size_t)((b * NH + h) * 32 + st_) * 64 + r) * 64 + (dk ^ ((r & 7) << 3));
            split_store2(Oh + e0, Ol + e0, a[0], a[1]);
            split_store2(Oh + e0 + 512, Ol + e0 + 512, a[2], a[3]);  // row+8
        }
    }
}

// final output GEMM: fp32 row-major out
__global__ __launch_bounds__(256) void gemm_out(
    const __nv_bfloat16* __restrict__ Ah_, const __nv_bfloat16* __restrict__ Al_,
    const __nv_bfloat16* __restrict__ Bh_, const __nv_bfloat16* __restrict__ Bl_,
    float* __restrict__ Of) {
    extern __shared__ char smc[];
    const uint32_t sb = smem_u32(smc);
    const int bx = blockIdx.x, by = blockIdx.y;
    const int tid = threadIdx.x;
    const int lane = tid & 31, wid = tid >> 5;
    const int wm = (wid >> 2) * 64, wn = (wid & 3) * 32;
    const int gr = lane >> 2, gc = (lane & 3) * 2;

    float acc[4][4][4];
#pragma unroll
    for (int i = 0; i < 4; i++)
#pragma unroll
        for (int j = 0; j < 4; j++)
#pragma unroll
            for (int c = 0; c < 4; c++) acc[i][j][c] = 0.f;

    gemm_mainloop(sb, Ah_, Al_, Bh_, Bl_, bx, by, acc);

#pragma unroll
    for (int mf = 0; mf < 4; mf++) {
        const int rowg = by * 128 + wm + mf * 16 + gr;
#pragma unroll
        for (int nf = 0; nf < 4; nf++) {
            const int col = bx * 128 + wn + nf * 8 + gc;
            float* a = acc[mf][nf];
            *(float2*)&Of[(size_t)rowg * ND + col] = make_float2(a[0], a[1]);
            *(float2*)&Of[(size_t)(rowg + 8) * ND + col] = make_float2(a[2], a[3]);
        }
    }
}

// ---------------- flash attention: TMA-bulk KV, bf16x2 3-pass, ldmatrix (+trans for V) ----
#define AT_KV 32768
#define AT_STG 32768
#define AT_MBAR (AT_KV + 2 * AT_STG)  // 98304
#define ATT_SMEM (AT_MBAR + 16)

__global__ __launch_bounds__(256) void attn_kernel(
    const __nv_bfloat16* __restrict__ Qh_, const __nv_bfloat16* __restrict__ Ql_,
    const __nv_bfloat16* __restrict__ Kh_, const __nv_bfloat16* __restrict__ Kl_,
    const __nv_bfloat16* __restrict__ Vh_, const __nv_bfloat16* __restrict__ Vl_,
    __nv_bfloat16* __restrict__ Xh, __nv_bfloat16* __restrict__ Xl) {
    extern __shared__ char smc[];
    const uint32_t sb = smem_u32(smc);
    __nv_bfloat16* smb = (__nv_bfloat16*)smc;

    const int tid = threadIdx.x;
    const int lane = tid & 31, wid = tid >> 5;
    const int gr = lane >> 2, gc = (lane & 3) * 2;
    const int qb = (gridDim.x - 1) - blockIdx.x;  // longest first
    const int h = blockIdx.y, b = blockIdx.z;

    const int qkbase = (b * NH + h) * 32;

    const uint32_t mb0 = sb + AT_MBAR;
    if (tid == 0) { mbar_init(mb0, 1); mbar_init(mb0 + 8, 1); }
    __syncthreads();

    auto issueKV = [&](int st, int kt, bool withQ) {
        if (tid == 0) {
            const uint32_t mb = mb0 + st * 8;
            mbar_expect(mb, withQ ? 65536u : 32768u);
            if (withQ) {
#pragma unroll
                for (int t = 0; t < 2; t++) {
                    bulk_g2s(sb + t * 8192,         Qh_ + (size_t)(qkbase + 2 * qb + t) * 4096, 8192, mb);
                    bulk_g2s(sb + 16384 + t * 8192, Ql_ + (size_t)(qkbase + 2 * qb + t) * 4096, 8192, mb);
                }
            }
            const uint32_t d = sb + AT_KV + st * AT_STG;
            bulk_g2s(d,         Kh_ + (size_t)(qkbase + kt) * 4096, 8192, mb);
            bulk_g2s(d + 8192,  Kl_ + (size_t)(qkbase + kt) * 4096, 8192, mb);
            bulk_g2s(d + 16384, Vh_ + (size_t)(qkbase + kt) * 4096, 8192, mb);
            bulk_g2s(d + 24576, Vl_ + (size_t)(qkbase + kt) * 4096, 8192, mb);
        }
    };
    const int nkt = 2 * qb + 2;
    issueKV(0, 0, true);
    issueKV(1, 1, false);

    const int arow_l = lane & 15;
    const uint32_t acol = (lane >> 4) << 4;
    const int brow_l = ((lane >> 4) << 3) + (lane & 7);
    const uint32_t bcol = ((lane >> 3) & 1) << 4;
    // trans-ldmatrix (V) lane mapping
    const int trow_l = (((lane >> 3) & 1) << 3) + (lane & 7);
    const uint32_t tcol = (uint32_t)((lane >> 4) << 4);

    uint32_t qfh[4][4], qfl[4][4];
    float O[8][4];
#pragma unroll
    for (int i = 0; i < 8; i++)
#pragma unroll
        for (int j = 0; j < 4; j++) O[i][j] = 0.f;
    float mrA = -INFINITY, mrB = -INFINITY, lrA = 0.f, lrB = 0.f;

    const int growA = qb * 128 + wid * 16 + gr;
    const int growB = growA + 8;
    const int prow = wid * 16 + gr;

    uint32_t ph[2] = {0, 0};
    for (int kt = 0; kt < nkt; kt++) {
        const int st = kt & 1;
        mbar_wait(mb0 + st * 8, ph[st]);
        ph[st] ^= 1;

        if (kt == 0) {
            const int row = wid * 16 + arow_l;
            const uint32_t rq = ((row >> 6) << 13) + ((row & 63) << 7);
#pragma unroll
            for (int df = 0; df < 4; df++) {
                const uint32_t ad = sb + rq + (((uint32_t)(df * 32) + acol) ^ ((row & 7) << 4));
                ldsm_x4(qfh[df], ad);
                ldsm_x4(qfl[df], ad + 16384);
            }
            __syncthreads();
        }

        const uint32_t kvb = sb + AT_KV + st * AT_STG;
        const bool act = !(kt == 2 * qb + 1 && wid < 4);
        if (act) {
            // ---- S = Q K^T ----
            float S[8][4];
#pragma unroll
            for (int i = 0; i < 8; i++)
#pragma unroll
                for (int j = 0; j < 4; j++) S[i][j] = 0.f;
#pragma unroll
            for (int df = 0; df < 4; df++) {
                uint32_t kh[4][4], kl[4][4];
#pragma unroll
                for (int pr = 0; pr < 4; pr++) {
                    const int row = pr * 16 + brow_l;
                    const uint32_t ad = kvb + (row << 7) +
                                        (((uint32_t)(df * 32) + bcol) ^ ((row & 7) << 4));
                    ldsm_x4(kh[pr], ad);
                    ldsm_x4(kl[pr], ad + 8192);
                }
#pragma unroll
                for (int pr = 0; pr < 4; pr++) {
                    mma_bf16(S[2 * pr],     qfh[df], kh[pr][0], kh[pr][1]);
                    mma_bf16(S[2 * pr + 1], qfh[df], kh[pr][2], kh[pr][3]);
                    mma_bf16(S[2 * pr],     qfh[df], kl[pr][0], kl[pr][1]);
                    mma_bf16(S[2 * pr + 1], qfh[df], kl[pr][2], kl[pr][3]);
                    mma_bf16(S[2 * pr],     qfl[df], kh[pr][0], kh[pr][1]);
                    mma_bf16(S[2 * pr + 1], qfl[df], kh[pr][2], kh[pr][3]);
                }
            }

            // ---- scale + causal mask ----
            const float sc = 0.125f;
#pragma unroll
            for (int nf = 0; nf < 8; nf++)
#pragma unroll
                for (int j = 0; j < 4; j++) S[nf][j] *= sc;
            if (kt >= 2 * qb) {
#pragma unroll
                for (int nf = 0; nf < 8; nf++) {
                    const int col = kt * 64 + nf * 8 + gc;
                    if (col > growA) S[nf][0] = -1e30f;
                    if (col + 1 > growA) S[nf][1] = -1e30f;
                    if (col > growB) S[nf][2] = -1e30f;
                    if (col + 1 > growB) S[nf][3] = -1e30f;
                }
            }

            // ---- online softmax ----
            float mA = -INFINITY, mB = -INFINITY;
#pragma unroll
            for (int nf = 0; nf < 8; nf++) {
                mA = fmaxf(mA, fmaxf(S[nf][0], S[nf][1]));
                mB = fmaxf(mB, fmaxf(S[nf][2], S[nf][3]));
            }
            mA = fmaxf(mA, __shfl_xor_sync(0xffffffffu, mA, 1));
            mA = fmaxf(mA, __shfl_xor_sync(0xffffffffu, mA, 2));
            mB = fmaxf(mB, __shfl_xor_sync(0xffffffffu, mB, 1));
            mB = fmaxf(mB, __shfl_xor_sync(0xffffffffu, mB, 2));
            const float mnA = fmaxf(mrA, mA), mnB = fmaxf(mrB, mB);
            const float aA = __expf(mrA - mnA), aB = __expf(mrB - mnB);
            float rsA = 0.f, rsB = 0.f;
            const uint32_t sA0 = (uint32_t)prow * 64;
            const uint32_t sB0 = (uint32_t)(prow + 8) * 64;
            const uint32_t swA = (uint32_t)((prow & 7) << 3);
#pragma unroll
            for (int nf = 0; nf < 8; nf++) {
                float p0 = __expf(S[nf][0] - mnA);
                float p1 = __expf(S[nf][1] - mnA);
                float p2 = __expf(S[nf][2] - mnB);
                float p3 = __expf(S[nf][3] - mnB);
                rsA += p0 + p1; rsB += p2 + p3;
                const uint32_t pc = (uint32_t)(nf * 8 + gc);
                const uint32_t eA = sA0 + (pc ^ swA);
                const uint32_t eB = sB0 + (pc ^ swA);
                split_store2(smb + eA, smb + 8192 + eA, p0, p1);
                split_store2(smb + eB, smb + 8192 + eB, p2, p3);
            }
            rsA += __shfl_xor_sync(0xffffffffu, rsA, 1);
            rsA += __shfl_xor_sync(0xffffffffu, rsA, 2);
            rsB += __shfl_xor_sync(0xffffffffu, rsB, 1);
            rsB += __shfl_xor_sync(0xffffffffu, rsB, 2);
            lrA = lrA * aA + rsA; mrA = mnA;
            lrB = lrB * aB + rsB; mrB = mnB;
#pragma unroll
            for (int df = 0; df < 8; df++) {
                O[df][0] *= aA; O[df][1] *= aA;
                O[df][2] *= aB; O[df][3] *= aB;
            }
            __syncwarp();

            // ---- O += P V ----  (V token-major, trans ldmatrix)
            const int prowf = wid * 16 + arow_l;
            const uint32_t pbase = sb + (uint32_t)(prowf << 7);
#pragma unroll
            for (int ks = 0; ks < 4; ks++) {
                uint32_t ph_[4], pl_[4];
                const uint32_t pad = pbase + (((uint32_t)(ks * 32) + acol) ^ ((prowf & 7) << 4));
                ldsm_x4(ph_, pad);
                ldsm_x4(pl_, pad + 16384);
                uint32_t vh[4][4], vl[4][4];
#pragma unroll
                for (int pr = 0; pr < 4; pr++) {
                    const int row = ks * 16 + trow_l;  // token row
                    const uint32_t vad = kvb + 16384 + (row << 7) +
                                         (((uint32_t)(pr * 32) + tcol) ^ ((row & 7) << 4));
                    ldsm_x4_t(vh[pr], vad);
                    ldsm_x4_t(vl[pr], vad + 8192);
                }
#pragma unroll
                for (int pr = 0; pr < 4; pr++) {
                    mma_bf16(O[2 * pr],     ph_, vh[pr][0], vh[pr][1]);
                    mma_bf16(O[2 * pr + 1], ph_, vh[pr][2], vh[pr][3]);
                    mma_bf16(O[2 * pr],     ph_, vl[pr][0], vl[pr][1]);
                    mma_bf16(O[2 * pr + 1], ph_, vl[pr][2], vl[pr][3]);
                    mma_bf16(O[2 * pr],     pl_, vh[pr][0], vh[pr][1]);
                    mma_bf16(O[2 * pr + 1], pl_, vh[pr][2], vh[pr][3]);
                }
            }
        }
        __syncthreads();
        if (kt + 2 < nkt) issueKV(st, kt + 2, false);
    }

    // ---- epilogue: X in GEMM-A tiled layout ----
    const float iA = 1.0f / lrA, iB = 1.0f / lrB;
    const int gA = b * NS + growA;
    const int r = gA & 63;
    const size_t e0 = ((size_t)((gA >> 6) * NKB + h) * 64 + r) * 64;
    const uint32_t sw = (uint32_t)((r & 7) << 3);
#pragma unroll
    for (int df = 0; df < 8; df++) {
        const uint32_t c = (uint32_t)(df * 8 + gc);
        const size_t eA = e0 + (c ^ sw);
        const size_t eB = eA + 512;
        split_store2(Xh + eA, Xl + eA, O[df][0] * iA, O[df][1] * iA);
        split_store2(Xh + eB, Xl + eB, O[df][2] * iB, O[df][3] * iB);
    }
}

// ---------------- launch ----------------
extern "C" void kernel_launch(void* const* d_in, const int* in_sizes, int n_in,
                              void* d_out, int out_size) {
    const float* q = (const float*)d_in[0];
    const float* k = (const float*)d_in[1];
    const float* v = (const float*)d_in[2];
    const float* wq = (const float*)d_in[4];
    const float* wk = (const float*)d_in[5];
    const float* wv = (const float*)d_in[6];
    const float* wo = (const float*)d_in[7];
    float* out = (float*)d_out;

    __nv_bfloat16 *qh, *ql, *kh, *kl, *vh, *vl;
    __nv_bfloat16 *wqh, *wql, *wkh, *wkl, *wvh, *wvl, *woh, *wol;
    __nv_bfloat16 *Qh, *Ql, *Kh, *Kl, *Vh, *Vl, *Xh, *Xl;
    cudaGetSymbolAddress((void**)&qh, g_qh);   cudaGetSymbolAddress((void**)&ql, g_ql);
    cudaGetSymbolAddress((void**)&kh, g_kh);   cudaGetSymbolAddress((void**)&kl, g_kl);
    cudaGetSymbolAddress((void**)&vh, g_vh);   cudaGetSymbolAddress((void**)&vl, g_vl);
    cudaGetSymbolAddress((void**)&wqh, g_wqh); cudaGetSymbolAddress((void**)&wql, g_wql);
    cudaGetSymbolAddress((void**)&wkh, g_wkh); cudaGetSymbolAddress((void**)&wkl, g_wkl);
    cudaGetSymbolAddress((void**)&wvh, g_wvh); cudaGetSymbolAddress((void**)&wvl, g_wvl);
    cudaGetSymbolAddress((void**)&woh, g_woh); cudaGetSymbolAddress((void**)&wol, g_wol);
    cudaGetSymbolAddress((void**)&Qh, g_Qh);   cudaGetSymbolAddress((void**)&Ql, g_Ql);
    cudaGetSymbolAddress((void**)&Kh, g_Kh);   cudaGetSymbolAddress((void**)&Kl, g_Kl);
    cudaGetSymbolAddress((void**)&Vh, g_Vh);   cudaGetSymbolAddress((void**)&Vl, g_Vl);
    cudaGetSymbolAddress((void**)&Xh, g_Xh);   cudaGetSymbolAddress((void**)&Xl, g_Xl);

    cudaFuncSetAttribute(gemm_qkv, cudaFuncAttributeMaxDynamicSharedMemorySize, GEMM_SMEM);
    cudaFuncSetAttribute(gemm_out, cudaFuncAttributeMaxDynamicSharedMemorySize, GEMM_SMEM);
    cudaFuncSetAttribute(attn_kernel, cudaFuncAttributeMaxDynamicSharedMemorySize, ATT_SMEM);

    split3_kernel<<<dim3(NM * ND / 4 / 256, 3), 256>>>(q, k, v, qh, ql, kh, kl, vh, vl);
    split4_kernel<<<dim3(ND * ND / 4 / 256, 4), 256>>>(wq, wk, wv, wo,
                                                       wqh, wql, wkh, wkl, wvh, wvl, woh, wol);

    QKVParams prm;
    prm.ah[0] = qh; prm.al[0] = ql; prm.bh[0] = wqh; prm.bl[0] = wql; prm.oh[0] = Qh; prm.ol[0] = Ql;
    prm.ah[1] = kh; prm.al[1] = kl; prm.bh[1] = wkh; prm.bl[1] = wkl; prm.oh[1] = Kh; prm.ol[1] = Kl;
    prm.ah[2] = vh; prm.al[2] = vl; prm.bh[2] = wvh; prm.bl[2] = wvl; prm.oh[2] = Vh; prm.ol[2] = Vl;

    gemm_qkv<<<dim3(ND / 128, NM / 128, 3), 256, GEMM_SMEM>>>(prm);

    attn_kernel<<<dim3(NS / 128, NH, NB), 256, ATT_SMEM>>>(Qh, Ql, Kh, Kl, Vh, Vl, Xh, Xl);

    gemm_out<<<dim3(ND / 128, NM / 128), 256, GEMM_SMEM>>>(Xh, Xl, woh, wol, out);
}

// round 15
// speedup vs baseline: 3.5228x; 1.0297x over previous
#include <cuda_runtime.h>
#include <cuda_bf16.h>
#include <math.h>
#include <stdint.h>

#define NB 4
#define NS 2048
#define ND 1024
#define NH 16
#define NDK 64
#define NM (NB * NS)  // 8192
#define NKB (ND / 64) // 16 k-blocks

// ---------------- device scratch: all planes in 64x64 swizzled tiles ----------------
// tile(m,k): elem = ((m>>6)*NKB + (k>>6))*4096 + (m&63)*64 + ((k&63) ^ ((m&7)<<3))
__device__ __align__(128) __nv_bfloat16 g_qh[NM * ND], g_ql[NM * ND];
__device__ __align__(128) __nv_bfloat16 g_kh[NM * ND], g_kl[NM * ND];
__device__ __align__(128) __nv_bfloat16 g_vh[NM * ND], g_vl[NM * ND];
__device__ __align__(128) __nv_bfloat16 g_wqh[ND * ND], g_wql[ND * ND];
__device__ __align__(128) __nv_bfloat16 g_wkh[ND * ND], g_wkl[ND * ND];
__device__ __align__(128) __nv_bfloat16 g_wvh[ND * ND], g_wvl[ND * ND];
__device__ __align__(128) __nv_bfloat16 g_woh[ND * ND], g_wol[ND * ND];
// Q,K,V: per (b,h): [32 s-tiles][64 tok][64 dk]  (tile index (b*16+h)*32+st)
__device__ __align__(128) __nv_bfloat16 g_Qh[NM * ND], g_Ql[NM * ND];
__device__ __align__(128) __nv_bfloat16 g_Kh[NM * ND], g_Kl[NM * ND];
__device__ __align__(128) __nv_bfloat16 g_Vh[NM * ND], g_Vl[NM * ND];
// X: GEMM-A tiling over (token 8192, feature 1024)
__device__ __align__(128) __nv_bfloat16 g_Xh[NM * ND], g_Xl[NM * ND];

// ---------------- helpers ----------------
__device__ __forceinline__ uint32_t smem_u32(const void* p) {
    return (uint32_t)__cvta_generic_to_shared(p);
}
__device__ __forceinline__ void mma_bf16(float* d, const uint32_t* a, uint32_t b0, uint32_t b1) {
    asm volatile(
        "mma.sync.aligned.m16n8k16.row.col.f32.bf16.bf16.f32 "
        "{%0,%1,%2,%3}, {%4,%5,%6,%7}, {%8,%9}, {%0,%1,%2,%3};\n"
        : "+f"(d[0]), "+f"(d[1]), "+f"(d[2]), "+f"(d[3])
        : "r"(a[0]), "r"(a[1]), "r"(a[2]), "r"(a[3]), "r"(b0), "r"(b1));
}
__device__ __forceinline__ void ldsm_x4(uint32_t* r, uint32_t addr) {
    asm volatile("ldmatrix.sync.aligned.m8n8.x4.shared.b16 {%0,%1,%2,%3}, [%4];"
                 : "=r"(r[0]), "=r"(r[1]), "=r"(r[2]), "=r"(r[3])
                 : "r"(addr));
}
__device__ __forceinline__ void ldsm_x4_t(uint32_t* r, uint32_t addr) {
    asm volatile("ldmatrix.sync.aligned.m8n8.x4.trans.shared.b16 {%0,%1,%2,%3}, [%4];"
                 : "=r"(r[0]), "=r"(r[1]), "=r"(r[2]), "=r"(r[3])
                 : "r"(addr));
}
__device__ __forceinline__ void bulk_g2s(uint32_t dst, const void* src, uint32_t bytes,
                                         uint32_t mbar) {
    asm volatile(
        "cp.async.bulk.shared::cluster.global.mbarrier::complete_tx::bytes [%0], [%1], %2, [%3];"
        ::"r"(dst), "l"(src), "r"(bytes), "r"(mbar) : "memory");
}
__device__ __forceinline__ void mbar_init(uint32_t addr, uint32_t cnt) {
    asm volatile("mbarrier.init.shared.b64 [%0], %1;" ::"r"(addr), "r"(cnt) : "memory");
}
__device__ __forceinline__ void mbar_expect(uint32_t addr, uint32_t bytes) {
    asm volatile("mbarrier.arrive.expect_tx.shared.b64 _, [%0], %1;"
                 ::"r"(addr), "r"(bytes) : "memory");
}
__device__ __forceinline__ void mbar_wait(uint32_t addr, uint32_t parity) {
    asm volatile(
        "{\n\t.reg .pred P;\n\tWL_%=:\n\t"
        "mbarrier.try_wait.parity.acquire.cta.shared::cta.b64 P, [%0], %1, 0x989680;\n\t"
        "@P bra.uni WD_%=;\n\tbra.uni WL_%=;\n\tWD_%=:\n\t}"
        ::"r"(addr), "r"(parity) : "memory");
}
__device__ __forceinline__ void split_store2(__nv_bfloat16* ph, __nv_bfloat16* pl,
                                             float x, float y) {
    __nv_bfloat16 hx = __float2bfloat16(x), hy = __float2bfloat16(y);
    __nv_bfloat162 h2; h2.x = hx; h2.y = hy;
    *(__nv_bfloat162*)ph = h2;
    __nv_bfloat162 l2;
    l2.x = __float2bfloat16(x - __bfloat162float(hx));
    l2.y = __float2bfloat16(y - __bfloat162float(hy));
    *(__nv_bfloat162*)pl = l2;
}

// ---------------- split: fp32 row-major -> tiled swizzled bf16 hi/lo planes ----------------
__device__ __forceinline__ void split_one(const float* s, __nv_bfloat16* h, __nv_bfloat16* l,
                                          int g) {
    const int m = g >> 8;
    const int k4 = (g & 255) << 2;
    float4 v = *(const float4*)(s + (size_t)m * ND + k4);
    size_t dst = ((size_t)((m >> 6) * NKB + (k4 >> 6))) * 4096 + (m & 63) * 64 +
                 ((k4 & 63) ^ ((m & 7) << 3));
    split_store2(h + dst, l + dst, v.x, v.y);
    split_store2(h + dst + 2, l + dst + 2, v.z, v.w);
}
__global__ void split3_kernel(const float* s0, const float* s1, const float* s2,
                              __nv_bfloat16* h0, __nv_bfloat16* l0,
                              __nv_bfloat16* h1, __nv_bfloat16* l1,
                              __nv_bfloat16* h2, __nv_bfloat16* l2) {
    int g = blockIdx.x * blockDim.x + threadIdx.x;
    const float* s = (blockIdx.y == 0) ? s0 : (blockIdx.y == 1) ? s1 : s2;
    __nv_bfloat16* h = (blockIdx.y == 0) ? h0 : (blockIdx.y == 1) ? h1 : h2;
    __nv_bfloat16* l = (blockIdx.y == 0) ? l0 : (blockIdx.y == 1) ? l1 : l2;
    split_one(s, h, l, g);
}
__global__ void split4_kernel(const float* s0, const float* s1, const float* s2, const float* s3,
                              __nv_bfloat16* h0, __nv_bfloat16* l0,
                              __nv_bfloat16* h1, __nv_bfloat16* l1,
                              __nv_bfloat16* h2, __nv_bfloat16* l2,
                              __nv_bfloat16* h3, __nv_bfloat16* l3) {
    int g = blockIdx.x * blockDim.x + threadIdx.x;
    const float* s = (blockIdx.y == 0) ? s0 : (blockIdx.y == 1) ? s1 : (blockIdx.y == 2) ? s2 : s3;
    __nv_bfloat16* h = (blockIdx.y == 0) ? h0 : (blockIdx.y == 1) ? h1 : (blockIdx.y == 2) ? h2 : h3;
    __nv_bfloat16* l = (blockIdx.y == 0) ? l0 : (blockIdx.y == 1) ? l1 : (blockIdx.y == 2) ? l2 : l3;
    split_one(s, h, l, g);
}

// ---------------- GEMM core: D[m(128), n(128)] = sum_k A[m,k] B[n,k] ----------------
#define GS_STAGE 65536
#define GS_MBAR (2 * GS_STAGE)
#define GEMM_SMEM (GS_MBAR + 16)

struct QKVParams {
    const __nv_bfloat16 *ah[3], *al[3], *bh[3], *bl[3];
    __nv_bfloat16 *oh[3], *ol[3];
};

__device__ __forceinline__ void gemm_mainloop(
    uint32_t sb, const __nv_bfloat16* Ah_, const __nv_bfloat16* Al_,
    const __nv_bfloat16* Bh_, const __nv_bfloat16* Bl_, int bx, int by,
    float acc[4][4][4]) {
    const int tid = threadIdx.x;
    const int lane = tid & 31, wid = tid >> 5;
    const int wm = (wid >> 2) * 64, wn = (wid & 3) * 32;

    const uint32_t mb0 = sb + GS_MBAR;
    if (tid == 0) { mbar_init(mb0, 1); mbar_init(mb0 + 8, 1); }
    __syncthreads();

    auto issue = [&](int st, int s) {
        if (tid == 0) {
            const uint32_t mb = mb0 + st * 8;
            mbar_expect(mb, 65536);
            const uint32_t d = sb + st * GS_STAGE;
#pragma unroll
            for (int t = 0; t < 2; t++) {
                bulk_g2s(d + t * 8192,         Ah_ + (size_t)((2 * by + t) * NKB + s) * 4096, 8192, mb);
                bulk_g2s(d + 16384 + t * 8192, Al_ + (size_t)((2 * by + t) * NKB + s) * 4096, 8192, mb);
                bulk_g2s(d + 32768 + t * 8192, Bh_ + (size_t)((2 * bx + t) * NKB + s) * 4096, 8192, mb);
                bulk_g2s(d + 49152 + t * 8192, Bl_ + (size_t)((2 * bx + t) * NKB + s) * 4096, 8192, mb);
            }
        }
    };
    issue(0, 0);
    issue(1, 1);

    const int arow_l = lane & 15;
    const uint32_t acol = (lane >> 4) << 4;
    const int brow_l = ((lane >> 4) << 3) + (lane & 7);
    const uint32_t bcol = ((lane >> 3) & 1) << 4;

    uint32_t ph[2] = {0, 0};
    for (int s = 0; s < NKB; s++) {
        const int st = s & 1;
        mbar_wait(mb0 + st * 8, ph[st]);
        ph[st] ^= 1;
        const uint32_t base = sb + st * GS_STAGE;

#pragma unroll
        for (int kk = 0; kk < 4; kk++) {
            const uint32_t kb = kk * 32;
            uint32_t bh[4][2], bl[4][2], t[4];
            uint32_t ah[4][4], al[4][4];
#pragma unroll
            for (int p2 = 0; p2 < 2; p2++) {
                const int row = wn + p2 * 16 + brow_l;
                const uint32_t ad = base + 32768 + ((row >> 6) << 13) + ((row & 63) << 7) +
                                    ((kb + bcol) ^ ((row & 7) << 4));
                ldsm_x4(t, ad);
                bh[2 * p2][0] = t[0]; bh[2 * p2][1] = t[1];
                bh[2 * p2 + 1][0] = t[2]; bh[2 * p2 + 1][1] = t[3];
                ldsm_x4(t, ad + 16384);
                bl[2 * p2][0] = t[0]; bl[2 * p2][1] = t[1];
                bl[2 * p2 + 1][0] = t[2]; bl[2 * p2 + 1][1] = t[3];
            }
#pragma unroll
            for (int mf = 0; mf < 4; mf++) {
                const int row = wm + mf * 16 + arow_l;
                const uint32_t ad = base + ((row >> 6) << 13) + ((row & 63) << 7) +
                                    ((kb + acol) ^ ((row & 7) << 4));
                ldsm_x4(ah[mf], ad);
                ldsm_x4(al[mf], ad + 16384);
            }
#pragma unroll
            for (int mf = 0; mf < 4; mf++) {
#pragma unroll
                for (int nf = 0; nf < 4; nf++) mma_bf16(acc[mf][nf], ah[mf], bh[nf][0], bh[nf][1]);
#pragma unroll
                for (int nf = 0; nf < 4; nf++) mma_bf16(acc[mf][nf], ah[mf], bl[nf][0], bl[nf][1]);
#pragma unroll
                for (int nf = 0; nf < 4; nf++) mma_bf16(acc[mf][nf], al[mf], bh[nf][0], bh[nf][1]);
            }
        }
        __syncthreads();
        if (s + 2 < NKB) issue(st, s + 2);
    }
}

// merged Q/K/V projection: grid (8, 64, 3)
__global__ __launch_bounds__(256) void gemm_qkv(QKVParams prm) {
    extern __shared__ char smc[];
    const uint32_t sb = smem_u32(smc);
    const int z = blockIdx.z;
    const int bx = blockIdx.x, by = blockIdx.y;
    const int tid = threadIdx.x;
    const int lane = tid & 31, wid = tid >> 5;
    const int wm = (wid >> 2) * 64, wn = (wid & 3) * 32;
    const int gr = lane >> 2, gc = (lane & 3) * 2;

    float acc[4][4][4];
#pragma unroll
    for (int i = 0; i < 4; i++)
#pragma unroll
        for (int j = 0; j < 4; j++)
#pragma unroll
            for (int c = 0; c < 4; c++) acc[i][j][c] = 0.f;

    gemm_mainloop(sb, prm.ah[z], prm.al[z], prm.bh[z], prm.bl[z], bx, by, acc);

    __nv_bfloat16* Oh = prm.oh[z];
    __nv_bfloat16* Ol = prm.ol[z];
#pragma unroll
    for (int mf = 0; mf < 4; mf++) {
        const int rowg = by * 128 + wm + mf * 16 + gr;
#pragma unroll
        for (int nf = 0; nf < 4; nf++) {
            const int col = bx * 128 + wn + nf * 8 + gc;
            float* a = acc[mf][nf];
            const int b = rowg >> 11, s_ = rowg & (NS - 1);
            const int st_ = s_ >> 6, r = s_ & 63;
            const int h = col >> 6, dk = col & 63;
            size_t e0 = ((size_t)((b * NH + h) * 32 + st_) * 64 + r) * 64 + (dk ^ ((r & 7) << 3));
            split_store2(Oh + e0, Ol + e0, a[0], a[1]);
            split_store2(Oh + e0 + 512, Ol + e0 + 512, a[2], a[3]);  // row+8
        }
    }
}

// final output GEMM: fp32 row-major out
__global__ __launch_bounds__(256) void gemm_out(
    const __nv_bfloat16* __restrict__ Ah_, const __nv_bfloat16* __restrict__ Al_,
    const __nv_bfloat16* __restrict__ Bh_, const __nv_bfloat16* __restrict__ Bl_,
    float* __restrict__ Of) {
    extern __shared__ char smc[];
    const uint32_t sb = smem_u32(smc);
    const int bx = blockIdx.x, by = blockIdx.y;
    const int tid = threadIdx.x;
    const int lane = tid & 31, wid = tid >> 5;
    const int wm = (wid >> 2) * 64, wn = (wid & 3) * 32;
    const int gr = lane >> 2, gc = (lane & 3) * 2;

    float acc[4][4][4];
#pragma unroll
    for (int i = 0; i < 4; i++)
#pragma unroll
        for (int j = 0; j < 4; j++)
#pragma unroll
            for (int c = 0; c < 4; c++) acc[i][j][c] = 0.f;

    gemm_mainloop(sb, Ah_, Al_, Bh_, Bl_, bx, by, acc);

#pragma unroll
    for (int mf = 0; mf < 4; mf++) {
        const int rowg = by * 128 + wm + mf * 16 + gr;
#pragma unroll
        for (int nf = 0; nf < 4; nf++) {
            const int col = bx * 128 + wn + nf * 8 + gc;
            float* a = acc[mf][nf];
            *(float2*)&Of[(size_t)rowg * ND + col] = make_float2(a[0], a[1]);
            *(float2*)&Of[(size_t)(rowg + 8) * ND + col] = make_float2(a[2], a[3]);
        }
    }
}

// ---------------- flash attention: TMA-bulk KV, bf16x2 3-pass, ldmatrix (+trans for V) ----
#define AT_KV 32768
#define AT_STG 32768
#define AT_MBAR (AT_KV + 2 * AT_STG)  // 98304
#define ATT_SMEM (AT_MBAR + 16)

__global__ __launch_bounds__(256, 2) void attn_kernel(
    const __nv_bfloat16* __restrict__ Qh_, const __nv_bfloat16* __restrict__ Ql_,
    const __nv_bfloat16* __restrict__ Kh_, const __nv_bfloat16* __restrict__ Kl_,
    const __nv_bfloat16* __restrict__ Vh_, const __nv_bfloat16* __restrict__ Vl_,
    __nv_bfloat16* __restrict__ Xh, __nv_bfloat16* __restrict__ Xl) {
    extern __shared__ char smc[];
    const uint32_t sb = smem_u32(smc);
    __nv_bfloat16* smb = (__nv_bfloat16*)smc;

    const int tid = threadIdx.x;
    const int lane = tid & 31, wid = tid >> 5;
    const int gr = lane >> 2, gc = (lane & 3) * 2;
    const int qb = (gridDim.x - 1) - blockIdx.x;  // longest first
    const int h = blockIdx.y, b = blockIdx.z;

    const int qkbase = (b * NH + h) * 32;

    const uint32_t mb0 = sb + AT_MBAR;
    if (tid == 0) { mbar_init(mb0, 1); mbar_init(mb0 + 8, 1); }
    __syncthreads();

    auto issueKV = [&](int st, int kt, bool withQ) {
        if (tid == 0) {
            const uint32_t mb = mb0 + st * 8;
            mbar_expect(mb, withQ ? 65536u : 32768u);
            if (withQ) {
#pragma unroll
                for (int t = 0; t < 2; t++) {
                    bulk_g2s(sb + t * 8192,         Qh_ + (size_t)(qkbase + 2 * qb + t) * 4096, 8192, mb);
                    bulk_g2s(sb + 16384 + t * 8192, Ql_ + (size_t)(qkbase + 2 * qb + t) * 4096, 8192, mb);
                }
            }
            const uint32_t d = sb + AT_KV + st * AT_STG;
            bulk_g2s(d,         Kh_ + (size_t)(qkbase + kt) * 4096, 8192, mb);
            bulk_g2s(d + 8192,  Kl_ + (size_t)(qkbase + kt) * 4096, 8192, mb);
            bulk_g2s(d + 16384, Vh_ + (size_t)(qkbase + kt) * 4096, 8192, mb);
            bulk_g2s(d + 24576, Vl_ + (size_t)(qkbase + kt) * 4096, 8192, mb);
        }
    };
    const int nkt = 2 * qb + 2;
    issueKV(0, 0, true);
    issueKV(1, 1, false);

    const int arow_l = lane & 15;
    const uint32_t acol = (lane >> 4) << 4;
    const int brow_l = ((lane >> 4) << 3) + (lane & 7);
    const uint32_t bcol = ((lane >> 3) & 1) << 4;
    const int trow_l = (((lane >> 3) & 1) << 3) + (lane & 7);
    const uint32_t tcol = (uint32_t)((lane >> 4) << 4);

    uint32_t qfh[4][4], qfl[4][4];
    float O[8][4];
#pragma unroll
    for (int i = 0; i < 8; i++)
#pragma unroll
        for (int j = 0; j < 4; j++) O[i][j] = 0.f;
    float mrA = -INFINITY, mrB = -INFINITY, lrA = 0.f, lrB = 0.f;

    const int growA = qb * 128 + wid * 16 + gr;
    const int growB = growA + 8;
    const int prow = wid * 16 + gr;

    uint32_t ph[2] = {0, 0};
    for (int kt = 0; kt < nkt; kt++) {
        const int st = kt & 1;
        mbar_wait(mb0 + st * 8, ph[st]);
        ph[st] ^= 1;

        if (kt == 0) {
            const int row = wid * 16 + arow_l;
            const uint32_t rq = ((row >> 6) << 13) + ((row & 63) << 7);
#pragma unroll
            for (int df = 0; df < 4; df++) {
                const uint32_t ad = sb + rq + (((uint32_t)(df * 32) + acol) ^ ((row & 7) << 4));
                ldsm_x4(qfh[df], ad);
                ldsm_x4(qfl[df], ad + 16384);
            }
            __syncthreads();
        }

        const uint32_t kvb = sb + AT_KV + st * AT_STG;
        const bool act = !(kt == 2 * qb + 1 && wid < 4);
        if (act) {
            // ---- S = Q K^T ----  (loads batched; pass-major, acc reuse distance 8)
            float S[8][4];
#pragma unroll
            for (int i = 0; i < 8; i++)
#pragma unroll
                for (int j = 0; j < 4; j++) S[i][j] = 0.f;
#pragma unroll
            for (int df = 0; df < 4; df++) {
                uint32_t kh[4][4], kl[4][4];
#pragma unroll
                for (int pr = 0; pr < 4; pr++) {
                    const int row = pr * 16 + brow_l;
                    const uint32_t ad = kvb + (row << 7) +
                                        (((uint32_t)(df * 32) + bcol) ^ ((row & 7) << 4));
                    ldsm_x4(kh[pr], ad);
                    ldsm_x4(kl[pr], ad + 8192);
                }
#pragma unroll
                for (int pr = 0; pr < 4; pr++) {
                    mma_bf16(S[2 * pr],     qfh[df], kh[pr][0], kh[pr][1]);
                    mma_bf16(S[2 * pr + 1], qfh[df], kh[pr][2], kh[pr][3]);
                }
#pragma unroll
                for (int pr = 0; pr < 4; pr++) {
                    mma_bf16(S[2 * pr],     qfh[df], kl[pr][0], kl[pr][1]);
                    mma_bf16(S[2 * pr + 1], qfh[df], kl[pr][2], kl[pr][3]);
                }
#pragma unroll
                for (int pr = 0; pr < 4; pr++) {
                    mma_bf16(S[2 * pr],     qfl[df], kh[pr][0], kh[pr][1]);
                    mma_bf16(S[2 * pr + 1], qfl[df], kh[pr][2], kh[pr][3]);
                }
            }

            // ---- scale + causal mask ----
            const float sc = 0.125f;
#pragma unroll
            for (int nf = 0; nf < 8; nf++)
#pragma unroll
                for (int j = 0; j < 4; j++) S[nf][j] *= sc;
            if (kt >= 2 * qb) {
#pragma unroll
                for (int nf = 0; nf < 8; nf++) {
                    const int col = kt * 64 + nf * 8 + gc;
                    if (col > growA) S[nf][0] = -1e30f;
                    if (col + 1 > growA) S[nf][1] = -1e30f;
                    if (col > growB) S[nf][2] = -1e30f;
                    if (col + 1 > growB) S[nf][3] = -1e30f;
                }
            }

            // ---- online softmax ----
            float mA = -INFINITY, mB = -INFINITY;
#pragma unroll
            for (int nf = 0; nf < 8; nf++) {
                mA = fmaxf(mA, fmaxf(S[nf][0], S[nf][1]));
                mB = fmaxf(mB, fmaxf(S[nf][2], S[nf][3]));
            }
            mA = fmaxf(mA, __shfl_xor_sync(0xffffffffu, mA, 1));
            mA = fmaxf(mA, __shfl_xor_sync(0xffffffffu, mA, 2));
            mB = fmaxf(mB, __shfl_xor_sync(0xffffffffu, mB, 1));
            mB = fmaxf(mB, __shfl_xor_sync(0xffffffffu, mB, 2));
            const float mnA = fmaxf(mrA, mA), mnB = fmaxf(mrB, mB);
            const float aA = __expf(mrA - mnA), aB = __expf(mrB - mnB);
            float rsA = 0.f, rsB = 0.f;
            const uint32_t sA0 = (uint32_t)prow * 64;
            const uint32_t sB0 = (uint32_t)(prow + 8) * 64;
            const uint32_t swA = (uint32_t)((prow & 7) << 3);
#pragma unroll
            for (int nf = 0; nf < 8; nf++) {
                float p0 = __expf(S[nf][0] - mnA);
                float p1 = __expf(S[nf][1] - mnA);
                float p2 = __expf(S[nf][2] - mnB);
                float p3 = __expf(S[nf][3] - mnB);
                rsA += p0 + p1; rsB += p2 + p3;
                const uint32_t pc = (uint32_t)(nf * 8 + gc);
                const uint32_t eA = sA0 + (pc ^ swA);
                const uint32_t eB = sB0 + (pc ^ swA);
                split_store2(smb + eA, smb + 8192 + eA, p0, p1);
                split_store2(smb + eB, smb + 8192 + eB, p2, p3);
            }
            rsA += __shfl_xor_sync(0xffffffffu, rsA, 1);
            rsA += __shfl_xor_sync(0xffffffffu, rsA, 2);
            rsB += __shfl_xor_sync(0xffffffffu, rsB, 1);
            rsB += __shfl_xor_sync(0xffffffffu, rsB, 2);
            lrA = lrA * aA + rsA; mrA = mnA;
            lrB = lrB * aB + rsB; mrB = mnB;
#pragma unroll
            for (int df = 0; df < 8; df++) {
                O[df][0] *= aA; O[df][1] *= aA;
                O[df][2] *= aB; O[df][3] *= aB;
            }
            __syncwarp();

            // ---- O += P V ----  (V token-major, trans ldmatrix; pass-major ordering)
            const int prowf = wid * 16 + arow_l;
            const uint32_t pbase = sb + (uint32_t)(prowf << 7);
#pragma unroll
            for (int ks = 0; ks < 4; ks++) {
                uint32_t ph_[4], pl_[4];
                const uint32_t pad = pbase + (((uint32_t)(ks * 32) + acol) ^ ((prowf & 7) << 4));
                ldsm_x4(ph_, pad);
                ldsm_x4(pl_, pad + 16384);
                uint32_t vh[4][4], vl[4][4];
#pragma unroll
                for (int pr = 0; pr < 4; pr++) {
                    const int row = ks * 16 + trow_l;  // token row
                    const uint32_t vad = kvb + 16384 + (row << 7) +
                                         (((uint32_t)(pr * 32) + tcol) ^ ((row & 7) << 4));
                    ldsm_x4_t(vh[pr], vad);
                    ldsm_x4_t(vl[pr], vad + 8192);
                }
#pragma unroll
                for (int pr = 0; pr < 4; pr++) {
                    mma_bf16(O[2 * pr],     ph_, vh[pr][0], vh[pr][1]);
                    mma_bf16(O[2 * pr + 1], ph_, vh[pr][2], vh[pr][3]);
                }
#pragma unroll
                for (int pr = 0; pr < 4; pr++) {
                    mma_bf16(O[2 * pr],     ph_, vl[pr][0], vl[pr][1]);
                    mma_bf16(O[2 * pr + 1], ph_, vl[pr][2], vl[pr][3]);
                }
#pragma unroll
                for (int pr = 0; pr < 4; pr++) {
                    mma_bf16(O[2 * pr],     pl_, vh[pr][0], vh[pr][1]);
                    mma_bf16(O[2 * pr + 1], pl_, vh[pr][2], vh[pr][3]);
                }
            }
        }
        __syncthreads();
        if (kt + 2 < nkt) issueKV(st, kt + 2, false);
    }

    // ---- epilogue: X in GEMM-A tiled layout ----
    const float iA = 1.0f / lrA, iB = 1.0f / lrB;
    const int gA = b * NS + growA;
    const int r = gA & 63;
    const size_t e0 = ((size_t)((gA >> 6) * NKB + h) * 64 + r) * 64;
    const uint32_t sw = (uint32_t)((r & 7) << 3);
#pragma unroll
    for (int df = 0; df < 8; df++) {
        const uint32_t c = (uint32_t)(df * 8 + gc);
        const size_t eA = e0 + (c ^ sw);
        const size_t eB = eA + 512;
        split_store2(Xh + eA, Xl + eA, O[df][0] * iA, O[df][1] * iA);
        split_store2(Xh + eB, Xl + eB, O[df][2] * iB, O[df][3] * iB);
    }
}

// ---------------- launch ----------------
extern "C" void kernel_launch(void* const* d_in, const int* in_sizes, int n_in,
                              void* d_out, int out_size) {
    const float* q = (const float*)d_in[0];
    const float* k = (const float*)d_in[1];
    const float* v = (const float*)d_in[2];
    const float* wq = (const float*)d_in[4];
    const float* wk = (const float*)d_in[5];
    const float* wv = (const float*)d_in[6];
    const float* wo = (const float*)d_in[7];
    float* out = (float*)d_out;

    __nv_bfloat16 *qh, *ql, *kh, *kl, *vh, *vl;
    __nv_bfloat16 *wqh, *wql, *wkh, *wkl, *wvh, *wvl, *woh, *wol;
    __nv_bfloat16 *Qh, *Ql, *Kh, *Kl, *Vh, *Vl, *Xh, *Xl;
    cudaGetSymbolAddress((void**)&qh, g_qh);   cudaGetSymbolAddress((void**)&ql, g_ql);
    cudaGetSymbolAddress((void**)&kh, g_kh);   cudaGetSymbolAddress((void**)&kl, g_kl);
    cudaGetSymbolAddress((void**)&vh, g_vh);   cudaGetSymbolAddress((void**)&vl, g_vl);
    cudaGetSymbolAddress((void**)&wqh, g_wqh); cudaGetSymbolAddress((void**)&wql, g_wql);
    cudaGetSymbolAddress((void**)&wkh, g_wkh); cudaGetSymbolAddress((void**)&wkl, g_wkl);
    cudaGetSymbolAddress((void**)&wvh, g_wvh); cudaGetSymbolAddress((void**)&wvl, g_wvl);
    cudaGetSymbolAddress((void**)&woh, g_woh); cudaGetSymbolAddress((void**)&wol, g_wol);
    cudaGetSymbolAddress((void**)&Qh, g_Qh);   cudaGetSymbolAddress((void**)&Ql, g_Ql);
    cudaGetSymbolAddress((void**)&Kh, g_Kh);   cudaGetSymbolAddress((void**)&Kl, g_Kl);
    cudaGetSymbolAddress((void**)&Vh, g_Vh);   cudaGetSymbolAddress((void**)&Vl, g_Vl);
    cudaGetSymbolAddress((void**)&Xh, g_Xh);   cudaGetSymbolAddress((void**)&Xl, g_Xl);

    cudaFuncSetAttribute(gemm_qkv, cudaFuncAttributeMaxDynamicSharedMemorySize, GEMM_SMEM);
    cudaFuncSetAttribute(gemm_out, cudaFuncAttributeMaxDynamicSharedMemorySize, GEMM_SMEM);
    cudaFuncSetAttribute(attn_kernel, cudaFuncAttributeMaxDynamicSharedMemorySize, ATT_SMEM);

    split3_kernel<<<dim3(NM * ND / 4 / 256, 3), 256>>>(q, k, v, qh, ql, kh, kl, vh, vl);
    split4_kernel<<<dim3(ND * ND / 4 / 256, 4), 256>>>(wq, wk, wv, wo,
                                                       wqh, wql, wkh, wkl, wvh, wvl, woh, wol);

    QKVParams prm;
    prm.ah[0] = qh; prm.al[0] = ql; prm.bh[0] = wqh; prm.bl[0] = wql; prm.oh[0] = Qh; prm.ol[0] = Ql;
    prm.ah[1] = kh; prm.al[1] = kl; prm.bh[1] = wkh; prm.bl[1] = wkl; prm.oh[1] = Kh; prm.ol[1] = Kl;
    prm.ah[2] = vh; prm.al[2] = vl; prm.bh[2] = wvh; prm.bl[2] = wvl; prm.oh[2] = Vh; prm.ol[2] = Vl;

    gemm_qkv<<<dim3(ND / 128, NM / 128, 3), 256, GEMM_SMEM>>>(prm);

    attn_kernel<<<dim3(NS / 128, NH, NB), 256, ATT_SMEM>>>(Qh, Ql, Kh, Kl, Vh, Vl, Xh, Xl);

    gemm_out<<<dim3(ND / 128, NM / 128), 256, GEMM_SMEM>>>(Xh, Xl, woh, wol, out);
}

// round 16
// speedup vs baseline: 3.5659x; 1.0122x over previous
#include <cuda_runtime.h>
#include <cuda_bf16.h>
#include <math.h>
#include <stdint.h>

#define NB 4
#define NS 2048
#define ND 1024
#define NH 16
#define NDK 64
#define NM (NB * NS)  // 8192
#define NKB (ND / 64) // 16 k-blocks

// ---------------- device scratch: all planes in 64x64 swizzled tiles ----------------
// tile(m,k): elem = ((m>>6)*NKB + (k>>6))*4096 + (m&63)*64 + ((k&63) ^ ((m&7)<<3))
__device__ __align__(128) __nv_bfloat16 g_qh[NM * ND], g_ql[NM * ND];
__device__ __align__(128) __nv_bfloat16 g_kh[NM * ND], g_kl[NM * ND];
__device__ __align__(128) __nv_bfloat16 g_vh[NM * ND], g_vl[NM * ND];
__device__ __align__(128) __nv_bfloat16 g_wqh[ND * ND], g_wql[ND * ND];
__device__ __align__(128) __nv_bfloat16 g_wkh[ND * ND], g_wkl[ND * ND];
__device__ __align__(128) __nv_bfloat16 g_wvh[ND * ND], g_wvl[ND * ND];
__device__ __align__(128) __nv_bfloat16 g_woh[ND * ND], g_wol[ND * ND];
// Q,K,V: per (b,h): [32 s-tiles][64 tok][64 dk]  (tile index (b*16+h)*32+st)
__device__ __align__(128) __nv_bfloat16 g_Qh[NM * ND], g_Ql[NM * ND];
__device__ __align__(128) __nv_bfloat16 g_Kh[NM * ND], g_Kl[NM * ND];
__device__ __align__(128) __nv_bfloat16 g_Vh[NM * ND], g_Vl[NM * ND];
// X: GEMM-A tiling over (token 8192, feature 1024)
__device__ __align__(128) __nv_bfloat16 g_Xh[NM * ND], g_Xl[NM * ND];

// ---------------- helpers ----------------
__device__ __forceinline__ uint32_t smem_u32(const void* p) {
    return (uint32_t)__cvta_generic_to_shared(p);
}
__device__ __forceinline__ void mma_bf16(float* d, const uint32_t* a, uint32_t b0, uint32_t b1) {
    asm volatile(
        "mma.sync.aligned.m16n8k16.row.col.f32.bf16.bf16.f32 "
        "{%0,%1,%2,%3}, {%4,%5,%6,%7}, {%8,%9}, {%0,%1,%2,%3};\n"
        : "+f"(d[0]), "+f"(d[1]), "+f"(d[2]), "+f"(d[3])
        : "r"(a[0]), "r"(a[1]), "r"(a[2]), "r"(a[3]), "r"(b0), "r"(b1));
}
__device__ __forceinline__ void ldsm_x4(uint32_t* r, uint32_t addr) {
    asm volatile("ldmatrix.sync.aligned.m8n8.x4.shared.b16 {%0,%1,%2,%3}, [%4];"
                 : "=r"(r[0]), "=r"(r[1]), "=r"(r[2]), "=r"(r[3])
                 : "r"(addr));
}
__device__ __forceinline__ void ldsm_x4_t(uint32_t* r, uint32_t addr) {
    asm volatile("ldmatrix.sync.aligned.m8n8.x4.trans.shared.b16 {%0,%1,%2,%3}, [%4];"
                 : "=r"(r[0]), "=r"(r[1]), "=r"(r[2]), "=r"(r[3])
                 : "r"(addr));
}
__device__ __forceinline__ void bulk_g2s(uint32_t dst, const void* src, uint32_t bytes,
                                         uint32_t mbar) {
    asm volatile(
        "cp.async.bulk.shared::cluster.global.mbarrier::complete_tx::bytes [%0], [%1], %2, [%3];"
        ::"r"(dst), "l"(src), "r"(bytes), "r"(mbar) : "memory");
}
__device__ __forceinline__ void mbar_init(uint32_t addr, uint32_t cnt) {
    asm volatile("mbarrier.init.shared.b64 [%0], %1;" ::"r"(addr), "r"(cnt) : "memory");
}
__device__ __forceinline__ void mbar_expect(uint32_t addr, uint32_t bytes) {
    asm volatile("mbarrier.arrive.expect_tx.shared.b64 _, [%0], %1;"
                 ::"r"(addr), "r"(bytes) : "memory");
}
__device__ __forceinline__ void mbar_arrive(uint32_t addr) {
    asm volatile("mbarrier.arrive.shared.b64 _, [%0];" ::"r"(addr) : "memory");
}
__device__ __forceinline__ void mbar_wait(uint32_t addr, uint32_t parity) {
    asm volatile(
        "{\n\t.reg .pred P;\n\tWL_%=:\n\t"
        "mbarrier.try_wait.parity.acquire.cta.shared::cta.b64 P, [%0], %1, 0x989680;\n\t"
        "@P bra.uni WD_%=;\n\tbra.uni WL_%=;\n\tWD_%=:\n\t}"
        ::"r"(addr), "r"(parity) : "memory");
}
__device__ __forceinline__ void split_store2(__nv_bfloat16* ph, __nv_bfloat16* pl,
                                             float x, float y) {
    __nv_bfloat16 hx = __float2bfloat16(x), hy = __float2bfloat16(y);
    __nv_bfloat162 h2; h2.x = hx; h2.y = hy;
    *(__nv_bfloat162*)ph = h2;
    __nv_bfloat162 l2;
    l2.x = __float2bfloat16(x - __bfloat162float(hx));
    l2.y = __float2bfloat16(y - __bfloat162float(hy));
    *(__nv_bfloat162*)pl = l2;
}
// pack two floats into bf16x2 hi/lo fragments (register-resident P)
__device__ __forceinline__ void mk_frag(float a, float b, uint32_t& h, uint32_t& l) {
    __nv_bfloat162 t = __floats2bfloat162_rn(a, b);  // a->x(lo), b->y(hi)
    h = *(uint32_t*)&t;
    __nv_bfloat162 r = __floats2bfloat162_rn(a - __bfloat162float(t.x),
                                             b - __bfloat162float(t.y));
    l = *(uint32_t*)&r;
}

// ---------------- split: fp32 row-major -> tiled swizzled bf16 hi/lo planes ----------------
__device__ __forceinline__ void split_one(const float* s, __nv_bfloat16* h, __nv_bfloat16* l,
                                          int g) {
    const int m = g >> 8;
    const int k4 = (g & 255) << 2;
    float4 v = *(const float4*)(s + (size_t)m * ND + k4);
    size_t dst = ((size_t)((m >> 6) * NKB + (k4 >> 6))) * 4096 + (m & 63) * 64 +
                 ((k4 & 63) ^ ((m & 7) << 3));
    split_store2(h + dst, l + dst, v.x, v.y);
    split_store2(h + dst + 2, l + dst + 2, v.z, v.w);
}
__global__ void split3_kernel(const float* s0, const float* s1, const float* s2,
                              __nv_bfloat16* h0, __nv_bfloat16* l0,
                              __nv_bfloat16* h1, __nv_bfloat16* l1,
                              __nv_bfloat16* h2, __nv_bfloat16* l2) {
    int g = blockIdx.x * blockDim.x + threadIdx.x;
    const float* s = (blockIdx.y == 0) ? s0 : (blockIdx.y == 1) ? s1 : s2;
    __nv_bfloat16* h = (blockIdx.y == 0) ? h0 : (blockIdx.y == 1) ? h1 : h2;
    __nv_bfloat16* l = (blockIdx.y == 0) ? l0 : (blockIdx.y == 1) ? l1 : l2;
    split_one(s, h, l, g);
}
__global__ void split4_kernel(const float* s0, const float* s1, const float* s2, const float* s3,
                              __nv_bfloat16* h0, __nv_bfloat16* l0,
                              __nv_bfloat16* h1, __nv_bfloat16* l1,
                              __nv_bfloat16* h2, __nv_bfloat16* l2,
                              __nv_bfloat16* h3, __nv_bfloat16* l3) {
    int g = blockIdx.x * blockDim.x + threadIdx.x;
    const float* s = (blockIdx.y == 0) ? s0 : (blockIdx.y == 1) ? s1 : (blockIdx.y == 2) ? s2 : s3;
    __nv_bfloat16* h = (blockIdx.y == 0) ? h0 : (blockIdx.y == 1) ? h1 : (blockIdx.y == 2) ? h2 : h3;
    __nv_bfloat16* l = (blockIdx.y == 0) ? l0 : (blockIdx.y == 1) ? l1 : (blockIdx.y == 2) ? l2 : l3;
    split_one(s, h, l, g);
}

// ---------------- GEMM core: D[m(128), n(128)] = sum_k A[m,k] B[n,k] ----------------
#define GS_STAGE 65536
#define GS_MBAR (2 * GS_STAGE)
#define GEMM_SMEM (GS_MBAR + 16)

struct QKVParams {
    const __nv_bfloat16 *ah[3], *al[3], *bh[3], *bl[3];
    __nv_bfloat16 *oh[3], *ol[3];
};

__device__ __forceinline__ void gemm_mainloop(
    uint32_t sb, const __nv_bfloat16* Ah_, const __nv_bfloat16* Al_,
    const __nv_bfloat16* Bh_, const __nv_bfloat16* Bl_, int bx, int by,
    float acc[4][4][4]) {
    const int tid = threadIdx.x;
    const int lane = tid & 31, wid = tid >> 5;
    const int wm = (wid >> 2) * 64, wn = (wid & 3) * 32;

    const uint32_t mb0 = sb + GS_MBAR;
    if (tid == 0) { mbar_init(mb0, 1); mbar_init(mb0 + 8, 1); }
    __syncthreads();

    auto issue = [&](int st, int s) {
        if (tid == 0) {
            const uint32_t mb = mb0 + st * 8;
            mbar_expect(mb, 65536);
            const uint32_t d = sb + st * GS_STAGE;
#pragma unroll
            for (int t = 0; t < 2; t++) {
                bulk_g2s(d + t * 8192,         Ah_ + (size_t)((2 * by + t) * NKB + s) * 4096, 8192, mb);
                bulk_g2s(d + 16384 + t * 8192, Al_ + (size_t)((2 * by + t) * NKB + s) * 4096, 8192, mb);
                bulk_g2s(d + 32768 + t * 8192, Bh_ + (size_t)((2 * bx + t) * NKB + s) * 4096, 8192, mb);
                bulk_g2s(d + 49152 + t * 8192, Bl_ + (size_t)((2 * bx + t) * NKB + s) * 4096, 8192, mb);
            }
        }
    };
    issue(0, 0);
    issue(1, 1);

    const int arow_l = lane & 15;
    const uint32_t acol = (lane >> 4) << 4;
    const int brow_l = ((lane >> 4) << 3) + (lane & 7);
    const uint32_t bcol = ((lane >> 3) & 1) << 4;

    uint32_t ph[2] = {0, 0};
    for (int s = 0; s < NKB; s++) {
        const int st = s & 1;
        mbar_wait(mb0 + st * 8, ph[st]);
        ph[st] ^= 1;
        const uint32_t base = sb + st * GS_STAGE;

#pragma unroll
        for (int kk = 0; kk < 4; kk++) {
            const uint32_t kb = kk * 32;
            uint32_t bh[4][2], bl[4][2], t[4];
            uint32_t ah[4][4], al[4][4];
#pragma unroll
            for (int p2 = 0; p2 < 2; p2++) {
                const int row = wn + p2 * 16 + brow_l;
                const uint32_t ad = base + 32768 + ((row >> 6) << 13) + ((row & 63) << 7) +
                                    ((kb + bcol) ^ ((row & 7) << 4));
                ldsm_x4(t, ad);
                bh[2 * p2][0] = t[0]; bh[2 * p2][1] = t[1];
                bh[2 * p2 + 1][0] = t[2]; bh[2 * p2 + 1][1] = t[3];
                ldsm_x4(t, ad + 16384);
                bl[2 * p2][0] = t[0]; bl[2 * p2][1] = t[1];
                bl[2 * p2 + 1][0] = t[2]; bl[2 * p2 + 1][1] = t[3];
            }
#pragma unroll
            for (int mf = 0; mf < 4; mf++) {
                const int row = wm + mf * 16 + arow_l;
                const uint32_t ad = base + ((row >> 6) << 13) + ((row & 63) << 7) +
                                    ((kb + acol) ^ ((row & 7) << 4));
                ldsm_x4(ah[mf], ad);
                ldsm_x4(al[mf], ad + 16384);
            }
#pragma unroll
            for (int mf = 0; mf < 4; mf++) {
#pragma unroll
                for (int nf = 0; nf < 4; nf++) mma_bf16(acc[mf][nf], ah[mf], bh[nf][0], bh[nf][1]);
#pragma unroll
                for (int nf = 0; nf < 4; nf++) mma_bf16(acc[mf][nf], ah[mf], bl[nf][0], bl[nf][1]);
#pragma unroll
                for (int nf = 0; nf < 4; nf++) mma_bf16(acc[mf][nf], al[mf], bh[nf][0], bh[nf][1]);
            }
        }
        __syncthreads();
        if (s + 2 < NKB) issue(st, s + 2);
    }
}

// merged Q/K/V projection: grid (8, 64, 3)
__global__ __launch_bounds__(256) void gemm_qkv(QKVParams prm) {
    extern __shared__ char smc[];
    const uint32_t sb = smem_u32(smc);
    const int z = blockIdx.z;
    const int bx = blockIdx.x, by = blockIdx.y;
    const int tid = threadIdx.x;
    const int lane = tid & 31, wid = tid >> 5;
    const int wm = (wid >> 2) * 64, wn = (wid & 3) * 32;
    const int gr = lane >> 2, gc = (lane & 3) * 2;

    float acc[4][4][4];
#pragma unroll
    for (int i = 0; i < 4; i++)
#pragma unroll
        for (int j = 0; j < 4; j++)
#pragma unroll
            for (int c = 0; c < 4; c++) acc[i][j][c] = 0.f;

    gemm_mainloop(sb, prm.ah[z], prm.al[z], prm.bh[z], prm.bl[z], bx, by, acc);

    __nv_bfloat16* Oh = prm.oh[z];
    __nv_bfloat16* Ol = prm.ol[z];
#pragma unroll
    for (int mf = 0; mf < 4; mf++) {
        const int rowg = by * 128 + wm + mf * 16 + gr;
#pragma unroll
        for (int nf = 0; nf < 4; nf++) {
            const int col = bx * 128 + wn + nf * 8 + gc;
            float* a = acc[mf][nf];
            const int b = rowg >> 11, s_ = rowg & (NS - 1);
            const int st_ = s_ >> 6, r = s_ & 63;
            const int h = col >> 6, dk = col & 63;
            size_t e0 = ((size_t)((b * NH + h) * 32 + st_) * 64 + r) * 64 + (dk ^ ((r & 7) << 3));
            split_store2(Oh + e0, Ol + e0, a[0], a[1]);
            split_store2(Oh + e0 + 512, Ol + e0 + 512, a[2], a[3]);  // row+8
        }
    }
}

// final output GEMM: fp32 row-major out
__global__ __launch_bounds__(256) void gemm_out(
    const __nv_bfloat16* __restrict__ Ah_, const __nv_bfloat16* __restrict__ Al_,
    const __nv_bfloat16* __restrict__ Bh_, const __nv_bfloat16* __restrict__ Bl_,
    float* __restrict__ Of) {
    extern __shared__ char smc[];
    const uint32_t sb = smem_u32(smc);
    const int bx = blockIdx.x, by = blockIdx.y;
    const int tid = threadIdx.x;
    const int lane = tid & 31, wid = tid >> 5;
    const int wm = (wid >> 2) * 64, wn = (wid & 3) * 32;
    const int gr = lane >> 2, gc = (lane & 3) * 2;

    float acc[4][4][4];
#pragma unroll
    for (int i = 0; i < 4; i++)
#pragma unroll
        for (int j = 0; j < 4; j++)
#pragma unroll
            for (int c = 0; c < 4; c++) acc[i][j][c] = 0.f;

    gemm_mainloop(sb, Ah_, Al_, Bh_, Bl_, bx, by, acc);

#pragma unroll
    for (int mf = 0; mf < 4; mf++) {
        const int rowg = by * 128 + wm + mf * 16 + gr;
#pragma unroll
        for (int nf = 0; nf < 4; nf++) {
            const int col = bx * 128 + wn + nf * 8 + gc;
            float* a = acc[mf][nf];
            *(float2*)&Of[(size_t)rowg * ND + col] = make_float2(a[0], a[1]);
            *(float2*)&Of[(size_t)(rowg + 8) * ND + col] = make_float2(a[2], a[3]);
        }
    }
}

// ---------------- flash attention: register-resident P, empty-mbar pipeline ----------------
// smem: [Q 32K][KV stage0 32K][KV stage1 32K][data mbar x2, empty mbar x2]
#define AT_KV 32768
#define AT_STG 32768
#define AT_MBAR (AT_KV + 2 * AT_STG)  // 98304
#define ATT_SMEM (AT_MBAR + 32)

__global__ __launch_bounds__(256, 2) void attn_kernel(
    const __nv_bfloat16* __restrict__ Qh_, const __nv_bfloat16* __restrict__ Ql_,
    const __nv_bfloat16* __restrict__ Kh_, const __nv_bfloat16* __restrict__ Kl_,
    const __nv_bfloat16* __restrict__ Vh_, const __nv_bfloat16* __restrict__ Vl_,
    __nv_bfloat16* __restrict__ Xh, __nv_bfloat16* __restrict__ Xl) {
    extern __shared__ char smc[];
    const uint32_t sb = smem_u32(smc);

    const int tid = threadIdx.x;
    const int lane = tid & 31, wid = tid >> 5;
    const int gr = lane >> 2, gc = (lane & 3) * 2;
    const int qb = (gridDim.x - 1) - blockIdx.x;  // longest first
    const int h = blockIdx.y, b = blockIdx.z;

    const int qkbase = (b * NH + h) * 32;

    const uint32_t mb0 = sb + AT_MBAR;   // data barriers
    const uint32_t emb = mb0 + 16;       // empty barriers (count 8 = warps)
    if (tid == 0) {
        mbar_init(mb0, 1); mbar_init(mb0 + 8, 1);
        mbar_init(emb, 8); mbar_init(emb + 8, 8);
    }
    __syncthreads();

    auto issueKV = [&](int st, int kt, bool withQ) {
        const uint32_t mb = mb0 + st * 8;
        mbar_expect(mb, withQ ? 65536u : 32768u);
        if (withQ) {
#pragma unroll
            for (int t = 0; t < 2; t++) {
                bulk_g2s(sb + t * 8192,         Qh_ + (size_t)(qkbase + 2 * qb + t) * 4096, 8192, mb);
                bulk_g2s(sb + 16384 + t * 8192, Ql_ + (size_t)(qkbase + 2 * qb + t) * 4096, 8192, mb);
            }
        }
        const uint32_t d = sb + AT_KV + st * AT_STG;
        bulk_g2s(d,         Kh_ + (size_t)(qkbase + kt) * 4096, 8192, mb);
        bulk_g2s(d + 8192,  Kl_ + (size_t)(qkbase + kt) * 4096, 8192, mb);
        bulk_g2s(d + 16384, Vh_ + (size_t)(qkbase + kt) * 4096, 8192, mb);
        bulk_g2s(d + 24576, Vl_ + (size_t)(qkbase + kt) * 4096, 8192, mb);
    };
    const int nkt = 2 * qb + 2;
    if (tid == 0) { issueKV(0, 0, true); issueKV(1, 1, false); }

    const int arow_l = lane & 15;
    const uint32_t acol = (lane >> 4) << 4;
    const int brow_l = ((lane >> 4) << 3) + (lane & 7);
    const uint32_t bcol = ((lane >> 3) & 1) << 4;
    const int trow_l = (((lane >> 3) & 1) << 3) + (lane & 7);
    const uint32_t tcol = (uint32_t)((lane >> 4) << 4);

    uint32_t qfh[4][4], qfl[4][4];
    float O[8][4];
#pragma unroll
    for (int i = 0; i < 8; i++)
#pragma unroll
        for (int j = 0; j < 4; j++) O[i][j] = 0.f;
    float mrA = -INFINITY, mrB = -INFINITY, lrA = 0.f, lrB = 0.f;

    const int growA = qb * 128 + wid * 16 + gr;
    const int growB = growA + 8;

    uint32_t ph[2] = {0, 0};
    uint32_t eph[2] = {0, 0};
    for (int kt = 0; kt < nkt; kt++) {
        const int st = kt & 1;
        mbar_wait(mb0 + st * 8, ph[st]);
        ph[st] ^= 1;

        if (kt == 0) {
            // extract Q fragments (Q smem never reused -> no block sync needed)
            const int row = wid * 16 + arow_l;
            const uint32_t rq = ((row >> 6) << 13) + ((row & 63) << 7);
#pragma unroll
            for (int df = 0; df < 4; df++) {
                const uint32_t ad = sb + rq + (((uint32_t)(df * 32) + acol) ^ ((row & 7) << 4));
                ldsm_x4(qfh[df], ad);
                ldsm_x4(qfl[df], ad + 16384);
            }
        }

        const uint32_t kvb = sb + AT_KV + st * AT_STG;
        const bool act = !(kt == 2 * qb + 1 && wid < 4);
        if (act) {
            // ---- S = Q K^T ----
            float S[8][4];
#pragma unroll
            for (int i = 0; i < 8; i++)
#pragma unroll
                for (int j = 0; j < 4; j++) S[i][j] = 0.f;
#pragma unroll
            for (int df = 0; df < 4; df++) {
                uint32_t kh[4][4], kl[4][4];
#pragma unroll
                for (int pr = 0; pr < 4; pr++) {
                    const int row = pr * 16 + brow_l;
                    const uint32_t ad = kvb + (row << 7) +
                                        (((uint32_t)(df * 32) + bcol) ^ ((row & 7) << 4));
                    ldsm_x4(kh[pr], ad);
                    ldsm_x4(kl[pr], ad + 8192);
                }
#pragma unroll
                for (int pr = 0; pr < 4; pr++) {
                    mma_bf16(S[2 * pr],     qfh[df], kh[pr][0], kh[pr][1]);
                    mma_bf16(S[2 * pr + 1], qfh[df], kh[pr][2], kh[pr][3]);
                }
#pragma unroll
                for (int pr = 0; pr < 4; pr++) {
                    mma_bf16(S[2 * pr],     qfh[df], kl[pr][0], kl[pr][1]);
                    mma_bf16(S[2 * pr + 1], qfh[df], kl[pr][2], kl[pr][3]);
                }
#pragma unroll
                for (int pr = 0; pr < 4; pr++) {
                    mma_bf16(S[2 * pr],     qfl[df], kh[pr][0], kh[pr][1]);
                    mma_bf16(S[2 * pr + 1], qfl[df], kh[pr][2], kh[pr][3]);
                }
            }

            // ---- scale + causal mask ----
            const float sc = 0.125f;
#pragma unroll
            for (int nf = 0; nf < 8; nf++)
#pragma unroll
                for (int j = 0; j < 4; j++) S[nf][j] *= sc;
            if (kt >= 2 * qb) {
#pragma unroll
                for (int nf = 0; nf < 8; nf++) {
                    const int col = kt * 64 + nf * 8 + gc;
                    if (col > growA) S[nf][0] = -1e30f;
                    if (col + 1 > growA) S[nf][1] = -1e30f;
                    if (col > growB) S[nf][2] = -1e30f;
                    if (col + 1 > growB) S[nf][3] = -1e30f;
                }
            }

            // ---- online softmax (p stored back into S registers) ----
            float mA = -INFINITY, mB = -INFINITY;
#pragma unroll
            for (int nf = 0; nf < 8; nf++) {
                mA = fmaxf(mA, fmaxf(S[nf][0], S[nf][1]));
                mB = fmaxf(mB, fmaxf(S[nf][2], S[nf][3]));
            }
            mA = fmaxf(mA, __shfl_xor_sync(0xffffffffu, mA, 1));
            mA = fmaxf(mA, __shfl_xor_sync(0xffffffffu, mA, 2));
            mB = fmaxf(mB, __shfl_xor_sync(0xffffffffu, mB, 1));
            mB = fmaxf(mB, __shfl_xor_sync(0xffffffffu, mB, 2));
            const float mnA = fmaxf(mrA, mA), mnB = fmaxf(mrB, mB);
            const float aA = __expf(mrA - mnA), aB = __expf(mrB - mnB);
            float rsA = 0.f, rsB = 0.f;
#pragma unroll
            for (int nf = 0; nf < 8; nf++) {
                S[nf][0] = __expf(S[nf][0] - mnA);
                S[nf][1] = __expf(S[nf][1] - mnA);
                S[nf][2] = __expf(S[nf][2] - mnB);
                S[nf][3] = __expf(S[nf][3] - mnB);
                rsA += S[nf][0] + S[nf][1];
                rsB += S[nf][2] + S[nf][3];
            }
            rsA += __shfl_xor_sync(0xffffffffu, rsA, 1);
            rsA += __shfl_xor_sync(0xffffffffu, rsA, 2);
            rsB += __shfl_xor_sync(0xffffffffu, rsB, 1);
            rsB += __shfl_xor_sync(0xffffffffu, rsB, 2);
            lrA = lrA * aA + rsA; mrA = mnA;
            lrB = lrB * aB + rsB; mrB = mnB;
#pragma unroll
            for (int df = 0; df < 8; df++) {
                O[df][0] *= aA; O[df][1] *= aA;
                O[df][2] *= aB; O[df][3] *= aB;
            }

            // ---- O += P V ----  (P fragments built directly from S registers)
#pragma unroll
            for (int ks = 0; ks < 4; ks++) {
                uint32_t ph_[4], pl_[4];
                mk_frag(S[2 * ks][0],     S[2 * ks][1],     ph_[0], pl_[0]);
                mk_frag(S[2 * ks][2],     S[2 * ks][3],     ph_[1], pl_[1]);
                mk_frag(S[2 * ks + 1][0], S[2 * ks + 1][1], ph_[2], pl_[2]);
                mk_frag(S[2 * ks + 1][2], S[2 * ks + 1][3], ph_[3], pl_[3]);
                uint32_t vh[4][4], vl[4][4];
#pragma unroll
                for (int pr = 0; pr < 4; pr++) {
                    const int row = ks * 16 + trow_l;  // token row
                    const uint32_t vad = kvb + 16384 + (row << 7) +
                                         (((uint32_t)(pr * 32) + tcol) ^ ((row & 7) << 4));
                    ldsm_x4_t(vh[pr], vad);
                    ldsm_x4_t(vl[pr], vad + 8192);
                }
#pragma unroll
                for (int pr = 0; pr < 4; pr++) {
                    mma_bf16(O[2 * pr],     ph_, vh[pr][0], vh[pr][1]);
                    mma_bf16(O[2 * pr + 1], ph_, vh[pr][2], vh[pr][3]);
                }
#pragma unroll
                for (int pr = 0; pr < 4; pr++) {
                    mma_bf16(O[2 * pr],     ph_, vl[pr][0], vl[pr][1]);
                    mma_bf16(O[2 * pr + 1], ph_, vl[pr][2], vl[pr][3]);
                }
#pragma unroll
                for (int pr = 0; pr < 4; pr++) {
                    mma_bf16(O[2 * pr],     pl_, vh[pr][0], vh[pr][1]);
                    mma_bf16(O[2 * pr + 1], pl_, vh[pr][2], vh[pr][3]);
                }
            }
        }

        // consumer -> producer handoff: per-warp arrive on empty barrier
        __syncwarp();
        if (lane == 0) mbar_arrive(emb + st * 8);
        if (kt + 2 < nkt) {
            if (tid == 0) {
                mbar_wait(emb + st * 8, eph[st]);  // all 8 warps done with stage st
                issueKV(st, kt + 2, false);
            }
            eph[st] ^= 1;
        }
    }

    // ---- epilogue: X in GEMM-A tiled layout ----
    const float iA = 1.0f / lrA, iB = 1.0f / lrB;
    const int gA = b * NS + growA;
    const int r = gA & 63;
    const size_t e0 = ((size_t)((gA >> 6) * NKB + h) * 64 + r) * 64;
    const uint32_t sw = (uint32_t)((r & 7) << 3);
#pragma unroll
    for (int df = 0; df < 8; df++) {
        const uint32_t c = (uint32_t)(df * 8 + gc);
        const size_t eA = e0 + (c ^ sw);
        const size_t eB = eA + 512;
        split_store2(Xh + eA, Xl + eA, O[df][0] * iA, O[df][1] * iA);
        split_store2(Xh + eB, Xl + eB, O[df][2] * iB, O[df][3] * iB);
    }
}

// ---------------- launch ----------------
extern "C" void kernel_launch(void* const* d_in, const int* in_sizes, int n_in,
                              void* d_out, int out_size) {
    const float* q = (const float*)d_in[0];
    const float* k = (const float*)d_in[1];
    const float* v = (const float*)d_in[2];
    const float* wq = (const float*)d_in[4];
    const float* wk = (const float*)d_in[5];
    const float* wv = (const float*)d_in[6];
    const float* wo = (const float*)d_in[7];
    float* out = (float*)d_out;

    __nv_bfloat16 *qh, *ql, *kh, *kl, *vh, *vl;
    __nv_bfloat16 *wqh, *wql, *wkh, *wkl, *wvh, *wvl, *woh, *wol;
    __nv_bfloat16 *Qh, *Ql, *Kh, *Kl, *Vh, *Vl, *Xh, *Xl;
    cudaGetSymbolAddress((void**)&qh, g_qh);   cudaGetSymbolAddress((void**)&ql, g_ql);
    cudaGetSymbolAddress((void**)&kh, g_kh);   cudaGetSymbolAddress((void**)&kl, g_kl);
    cudaGetSymbolAddress((void**)&vh, g_vh);   cudaGetSymbolAddress((void**)&vl, g_vl);
    cudaGetSymbolAddress((void**)&wqh, g_wqh); cudaGetSymbolAddress((void**)&wql, g_wql);
    cudaGetSymbolAddress((void**)&wkh, g_wkh); cudaGetSymbolAddress((void**)&wkl, g_wkl);
    cudaGetSymbolAddress((void**)&wvh, g_wvh); cudaGetSymbolAddress((void**)&wvl, g_wvl);
    cudaGetSymbolAddress((void**)&woh, g_woh); cudaGetSymbolAddress((void**)&wol, g_wol);
    cudaGetSymbolAddress((void**)&Qh, g_Qh);   cudaGetSymbolAddress((void**)&Ql, g_Ql);
    cudaGetSymbolAddress((void**)&Kh, g_Kh);   cudaGetSymbolAddress((void**)&Kl, g_Kl);
    cudaGetSymbolAddress((void**)&Vh, g_Vh);   cudaGetSymbolAddress((void**)&Vl, g_Vl);
    cudaGetSymbolAddress((void**)&Xh, g_Xh);   cudaGetSymbolAddress((void**)&Xl, g_Xl);

    cudaFuncSetAttribute(gemm_qkv, cudaFuncAttributeMaxDynamicSharedMemorySize, GEMM_SMEM);
    cudaFuncSetAttribute(gemm_out, cudaFuncAttributeMaxDynamicSharedMemorySize, GEMM_SMEM);
    cudaFuncSetAttribute(attn_kernel, cudaFuncAttributeMaxDynamicSharedMemorySize, ATT_SMEM);

    split3_kernel<<<dim3(NM * ND / 4 / 256, 3), 256>>>(q, k, v, qh, ql, kh, kl, vh, vl);
    split4_kernel<<<dim3(ND * ND / 4 / 256, 4), 256>>>(wq, wk, wv, wo,
                                                       wqh, wql, wkh, wkl, wvh, wvl, woh, wol);

    QKVParams prm;
    prm.ah[0] = qh; prm.al[0] = ql; prm.bh[0] = wqh; prm.bl[0] = wql; prm.oh[0] = Qh; prm.ol[0] = Ql;
    prm.ah[1] = kh; prm.al[1] = kl; prm.bh[1] = wkh; prm.bl[1] = wkl; prm.oh[1] = Kh; prm.ol[1] = Kl;
    prm.ah[2] = vh; prm.al[2] = vl; prm.bh[2] = wvh; prm.bl[2] = wvl; prm.oh[2] = Vh; prm.ol[2] = Vl;

    gemm_qkv<<<dim3(ND / 128, NM / 128, 3), 256, GEMM_SMEM>>>(prm);

    attn_kernel<<<dim3(NS / 128, NH, NB), 256, ATT_SMEM>>>(Qh, Ql, Kh, Kl, Vh, Vl, Xh, Xl);

    gemm_out<<<dim3(ND / 128, NM / 128), 256, GEMM_SMEM>>>(Xh, Xl, woh, wol, out);
}